// round 12
// baseline (speedup 1.0000x reference)
#include <cuda_runtime.h>
#include <cuda_bf16.h>
#include <math.h>

#define BB 4096
#define DD 128

typedef unsigned int u32;

// ---- tensor-core helpers ----
__device__ __forceinline__ uint4 ldsm4(u32 addr) {
    uint4 r;
    asm volatile("ldmatrix.sync.aligned.m8n8.x4.shared.b16 {%0,%1,%2,%3},[%4];"
        : "=r"(r.x), "=r"(r.y), "=r"(r.z), "=r"(r.w) : "r"(addr));
    return r;
}
__device__ __forceinline__ uint4 ldsm4t(u32 addr) {
    uint4 r;
    asm volatile("ldmatrix.sync.aligned.m8n8.x4.trans.shared.b16 {%0,%1,%2,%3},[%4];"
        : "=r"(r.x), "=r"(r.y), "=r"(r.z), "=r"(r.w) : "r"(addr));
    return r;
}
__device__ __forceinline__ void mma16816(float* c, uint4 a, u32 b0, u32 b1) {
    asm volatile(
        "mma.sync.aligned.m16n8k16.row.col.f32.bf16.bf16.f32 "
        "{%0,%1,%2,%3},{%4,%5,%6,%7},{%8,%9},{%0,%1,%2,%3};"
        : "+f"(c[0]), "+f"(c[1]), "+f"(c[2]), "+f"(c[3])
        : "r"(a.x), "r"(a.y), "r"(a.z), "r"(a.w), "r"(b0), "r"(b1));
}
__device__ __forceinline__ float ex2f(float x) {
    float y; asm("ex2.approx.f32 %0,%1;" : "=f"(y) : "f"(x)); return y;
}
__device__ __forceinline__ u32 cvtbf2(float hi, float lo) {
    u32 r; asm("cvt.rn.bf16x2.f32 %0,%1,%2;" : "=r"(r) : "f"(hi), "f"(lo)); return r;
}
__device__ __forceinline__ u32 s2u(const void* p) {
    return (u32)__cvta_generic_to_shared(p);
}
__device__ __forceinline__ void split2(float v0, float v1, u32& hp, u32& lp) {
    hp = cvtbf2(v1, v0);
    float h0 = __uint_as_float(hp << 16);
    float h1 = __uint_as_float(hp & 0xffff0000u);
    lp = cvtbf2(v1 - h1, v0 - h0);
}
__device__ __forceinline__ void cpa16(u32 dst, const void* src) {
    asm volatile("cp.async.cg.shared.global [%0],[%1],16;" :: "r"(dst), "l"(src));
}
__device__ __forceinline__ void cpa_commit() {
    asm volatile("cp.async.commit_group;");
}
__device__ __forceinline__ void cpa_wait0() {
    asm volatile("cp.async.wait_group 0;");
}
__device__ __forceinline__ void cpa_wait1() {
    asm volatile("cp.async.wait_group 1;");
}

#define QSCALE 0.17677669529663688f
#define LOG2E  1.4426950408889634f

// ---------------- scratch ----------------
__device__ float g_x[BB*DD];
__device__ float g_y[BB*DD];
__device__ __nv_bfloat16 g_xh[BB*DD];
__device__ __nv_bfloat16 g_xl[BB*DD];
__device__ __nv_bfloat16 g_qkvh[BB*3*DD];
__device__ __nv_bfloat16 g_attnh[BB*DD];
__device__ __nv_bfloat16 g_attnl[BB*DD];
__device__ __nv_bfloat16 g_wh[327680];
__device__ __nv_bfloat16 g_wl[327680];
__device__ float g_ca[10*DD];

#define WO_SAIN  0
#define WO_SAOUT 49152
#define WO_M1W1  65536
#define WO_M1W2  131072
#define WO_M2W1  196608
#define WO_M2W2  262144
#define W_TOTAL  327680

// ---------------- setup: weight convert + embed + ca table in ONE launch ----------------
struct WSrc { const float* p[6]; int end[6]; };
// blocks [0,640): cvtw ; [640,2688): embed (2 rows/block) ; [2688,2698): ca (1 class/block)
__global__ __launch_bounds__(256) void k_setup(WSrc a, __nv_bfloat16* dh, __nv_bfloat16* dl,
    const float* __restrict__ coords, const float* __restrict__ ce_w, const float* __restrict__ ce_b,
    const float* __restrict__ emb, const float* __restrict__ wv, const float* __restrict__ bv,
    const float* __restrict__ wo, const float* __restrict__ bo)
{
    int b = blockIdx.x;
    int tid = threadIdx.x;
    if (b < 640) {
        int i = b*256 + tid;
        if (i >= a.end[5]) return;
        int k = 0;
        #pragma unroll
        for (int j = 1; j < 6; j++) if (i >= a.end[j-1]) k = j;
        int beg = (k > 0) ? a.end[k-1] : 0;
        float2 v = ((const float2*)a.p[k])[i - beg];
        u32 hp, lp; split2(v.x, v.y, hp, lp);
        ((u32*)dh)[i] = hp;
        ((u32*)dl)[i] = lp;
    } else if (b < 2688) {
        int i = (b - 640)*2 + (tid >> 7);
        int d = tid & 127;
        float c0 = coords[2*i], c1 = coords[2*i+1];
        int j = d >> 1;
        float dv = expf(9.210340371976184f * (float)j * (1.0f/64.0f));
        float pe = (d & 1) ? cosf(c1 / dv) : sinf(c0 / dv);
        float v = c0*ce_w[2*d] + c1*ce_w[2*d+1] + ce_b[d] + pe;
        g_x[i*DD + d] = v;
        __nv_bfloat16 h = __float2bfloat16_rn(v);
        g_xh[i*DD + d] = h;
        g_xl[i*DD + d] = __float2bfloat16_rn(v - __bfloat162float(h));
    } else {
        __shared__ float e[128], t[128];
        int c = b - 2688, j = tid;
        if (j < 128) e[j] = emb[c*128 + j];
        __syncthreads();
        if (j < 128) {
            float s = bv[j];
            #pragma unroll 8
            for (int d0 = 0; d0 < 128; d0++) s += e[d0]*wv[j*128 + d0];
            t[j] = s;
        }
        __syncthreads();
        if (j < 128) {
            float s2 = bo[j];
            #pragma unroll 8
            for (int d0 = 0; d0 < 128; d0++) s2 += t[d0]*wo[j*128 + d0];
            g_ca[c*128 + j] = s2;
        }
    }
}

// ---------------- 3xBF16 GEMM, 64x64 tile (qkv) ----------------
template<int OUTMODE, int ACT>
__global__ __launch_bounds__(256) void k_gemm3(
    const __nv_bfloat16* __restrict__ Ah, const __nv_bfloat16* __restrict__ Al,
    const __nv_bfloat16* __restrict__ Wh, const __nv_bfloat16* __restrict__ Wl,
    const float* __restrict__ bias,
    void* __restrict__ out1, void* __restrict__ out2, int N, int K)
{
    __shared__ __nv_bfloat16 sA[2][2][64][40];
    __shared__ __nv_bfloat16 sW[2][2][64][40];

    const int tid = threadIdx.x;
    const int lane = tid & 31, w = tid >> 5;
    const int wr = w & 3, wc = w >> 2;
    const int m0 = blockIdx.y*64, n0 = blockIdx.x*64;
    const int r = tid >> 2, q = tid & 3;
    const int nc = K >> 5;

    const __nv_bfloat16* pAh = Ah + (size_t)(m0+r)*K + q*8;
    const __nv_bfloat16* pAl = Al + (size_t)(m0+r)*K + q*8;
    const __nv_bfloat16* pWh = Wh + (size_t)(n0+r)*K + q*8;
    const __nv_bfloat16* pWl = Wl + (size_t)(n0+r)*K + q*8;

    {
        uint4 va = *(const uint4*)pAh;
        uint4 vl = *(const uint4*)pAl;
        uint4 vw = *(const uint4*)pWh;
        uint4 vx = *(const uint4*)pWl;
        *(uint4*)&sA[0][0][r][q*8] = va;
        *(uint4*)&sA[0][1][r][q*8] = vl;
        *(uint4*)&sW[0][0][r][q*8] = vw;
        *(uint4*)&sW[0][1][r][q*8] = vx;
    }
    __syncthreads();

    float c[4][4];
    #pragma unroll
    for (int j = 0; j < 4; j++) { c[j][0]=0.f; c[j][1]=0.f; c[j][2]=0.f; c[j][3]=0.f; }

    const u32 frag_off = (u32)((lane & 15)*80 + (lane >> 4)*16);
    const u32 aA = s2u(&sA[0][0][0][0]) + (u32)(wr*16*80) + frag_off;
    const u32 aW = s2u(&sW[0][0][0][0]) + (u32)(wc*32*80) + frag_off;

    for (int t = 0; t < nc; t++) {
        uint4 va, vl, vw, vx;
        if (t + 1 < nc) {
            int o = (t+1)*32;
            va = *(const uint4*)(pAh+o);
            vl = *(const uint4*)(pAl+o);
            vw = *(const uint4*)(pWh+o);
            vx = *(const uint4*)(pWl+o);
        }
        u32 bofs = (u32)(t & 1) * 10240u;
        #pragma unroll
        for (int sub = 0; sub < 2; sub++) {
            u32 ko = bofs + sub*32;
            uint4 fAh = ldsm4(aA + ko);
            uint4 fAl = ldsm4(aA + ko + 5120);
            uint4 bh0 = ldsm4(aW + ko);
            uint4 bh1 = ldsm4(aW + ko + 1280);
            uint4 bl0 = ldsm4(aW + ko + 5120);
            uint4 bl1 = ldsm4(aW + ko + 5120 + 1280);
            mma16816(c[0], fAh, bh0.x, bh0.z);
            mma16816(c[1], fAh, bh0.y, bh0.w);
            mma16816(c[2], fAh, bh1.x, bh1.z);
            mma16816(c[3], fAh, bh1.y, bh1.w);
            mma16816(c[0], fAh, bl0.x, bl0.z);
            mma16816(c[1], fAh, bl0.y, bl0.w);
            mma16816(c[2], fAh, bl1.x, bl1.z);
            mma16816(c[3], fAh, bl1.y, bl1.w);
            mma16816(c[0], fAl, bh0.x, bh0.z);
            mma16816(c[1], fAl, bh0.y, bh0.w);
            mma16816(c[2], fAl, bh1.x, bh1.z);
            mma16816(c[3], fAl, bh1.y, bh1.w);
        }
        if (t + 1 < nc) {
            int nb = (t & 1) ^ 1;
            *(uint4*)&sA[nb][0][r][q*8] = va;
            *(uint4*)&sA[nb][1][r][q*8] = vl;
            *(uint4*)&sW[nb][0][r][q*8] = vw;
            *(uint4*)&sW[nb][1][r][q*8] = vx;
        }
        __syncthreads();
    }

    const int row = m0 + wr*16 + (lane >> 2);
    const int cbase = n0 + wc*32;
    const int cb = (lane & 3)*2;
    #pragma unroll
    for (int nt = 0; nt < 4; nt++) {
        int col = cbase + nt*8 + cb;
        float b0 = bias[col], b1 = bias[col+1];
        float v0 = c[nt][0]+b0, v1 = c[nt][1]+b1;
        float v2 = c[nt][2]+b0, v3 = c[nt][3]+b1;
        if (ACT == 1) {
            v0 = 0.5f*v0*(1.0f + erff(v0*0.7071067811865475f));
            v1 = 0.5f*v1*(1.0f + erff(v1*0.7071067811865475f));
            v2 = 0.5f*v2*(1.0f + erff(v2*0.7071067811865475f));
            v3 = 0.5f*v3*(1.0f + erff(v3*0.7071067811865475f));
        }
        if (OUTMODE == 1) {
            u32* O = (u32*)out1;
            float sc = (col < 128) ? (QSCALE*LOG2E) : 1.0f;
            O[((size_t)row*N + col) >> 1]     = cvtbf2(v1*sc, v0*sc);
            O[((size_t)(row+8)*N + col) >> 1] = cvtbf2(v3*sc, v2*sc);
        } else {
            u32* OH = (u32*)out1; u32* OL = (u32*)out2;
            u32 hp, lp;
            split2(v0, v1, hp, lp);
            OH[((size_t)row*N + col) >> 1] = hp;
            OL[((size_t)row*N + col) >> 1] = lp;
            split2(v2, v3, hp, lp);
            OH[((size_t)(row+8)*N + col) >> 1] = hp;
            OL[((size_t)(row+8)*N + col) >> 1] = lp;
        }
    }
}

// ---------------- fused GEMM(+residual+LN) : tile 32 x 128 (sa_out path) ----------------
template<int MODE>
__global__ __launch_bounds__(256) void k_gemmln(
    const __nv_bfloat16* __restrict__ Ah, const __nv_bfloat16* __restrict__ Al,
    const __nv_bfloat16* __restrict__ Wh, const __nv_bfloat16* __restrict__ Wl,
    const float* __restrict__ bias, const float* __restrict__ R,
    const float* __restrict__ g1, const float* __restrict__ b1,
    float* __restrict__ outf, __nv_bfloat16* __restrict__ oh, __nv_bfloat16* __restrict__ ol,
    int K)
{
    extern __shared__ char sm[];
    const u32 SA = 0, SW = 10240, SC = 51200;
    float* sC = (float*)(sm + SC);

    const int tid = threadIdx.x;
    const int lane = tid & 31, w = tid >> 5;
    const int wr = w & 1, wc = w >> 1;
    const int m0 = blockIdx.x * 32;
    const int nc = K >> 5;

    const int rA = tid >> 3, uA = tid & 7, mA = uA >> 2, cA = uA & 3;
    const __nv_bfloat16* pA = (mA ? Al : Ah) + (size_t)(m0 + rA)*K + cA*8;
    char* dstA = sm + SA + mA*2560 + rA*80 + cA*16;

    const int rW = tid >> 1, cW = (tid & 1)*2;
    const __nv_bfloat16* pWh = Wh + (size_t)rW*K + cW*8;
    const __nv_bfloat16* pWl = Wl + (size_t)rW*K + cW*8;
    char* dstWh = sm + SW + rW*80 + cW*16;
    char* dstWl = sm + SW + 10240 + rW*80 + cW*16;

    {
        uint4 va  = *(const uint4*)pA;
        uint4 wh0 = *(const uint4*)pWh, wh1 = *(const uint4*)(pWh+8);
        uint4 wl0 = *(const uint4*)pWl, wl1 = *(const uint4*)(pWl+8);
        *(uint4*)dstA = va;
        *(uint4*)dstWh = wh0; *(uint4*)(dstWh+16) = wh1;
        *(uint4*)dstWl = wl0; *(uint4*)(dstWl+16) = wl1;
    }
    __syncthreads();

    float c[4][4];
    #pragma unroll
    for (int j = 0; j < 4; j++) { c[j][0]=0.f; c[j][1]=0.f; c[j][2]=0.f; c[j][3]=0.f; }

    const u32 frag_off = (u32)((lane & 15)*80 + (lane >> 4)*16);
    const u32 aA = s2u(sm) + SA + (u32)(wr*16*80) + frag_off;
    const u32 aW = s2u(sm) + SW + (u32)(wc*32*80) + frag_off;

    for (int t = 0; t < nc; t++) {
        uint4 va, wh0, wh1, wl0, wl1;
        if (t + 1 < nc) {
            int o = (t+1)*32;
            va  = *(const uint4*)(pA+o);
            wh0 = *(const uint4*)(pWh+o); wh1 = *(const uint4*)(pWh+o+8);
            wl0 = *(const uint4*)(pWl+o); wl1 = *(const uint4*)(pWl+o+8);
        }
        u32 bA = (u32)(t & 1) * 5120u;
        u32 bW = (u32)(t & 1) * 20480u;
        #pragma unroll
        for (int sub = 0; sub < 2; sub++) {
            u32 ko = sub*32;
            uint4 fAh = ldsm4(aA + bA + ko);
            uint4 fAl = ldsm4(aA + bA + ko + 2560);
            uint4 bh0 = ldsm4(aW + bW + ko);
            uint4 bh1 = ldsm4(aW + bW + ko + 1280);
            uint4 bl0 = ldsm4(aW + bW + ko + 10240);
            uint4 bl1 = ldsm4(aW + bW + ko + 11520);
            mma16816(c[0], fAh, bh0.x, bh0.z);
            mma16816(c[1], fAh, bh0.y, bh0.w);
            mma16816(c[2], fAh, bh1.x, bh1.z);
            mma16816(c[3], fAh, bh1.y, bh1.w);
            mma16816(c[0], fAh, bl0.x, bl0.z);
            mma16816(c[1], fAh, bl0.y, bl0.w);
            mma16816(c[2], fAh, bl1.x, bl1.z);
            mma16816(c[3], fAh, bl1.y, bl1.w);
            mma16816(c[0], fAl, bh0.x, bh0.z);
            mma16816(c[1], fAl, bh0.y, bh0.w);
            mma16816(c[2], fAl, bh1.x, bh1.z);
            mma16816(c[3], fAl, bh1.y, bh1.w);
        }
        if (t + 1 < nc) {
            u32 nb = (u32)((t & 1) ^ 1);
            *(uint4*)(dstA + nb*5120) = va;
            *(uint4*)(dstWh + nb*20480) = wh0; *(uint4*)(dstWh + nb*20480 + 16) = wh1;
            *(uint4*)(dstWl + nb*20480) = wl0; *(uint4*)(dstWl + nb*20480 + 16) = wl1;
        }
        __syncthreads();
    }

    {
        const int rl = wr*16 + (lane >> 2);
        const int cb = (lane & 3)*2;
        #pragma unroll
        for (int nt = 0; nt < 4; nt++) {
            int col = wc*32 + nt*8 + cb;
            float b0 = bias[col], b1 = bias[col+1];
            sC[rl*132 + col]       = c[nt][0] + b0;
            sC[rl*132 + col + 1]   = c[nt][1] + b1;
            sC[(rl+8)*132 + col]     = c[nt][2] + b0;
            sC[(rl+8)*132 + col + 1] = c[nt][3] + b1;
        }
    }
    __syncthreads();

    float4 g1v = *(const float4*)&g1[lane*4];
    float4 b1v = *(const float4*)&b1[lane*4];
    #pragma unroll
    for (int rr = 0; rr < 4; rr++) {
        int rl2 = w*4 + rr;
        int row = m0 + rl2;
        float4 v = *(float4*)&sC[rl2*132 + lane*4];
        float4 rv = *(const float4*)&R[(size_t)row*128 + lane*4];
        v.x += rv.x; v.y += rv.y; v.z += rv.z; v.w += rv.w;

        float s  = v.x + v.y + v.z + v.w;
        float s2 = v.x*v.x + v.y*v.y + v.z*v.z + v.w*v.w;
        #pragma unroll
        for (int off = 16; off > 0; off >>= 1) {
            s  += __shfl_xor_sync(0xffffffffu, s,  off);
            s2 += __shfl_xor_sync(0xffffffffu, s2, off);
        }
        float mean = s * (1.0f/128.0f);
        float var  = s2 * (1.0f/128.0f) - mean*mean;
        float rstd = rsqrtf(var + 1e-5f);
        v.x = (v.x - mean)*rstd*g1v.x + b1v.x;
        v.y = (v.y - mean)*rstd*g1v.y + b1v.y;
        v.z = (v.z - mean)*rstd*g1v.z + b1v.z;
        v.w = (v.w - mean)*rstd*g1v.w + b1v.w;

        *(float4*)&outf[(size_t)row*128 + lane*4] = v;
        u32 hp, lp;
        size_t idx = ((size_t)row*128 + lane*4) >> 1;
        split2(v.x, v.y, hp, lp);
        ((u32*)oh)[idx]   = hp; ((u32*)ol)[idx]   = lp;
        split2(v.z, v.w, hp, lp);
        ((u32*)oh)[idx+1] = hp; ((u32*)ol)[idx+1] = lp;
    }
}

// ---------------- fused MLP (unchanged from round 11) ----------------
template<int MODE>
__global__ __launch_bounds__(256) void k_mlpln(
    const __nv_bfloat16* __restrict__ Ah, const __nv_bfloat16* __restrict__ Al,
    const __nv_bfloat16* __restrict__ W1h, const __nv_bfloat16* __restrict__ W1l,
    const float* __restrict__ b1,
    const __nv_bfloat16* __restrict__ W2h, const __nv_bfloat16* __restrict__ W2l,
    const float* __restrict__ b2,
    const float* __restrict__ R,
    const float* __restrict__ ng1, const float* __restrict__ nb1,
    const float* __restrict__ ng2, const float* __restrict__ nb2,
    const float* __restrict__ catab, const int* __restrict__ labels,
    float* __restrict__ outf, __nv_bfloat16* __restrict__ oh, __nv_bfloat16* __restrict__ ol)
{
    extern __shared__ char sm[];
    const u32 SW1 = 0;
    const u32 SW2 = 81920;
    const u32 SH  = 163840;
    const u32 SC  = 174080;
    float* sC = (float*)(sm + SC);

    const int tid = threadIdx.x;
    const int lane = tid & 31, w = tid >> 5;
    const int wr = w & 1, wc = w >> 1;
    const int m0 = blockIdx.x * 32;
    const u32 smb = s2u(sm);
    const u32 frag_off = (u32)((lane & 15)*80 + (lane >> 4)*16);

    #pragma unroll
    for (int i = 0; i < 4; i++) {
        int idx = tid + i*256;
        int kc = idx >> 8;
        int rem = idx & 255;
        int mat = rem >> 7;
        int rm  = rem & 127;
        int row = rm >> 2;
        int seg = rm & 3;
        const __nv_bfloat16* src = (mat ? Al : Ah) + (size_t)(m0+row)*128 + kc*32 + seg*8;
        cpa16(smb + SW2 + (u32)(kc*5120 + mat*2560 + row*80 + seg*16), src);
    }
    cpa_commit();
    cpa_wait0();
    __syncthreads();

    uint4 fXh[4][2], fXl[4][2];
    {
        u32 aX = smb + SW2 + (u32)(wr*16*80) + frag_off;
        #pragma unroll
        for (int kc = 0; kc < 4; kc++) {
            fXh[kc][0] = ldsm4(aX + kc*5120);
            fXh[kc][1] = ldsm4(aX + kc*5120 + 32);
            fXl[kc][0] = ldsm4(aX + kc*5120 + 2560);
            fXl[kc][1] = ldsm4(aX + kc*5120 + 2560 + 32);
        }
    }
    __syncthreads();

    auto stageW = [&](int nh, int b) {
        #pragma unroll
        for (int i = 0; i < 8; i++) {
            int idx = tid + i*256;
            int kc = idx >> 9;
            int rem = idx & 511;
            int mat = rem >> 8;
            int rm = rem & 255;
            int row = rm >> 2;
            int seg = rm & 3;
            const __nv_bfloat16* src = (mat ? W1l : W1h) + (size_t)(nh*64+row)*128 + kc*32 + seg*8;
            cpa16(smb + SW1 + (u32)(b*40960 + kc*10240 + mat*5120 + row*80 + seg*16), src);
        }
        #pragma unroll
        for (int i = 0; i < 8; i++) {
            int idx = tid + i*256;
            int kc = idx >> 10;
            int rem = idx & 1023;
            int mat = rem >> 9;
            int rm = rem & 511;
            int row = rm >> 2;
            int seg = rm & 3;
            const __nv_bfloat16* src = (mat ? W2l : W2h) + (size_t)row*512 + nh*64 + kc*32 + seg*8;
            cpa16(smb + SW2 + (u32)(b*40960 + kc*20480 + mat*10240 + row*80 + seg*16), src);
        }
    };

    stageW(0, 0);
    cpa_commit();

    float c2[4][4];
    #pragma unroll
    for (int j = 0; j < 4; j++) { c2[j][0]=0.f; c2[j][1]=0.f; c2[j][2]=0.f; c2[j][3]=0.f; }

    const int r0 = wr*16 + (lane >> 2);

    for (int nh = 0; nh < 8; nh++) {
        const int b = nh & 1;
        __syncthreads();
        if (nh + 1 < 8) { stageW(nh+1, b^1); cpa_commit(); cpa_wait1(); }
        else cpa_wait0();
        __syncthreads();

        float c1[2][4];
        c1[0][0]=0.f; c1[0][1]=0.f; c1[0][2]=0.f; c1[0][3]=0.f;
        c1[1][0]=0.f; c1[1][1]=0.f; c1[1][2]=0.f; c1[1][3]=0.f;
        {
            u32 aW1 = smb + SW1 + (u32)(b*40960) + (u32)(wc*16*80) + frag_off;
            #pragma unroll
            for (int kc = 0; kc < 4; kc++) {
                #pragma unroll
                for (int sub = 0; sub < 2; sub++) {
                    u32 ko = (u32)(kc*10240 + sub*32);
                    uint4 bh = ldsm4(aW1 + ko);
                    uint4 bl = ldsm4(aW1 + ko + 5120);
                    uint4 fh = fXh[kc][sub], fl = fXl[kc][sub];
                    mma16816(c1[0], fh, bh.x, bh.z);
                    mma16816(c1[1], fh, bh.y, bh.w);
                    mma16816(c1[0], fh, bl.x, bl.z);
                    mma16816(c1[1], fh, bl.y, bl.w);
                    mma16816(c1[0], fl, bh.x, bh.z);
                    mma16816(c1[1], fl, bh.y, bh.w);
                }
            }
        }
        #pragma unroll
        for (int nt = 0; nt < 2; nt++) {
            int hc = wc*16 + nt*8 + (lane & 3)*2;
            float bb0 = b1[nh*64 + hc], bb1 = b1[nh*64 + hc + 1];
            float v0 = c1[nt][0]+bb0, v1 = c1[nt][1]+bb1;
            float v2 = c1[nt][2]+bb0, v3 = c1[nt][3]+bb1;
            v0 = 0.5f*v0*(1.0f + erff(v0*0.7071067811865475f));
            v1 = 0.5f*v1*(1.0f + erff(v1*0.7071067811865475f));
            v2 = 0.5f*v2*(1.0f + erff(v2*0.7071067811865475f));
            v3 = 0.5f*v3*(1.0f + erff(v3*0.7071067811865475f));
            int kc2 = hc >> 5, cc = hc & 31;
            char* p0 = sm + SH + kc2*5120 + r0*80 + cc*2;
            u32 hp, lp;
            split2(v0, v1, hp, lp);
            *(u32*)p0 = hp; *(u32*)(p0 + 2560) = lp;
            split2(v2, v3, hp, lp);
            *(u32*)(p0 + 640) = hp; *(u32*)(p0 + 640 + 2560) = lp;
        }
        __syncthreads();

        {
            u32 aH  = smb + SH + (u32)(wr*16*80) + frag_off;
            u32 aW2 = smb + SW2 + (u32)(b*40960) + (u32)(wc*32*80) + frag_off;
            #pragma unroll
            for (int kc = 0; kc < 2; kc++) {
                #pragma unroll
                for (int sub = 0; sub < 2; sub++) {
                    u32 koA = (u32)(kc*5120 + sub*32);
                    u32 koB = (u32)(kc*20480 + sub*32);
                    uint4 ah = ldsm4(aH + koA);
                    uint4 al = ldsm4(aH + koA + 2560);
                    uint4 bh0 = ldsm4(aW2 + koB);
                    uint4 bh1 = ldsm4(aW2 + koB + 1280);
                    uint4 bl0 = ldsm4(aW2 + koB + 10240);
                    uint4 bl1 = ldsm4(aW2 + koB + 10240 + 1280);
                    mma16816(c2[0], ah, bh0.x, bh0.z);
                    mma16816(c2[1], ah, bh0.y, bh0.w);
                    mma16816(c2[2], ah, bh1.x, bh1.z);
                    mma16816(c2[3], ah, bh1.y, bh1.w);
                    mma16816(c2[0], ah, bl0.x, bl0.z);
                    mma16816(c2[1], ah, bl0.y, bl0.w);
                    mma16816(c2[2], ah, bl1.x, bl1.z);
                    mma16816(c2[3], ah, bl1.y, bl1.w);
                    mma16816(c2[0], al, bh0.x, bh0.z);
                    mma16816(c2[1], al, bh0.y, bh0.w);
                    mma16816(c2[2], al, bh1.x, bh1.z);
                    mma16816(c2[3], al, bh1.y, bh1.w);
                }
            }
        }
    }

    {
        const int cb = (lane & 3)*2;
        #pragma unroll
        for (int nt = 0; nt < 4; nt++) {
            int col = wc*32 + nt*8 + cb;
            float bb0 = b2[col], bb1 = b2[col+1];
            sC[r0*132 + col]       = c2[nt][0] + bb0;
            sC[r0*132 + col + 1]   = c2[nt][1] + bb1;
            sC[(r0+8)*132 + col]     = c2[nt][2] + bb0;
            sC[(r0+8)*132 + col + 1] = c2[nt][3] + bb1;
        }
    }
    __syncthreads();

    float4 g1v = *(const float4*)&ng1[lane*4];
    float4 b1v = *(const float4*)&nb1[lane*4];
    float4 g2v = make_float4(0,0,0,0), b2v = make_float4(0,0,0,0), fwv = make_float4(0,0,0,0);
    float fb = 0.f;
    if (MODE == 1) { g2v = *(const float4*)&ng2[lane*4]; b2v = *(const float4*)&nb2[lane*4]; }
    if (MODE == 2) { fwv = *(const float4*)&ng2[lane*4]; fb = nb2[0]; }

    #pragma unroll
    for (int rr = 0; rr < 4; rr++) {
        int rl2 = w*4 + rr;
        int row = m0 + rl2;
        float4 v = *(float4*)&sC[rl2*132 + lane*4];
        float4 rv = *(const float4*)&R[(size_t)row*128 + lane*4];
        v.x += rv.x; v.y += rv.y; v.z += rv.z; v.w += rv.w;

        float s  = v.x + v.y + v.z + v.w;
        float s2 = v.x*v.x + v.y*v.y + v.z*v.z + v.w*v.w;
        #pragma unroll
        for (int off = 16; off > 0; off >>= 1) {
            s  += __shfl_xor_sync(0xffffffffu, s,  off);
            s2 += __shfl_xor_sync(0xffffffffu, s2, off);
        }
        float mean = s * (1.0f/128.0f);
        float var  = s2 * (1.0f/128.0f) - mean*mean;
        float rstd = rsqrtf(var + 1e-5f);
        v.x = (v.x - mean)*rstd*g1v.x + b1v.x;
        v.y = (v.y - mean)*rstd*g1v.y + b1v.y;
        v.z = (v.z - mean)*rstd*g1v.z + b1v.z;
        v.w = (v.w - mean)*rstd*g1v.w + b1v.w;

        if (MODE == 1) {
            int lab = labels[row];
            float4 cv = *(const float4*)&catab[(size_t)lab*128 + lane*4];
            v.x += cv.x; v.y += cv.y; v.z += cv.z; v.w += cv.w;
            float t1 = v.x + v.y + v.z + v.w;
            float t2 = v.x*v.x + v.y*v.y + v.z*v.z + v.w*v.w;
            #pragma unroll
            for (int off = 16; off > 0; off >>= 1) {
                t1 += __shfl_xor_sync(0xffffffffu, t1, off);
                t2 += __shfl_xor_sync(0xffffffffu, t2, off);
            }
            float mean2 = t1 * (1.0f/128.0f);
            float var2  = t2 * (1.0f/128.0f) - mean2*mean2;
            float rstd2 = rsqrtf(var2 + 1e-5f);
            v.x = (v.x - mean2)*rstd2*g2v.x + b2v.x;
            v.y = (v.y - mean2)*rstd2*g2v.y + b2v.y;
            v.z = (v.z - mean2)*rstd2*g2v.z + b2v.z;
            v.w = (v.w - mean2)*rstd2*g2v.w + b2v.w;
        }

        if (MODE == 2) {
            float d = v.x*fwv.x + v.y*fwv.y + v.z*fwv.z + v.w*fwv.w;
            #pragma unroll
            for (int off = 16; off > 0; off >>= 1) d += __shfl_xor_sync(0xffffffffu, d, off);
            if (lane == 0) outf[row] = 1.0f/(1.0f + expf(-(d + fb)));
        } else {
            *(float4*)&outf[(size_t)row*128 + lane*4] = v;
            u32 hp, lp;
            size_t idx = ((size_t)row*128 + lane*4) >> 1;
            split2(v.x, v.y, hp, lp);
            ((u32*)oh)[idx]   = hp; ((u32*)ol)[idx]   = lp;
            split2(v.z, v.w, hp, lp);
            ((u32*)oh)[idx+1] = hp; ((u32*)ol)[idx+1] = lp;
        }
    }
}

// ---------------- flash attention: 256-row KV blocks (1 sync per block) ----------------
// 16 warps: warp (wq = w&3, hf = w>>2): q-rows wq*32.. x KV-column quarter hf*32..
__global__ __launch_bounds__(512, 1) void k_attn() {
    extern __shared__ __nv_bfloat16 smh[];
    __nv_bfloat16* Qs  = smh;               // 128 x 40
    __nv_bfloat16* Ks0 = smh + 5120;        // 256 x 40
    __nv_bfloat16* Ks1 = smh + 15360;
    __nv_bfloat16* Vs0 = smh + 25600;
    __nv_bfloat16* Vs1 = smh + 35840;
    float* cbuf = (float*)(smh + 46080);    // 3 x 128 x 36 floats

    const int h  = blockIdx.y;
    const int q0 = blockIdx.x * 128;
    const int tid  = threadIdx.x;
    const int lane = tid & 31;
    const int w    = tid >> 5;
    const int wq   = w & 3;
    const int hf   = w >> 2;

    const __nv_bfloat16* QKV = g_qkvh;

    const int sr = tid >> 2, sg = (tid & 3)*16;
    {
        const char* gq = (const char*)(QKV + (size_t)(q0 + sr)*384 + h*32);
        cpa16(s2u(Qs + sr*40) + sg, gq + sg);
        #pragma unroll
        for (int half = 0; half < 2; half++) {
            int row = half*128 + sr;
            const char* gk = (const char*)(QKV + (size_t)row*384 + 128 + h*32);
            cpa16(s2u(Ks0 + row*40) + sg, gk + sg);
            const char* gv = (const char*)(QKV + (size_t)row*384 + 256 + h*32);
            cpa16(s2u(Vs0 + row*40) + sg, gv + sg);
        }
    }
    cpa_commit();
    cpa_wait0();
    __syncthreads();

    const u32 frag_off = (u32)((lane & 15)*80 + (lane >> 4)*16);
    const u32 aQ  = s2u(Qs)  + (u32)(wq*32*80) + frag_off;
    const u32 qofs = (u32)hf * 2560u;
    const u32 aK0 = s2u(Ks0) + qofs + frag_off;
    const u32 aK1 = s2u(Ks1) + qofs + frag_off;
    const u32 aV0 = s2u(Vs0) + qofs + frag_off;
    const u32 aV1 = s2u(Vs1) + qofs + frag_off;

    uint4 qa[2][2];
    qa[0][0] = ldsm4(aQ);
    qa[0][1] = ldsm4(aQ + 32);
    qa[1][0] = ldsm4(aQ + 1280);
    qa[1][1] = ldsm4(aQ + 1280 + 32);

    float o[2][4][4];
    #pragma unroll
    for (int rg = 0; rg < 2; rg++)
        #pragma unroll
        for (int j = 0; j < 4; j++) { o[rg][j][0]=0.f; o[rg][j][1]=0.f; o[rg][j][2]=0.f; o[rg][j][3]=0.f; }
    float l[2][2] = {{0.f,0.f},{0.f,0.f}};

    for (int t = 0; t < 16; t++) {
        if (t < 15) {
            __nv_bfloat16* Kd = (t & 1) ? Ks0 : Ks1;
            __nv_bfloat16* Vd = (t & 1) ? Vs0 : Vs1;
            #pragma unroll
            for (int half = 0; half < 2; half++) {
                int lrow = half*128 + sr;
                int grow = (t+1)*256 + lrow;
                const char* gk = (const char*)(QKV + (size_t)grow*384 + 128 + h*32);
                cpa16(s2u(Kd + lrow*40) + sg, gk + sg);
                const char* gv = (const char*)(QKV + (size_t)grow*384 + 256 + h*32);
                cpa16(s2u(Vd + lrow*40) + sg, gv + sg);
            }
            cpa_commit();
        }
        const u32 aKbase = (t & 1) ? aK1 : aK0;
        const u32 aVbase = (t & 1) ? aV1 : aV0;

        #pragma unroll
        for (int half = 0; half < 2; half++) {
            const u32 aKb = aKbase + half*10240;
            const u32 aVb = aVbase + half*10240;

            float c[2][4][4];
            #pragma unroll
            for (int rg = 0; rg < 2; rg++)
                #pragma unroll
                for (int j = 0; j < 4; j++) { c[rg][j][0]=0.f; c[rg][j][1]=0.f; c[rg][j][2]=0.f; c[rg][j][3]=0.f; }

            #pragma unroll
            for (int g = 0; g < 2; g++) {
                uint4 k0 = ldsm4(aKb + g*1280);
                uint4 k1 = ldsm4(aKb + g*1280 + 32);
                #pragma unroll
                for (int rg = 0; rg < 2; rg++) {
                    mma16816(c[rg][2*g],   qa[rg][0], k0.x, k0.z);
                    mma16816(c[rg][2*g+1], qa[rg][0], k0.y, k0.w);
                    mma16816(c[rg][2*g],   qa[rg][1], k1.x, k1.z);
                    mma16816(c[rg][2*g+1], qa[rg][1], k1.y, k1.w);
                }
            }

            #pragma unroll
            for (int rg = 0; rg < 2; rg++) {
                #pragma unroll
                for (int j = 0; j < 4; j++) {
                    c[rg][j][0] = ex2f(c[rg][j][0]);
                    c[rg][j][1] = ex2f(c[rg][j][1]);
                    c[rg][j][2] = ex2f(c[rg][j][2]);
                    c[rg][j][3] = ex2f(c[rg][j][3]);
                    l[rg][0] += c[rg][j][0] + c[rg][j][1];
                    l[rg][1] += c[rg][j][2] + c[rg][j][3];
                }
            }

            #pragma unroll
            for (int kc = 0; kc < 2; kc++) {
                uint4 v0 = ldsm4t(aVb + kc*1280);
                uint4 v1 = ldsm4t(aVb + kc*1280 + 32);
                #pragma unroll
                for (int rg = 0; rg < 2; rg++) {
                    uint4 pa;
                    pa.x = cvtbf2(c[rg][2*kc][1],   c[rg][2*kc][0]);
                    pa.y = cvtbf2(c[rg][2*kc][3],   c[rg][2*kc][2]);
                    pa.z = cvtbf2(c[rg][2*kc+1][1], c[rg][2*kc+1][0]);
                    pa.w = cvtbf2(c[rg][2*kc+1][3], c[rg][2*kc+1][2]);
                    mma16816(o[rg][0], pa, v0.x, v0.y);
                    mma16816(o[rg][1], pa, v0.z, v0.w);
                    mma16816(o[rg][2], pa, v1.x, v1.y);
                    mma16816(o[rg][3], pa, v1.z, v1.w);
                }
            }
        }

        if (t < 15) cpa_wait0();
        __syncthreads();
    }

    if (hf > 0) {
        float* dst = cbuf + (size_t)(hf-1)*128*36 + (wq*32 + lane)*36;
        #pragma unroll
        for (int rg = 0; rg < 2; rg++)
            #pragma unroll
            for (int j = 0; j < 4; j++)
                *(float4*)&dst[rg*16 + j*4] = make_float4(o[rg][j][0], o[rg][j][1], o[rg][j][2], o[rg][j][3]);
        *(float4*)&dst[32] = make_float4(l[0][0], l[0][1], l[1][0], l[1][1]);
    }
    __syncthreads();
    if (hf > 0) return;

    #pragma unroll
    for (int b = 0; b < 3; b++) {
        const float* src = cbuf + (size_t)b*128*36 + (wq*32 + lane)*36;
        #pragma unroll
        for (int rg = 0; rg < 2; rg++)
            #pragma unroll
            for (int j = 0; j < 4; j++) {
                float4 s4 = *(const float4*)&src[rg*16 + j*4];
                o[rg][j][0] += s4.x; o[rg][j][1] += s4.y; o[rg][j][2] += s4.z; o[rg][j][3] += s4.w;
            }
        float4 ls = *(const float4*)&src[32];
        l[0][0] += ls.x; l[0][1] += ls.y; l[1][0] += ls.z; l[1][1] += ls.w;
    }

    #pragma unroll
    for (int rg = 0; rg < 2; rg++) {
        #pragma unroll
        for (int p = 0; p < 2; p++) {
            l[rg][p] += __shfl_xor_sync(0xffffffffu, l[rg][p], 1);
            l[rg][p] += __shfl_xor_sync(0xffffffffu, l[rg][p], 2);
        }
    }

    u32* OH = (u32*)g_attnh;
    u32* OL = (u32*)g_attnl;
    const int col = h*32 + (lane & 3)*2;
    #pragma unroll
    for (int rg = 0; rg < 2; rg++) {
        float li0 = 1.0f / l[rg][0], li1 = 1.0f / l[rg][1];
        int row0 = q0 + wq*32 + rg*16 + (lane >> 2);
        #pragma unroll
        for (int j = 0; j < 4; j++) {
            u32 hp, lp;
            split2(o[rg][j][0]*li0, o[rg][j][1]*li0, hp, lp);
            OH[((size_t)row0*128 + col + j*8) >> 1] = hp;
            OL[((size_t)row0*128 + col + j*8) >> 1] = lp;
            split2(o[rg][j][2]*li1, o[rg][j][3]*li1, hp, lp);
            OH[((size_t)(row0+8)*128 + col + j*8) >> 1] = hp;
            OL[((size_t)(row0+8)*128 + col + j*8) >> 1] = lp;
        }
    }
}

// ---------------- launch ----------------
extern "C" void kernel_launch(void* const* d_in, const int* in_sizes, int n_in,
                              void* d_out, int out_size) {
    const float* coords   = (const float*)d_in[0];
    const int*   labels   = (const int*)  d_in[1];
    const float* ce_w     = (const float*)d_in[2];
    const float* ce_b     = (const float*)d_in[3];
    const float* emb      = (const float*)d_in[4];
    const float* sa_in_w  = (const float*)d_in[5];
    const float* sa_in_b  = (const float*)d_in[6];
    const float* sa_out_w = (const float*)d_in[7];
    const float* sa_out_b = (const float*)d_in[8];
    const float* n1_g     = (const float*)d_in[9];
    const float* n1_b     = (const float*)d_in[10];
    const float* m1_w1    = (const float*)d_in[11];
    const float* m1_b1    = (const float*)d_in[12];
    const float* m1_w2    = (const float*)d_in[13];
    const float* m1_b2    = (const float*)d_in[14];
    const float* n2_g     = (const float*)d_in[15];
    const float* n2_b     = (const float*)d_in[16];
    const float* ca_in_w  = (const float*)d_in[17];
    const float* ca_in_b  = (const float*)d_in[18];
    const float* ca_out_w = (const float*)d_in[19];
    const float* ca_out_b = (const float*)d_in[20];
    const float* n3_g     = (const float*)d_in[21];
    const float* n3_b     = (const float*)d_in[22];
    const float* m2_w1    = (const float*)d_in[23];
    const float* m2_b1    = (const float*)d_in[24];
    const float* m2_w2    = (const float*)d_in[25];
    const float* m2_b2    = (const float*)d_in[26];
    const float* n4_g     = (const float*)d_in[27];
    const float* n4_b     = (const float*)d_in[28];
    const float* fin_w    = (const float*)d_in[29];
    const float* fin_b    = (const float*)d_in[30];
    float* out = (float*)d_out;

    float *px, *py, *pca;
    __nv_bfloat16 *pxh, *pxl, *pqkvh, *pah, *pal, *pwh, *pwl;
    cudaGetSymbolAddress((void**)&px,    g_x);
    cudaGetSymbolAddress((void**)&py,    g_y);
    cudaGetSymbolAddress((void**)&pxh,   g_xh);
    cudaGetSymbolAddress((void**)&pxl,   g_xl);
    cudaGetSymbolAddress((void**)&pqkvh, g_qkvh);
    cudaGetSymbolAddress((void**)&pah,   g_attnh);
    cudaGetSymbolAddress((void**)&pal,   g_attnl);
    cudaGetSymbolAddress((void**)&pwh,   g_wh);
    cudaGetSymbolAddress((void**)&pwl,   g_wl);
    cudaGetSymbolAddress((void**)&pca,   g_ca);

    const int ATTN_SMEM = (5120 + 4*10240)*2 + 3*128*36*4;   // 92160 + 55296 = 147456 B
    cudaFuncSetAttribute(k_attn, cudaFuncAttributeMaxDynamicSharedMemorySize, ATTN_SMEM);
    const int LN_SMEM = 68096;
    cudaFuncSetAttribute(k_gemmln<0>, cudaFuncAttributeMaxDynamicSharedMemorySize, LN_SMEM);
    const int MLP_SMEM = 190976;
    cudaFuncSetAttribute(k_mlpln<1>, cudaFuncAttributeMaxDynamicSharedMemorySize, MLP_SMEM);
    cudaFuncSetAttribute(k_mlpln<2>, cudaFuncAttributeMaxDynamicSharedMemorySize, MLP_SMEM);

    WSrc ws;
    ws.p[0] = sa_in_w;  ws.p[1] = sa_out_w; ws.p[2] = m1_w1;
    ws.p[3] = m1_w2;    ws.p[4] = m2_w1;    ws.p[5] = m2_w2;
    ws.end[0] = WO_SAOUT/2; ws.end[1] = WO_M1W1/2; ws.end[2] = WO_M1W2/2;
    ws.end[3] = WO_M2W1/2;  ws.end[4] = WO_M2W2/2; ws.end[5] = W_TOTAL/2;

    // setup: cvtw (640 blocks) + embed (2048 blocks) + ca (10 blocks) in ONE launch
    k_setup<<<2698, 256>>>(ws, pwh, pwl, coords, ce_w, ce_b,
                           emb, ca_in_w + 2*DD*DD, ca_in_b + 2*DD, ca_out_w, ca_out_b);
    // qkv
    k_gemm3<1,0><<<dim3(6, 64), 256>>>(pxh, pxl, pwh+WO_SAIN, pwl+WO_SAIN, sa_in_b, pqkvh, nullptr, 384, 128);
    k_attn<<<dim3(32, 4), 512, ATTN_SMEM>>>();
    // sa_out + residual + LN1 -> px fp32 + pxh/pxl
    k_gemmln<0><<<128, 256, LN_SMEM>>>(pah, pal, pwh+WO_SAOUT, pwl+WO_SAOUT, sa_out_b, px,
                                       n1_g, n1_b, px, pxh, pxl, 128);
    // fused MLP1 + LN2 + ca + LN3 -> py fp32 + pxh/pxl
    k_mlpln<1><<<128, 256, MLP_SMEM>>>(pxh, pxl, pwh+WO_M1W1, pwl+WO_M1W1, m1_b1,
                                       pwh+WO_M1W2, pwl+WO_M1W2, m1_b2, px,
                                       n2_g, n2_b, n3_g, n3_b, pca, labels,
                                       py, pxh, pxl);
    // fused MLP2 + LN4 + final sigmoid -> out
    k_mlpln<2><<<128, 256, MLP_SMEM>>>(pxh, pxl, pwh+WO_M2W1, pwl+WO_M2W1, m2_b1,
                                       pwh+WO_M2W2, pwl+WO_M2W2, m2_b2, py,
                                       n4_g, n4_b, fin_w, fin_b, nullptr, nullptr,
                                       out, nullptr, nullptr);
}

// round 13
// speedup vs baseline: 1.0266x; 1.0266x over previous
#include <cuda_runtime.h>
#include <cuda_bf16.h>
#include <math.h>

#define BB 4096
#define DD 128

typedef unsigned int u32;

// ---- tensor-core helpers ----
__device__ __forceinline__ uint4 ldsm4(u32 addr) {
    uint4 r;
    asm volatile("ldmatrix.sync.aligned.m8n8.x4.shared.b16 {%0,%1,%2,%3},[%4];"
        : "=r"(r.x), "=r"(r.y), "=r"(r.z), "=r"(r.w) : "r"(addr));
    return r;
}
__device__ __forceinline__ uint4 ldsm4t(u32 addr) {
    uint4 r;
    asm volatile("ldmatrix.sync.aligned.m8n8.x4.trans.shared.b16 {%0,%1,%2,%3},[%4];"
        : "=r"(r.x), "=r"(r.y), "=r"(r.z), "=r"(r.w) : "r"(addr));
    return r;
}
__device__ __forceinline__ void mma16816(float* c, uint4 a, u32 b0, u32 b1) {
    asm volatile(
        "mma.sync.aligned.m16n8k16.row.col.f32.bf16.bf16.f32 "
        "{%0,%1,%2,%3},{%4,%5,%6,%7},{%8,%9},{%0,%1,%2,%3};"
        : "+f"(c[0]), "+f"(c[1]), "+f"(c[2]), "+f"(c[3])
        : "r"(a.x), "r"(a.y), "r"(a.z), "r"(a.w), "r"(b0), "r"(b1));
}
__device__ __forceinline__ float ex2f(float x) {
    float y; asm("ex2.approx.f32 %0,%1;" : "=f"(y) : "f"(x)); return y;
}
__device__ __forceinline__ u32 cvtbf2(float hi, float lo) {
    u32 r; asm("cvt.rn.bf16x2.f32 %0,%1,%2;" : "=r"(r) : "f"(hi), "f"(lo)); return r;
}
__device__ __forceinline__ u32 s2u(const void* p) {
    return (u32)__cvta_generic_to_shared(p);
}
__device__ __forceinline__ void split2(float v0, float v1, u32& hp, u32& lp) {
    hp = cvtbf2(v1, v0);
    float h0 = __uint_as_float(hp << 16);
    float h1 = __uint_as_float(hp & 0xffff0000u);
    lp = cvtbf2(v1 - h1, v0 - h0);
}
__device__ __forceinline__ void cpa16(u32 dst, const void* src) {
    asm volatile("cp.async.cg.shared.global [%0],[%1],16;" :: "r"(dst), "l"(src));
}
__device__ __forceinline__ void cpa_commit() {
    asm volatile("cp.async.commit_group;");
}
__device__ __forceinline__ void cpa_wait0() {
    asm volatile("cp.async.wait_group 0;");
}
__device__ __forceinline__ void cpa_wait1() {
    asm volatile("cp.async.wait_group 1;");
}

#define QSCALE 0.17677669529663688f
#define LOG2E  1.4426950408889634f

// ---------------- scratch ----------------
__device__ float g_x[BB*DD];
__device__ float g_y[BB*DD];
__device__ __nv_bfloat16 g_xh[BB*DD];
__device__ __nv_bfloat16 g_xl[BB*DD];
__device__ __nv_bfloat16 g_qkvh[BB*3*DD];
__device__ __nv_bfloat16 g_attnh[BB*DD];
__device__ __nv_bfloat16 g_attnl[BB*DD];
__device__ __nv_bfloat16 g_wh[327680];
__device__ __nv_bfloat16 g_wl[327680];
__device__ float g_ca[10*DD];

#define WO_SAIN  0
#define WO_SAOUT 49152
#define WO_M1W1  65536
#define WO_M1W2  131072
#define WO_M2W1  196608
#define WO_M2W2  262144
#define W_TOTAL  327680

// ---------------- setup: weight convert + embed + ca table in ONE launch ----------------
struct WSrc { const float* p[6]; int end[6]; };
__global__ __launch_bounds__(256) void k_setup(WSrc a, __nv_bfloat16* dh, __nv_bfloat16* dl,
    const float* __restrict__ coords, const float* __restrict__ ce_w, const float* __restrict__ ce_b,
    const float* __restrict__ emb, const float* __restrict__ wv, const float* __restrict__ bv,
    const float* __restrict__ wo, const float* __restrict__ bo)
{
    int b = blockIdx.x;
    int tid = threadIdx.x;
    if (b < 640) {
        int i = b*256 + tid;
        if (i >= a.end[5]) return;
        int k = 0;
        #pragma unroll
        for (int j = 1; j < 6; j++) if (i >= a.end[j-1]) k = j;
        int beg = (k > 0) ? a.end[k-1] : 0;
        float2 v = ((const float2*)a.p[k])[i - beg];
        u32 hp, lp; split2(v.x, v.y, hp, lp);
        ((u32*)dh)[i] = hp;
        ((u32*)dl)[i] = lp;
    } else if (b < 2688) {
        int i = (b - 640)*2 + (tid >> 7);
        int d = tid & 127;
        float c0 = coords[2*i], c1 = coords[2*i+1];
        int j = d >> 1;
        float dv = expf(9.210340371976184f * (float)j * (1.0f/64.0f));
        float pe = (d & 1) ? cosf(c1 / dv) : sinf(c0 / dv);
        float v = c0*ce_w[2*d] + c1*ce_w[2*d+1] + ce_b[d] + pe;
        g_x[i*DD + d] = v;
        __nv_bfloat16 h = __float2bfloat16_rn(v);
        g_xh[i*DD + d] = h;
        g_xl[i*DD + d] = __float2bfloat16_rn(v - __bfloat162float(h));
    } else {
        __shared__ float e[128], t[128];
        int c = b - 2688, j = tid;
        if (j < 128) e[j] = emb[c*128 + j];
        __syncthreads();
        if (j < 128) {
            float s = bv[j];
            #pragma unroll 8
            for (int d0 = 0; d0 < 128; d0++) s += e[d0]*wv[j*128 + d0];
            t[j] = s;
        }
        __syncthreads();
        if (j < 128) {
            float s2 = bo[j];
            #pragma unroll 8
            for (int d0 = 0; d0 < 128; d0++) s2 += t[d0]*wo[j*128 + d0];
            g_ca[c*128 + j] = s2;
        }
    }
}

// ---------------- 3xBF16 GEMM, 64x64 tile (qkv) ----------------
template<int OUTMODE, int ACT>
__global__ __launch_bounds__(256) void k_gemm3(
    const __nv_bfloat16* __restrict__ Ah, const __nv_bfloat16* __restrict__ Al,
    const __nv_bfloat16* __restrict__ Wh, const __nv_bfloat16* __restrict__ Wl,
    const float* __restrict__ bias,
    void* __restrict__ out1, void* __restrict__ out2, int N, int K)
{
    __shared__ __nv_bfloat16 sA[2][2][64][40];
    __shared__ __nv_bfloat16 sW[2][2][64][40];

    const int tid = threadIdx.x;
    const int lane = tid & 31, w = tid >> 5;
    const int wr = w & 3, wc = w >> 2;
    const int m0 = blockIdx.y*64, n0 = blockIdx.x*64;
    const int r = tid >> 2, q = tid & 3;
    const int nc = K >> 5;

    const __nv_bfloat16* pAh = Ah + (size_t)(m0+r)*K + q*8;
    const __nv_bfloat16* pAl = Al + (size_t)(m0+r)*K + q*8;
    const __nv_bfloat16* pWh = Wh + (size_t)(n0+r)*K + q*8;
    const __nv_bfloat16* pWl = Wl + (size_t)(n0+r)*K + q*8;

    {
        uint4 va = *(const uint4*)pAh;
        uint4 vl = *(const uint4*)pAl;
        uint4 vw = *(const uint4*)pWh;
        uint4 vx = *(const uint4*)pWl;
        *(uint4*)&sA[0][0][r][q*8] = va;
        *(uint4*)&sA[0][1][r][q*8] = vl;
        *(uint4*)&sW[0][0][r][q*8] = vw;
        *(uint4*)&sW[0][1][r][q*8] = vx;
    }
    __syncthreads();

    float c[4][4];
    #pragma unroll
    for (int j = 0; j < 4; j++) { c[j][0]=0.f; c[j][1]=0.f; c[j][2]=0.f; c[j][3]=0.f; }

    const u32 frag_off = (u32)((lane & 15)*80 + (lane >> 4)*16);
    const u32 aA = s2u(&sA[0][0][0][0]) + (u32)(wr*16*80) + frag_off;
    const u32 aW = s2u(&sW[0][0][0][0]) + (u32)(wc*32*80) + frag_off;

    for (int t = 0; t < nc; t++) {
        uint4 va, vl, vw, vx;
        if (t + 1 < nc) {
            int o = (t+1)*32;
            va = *(const uint4*)(pAh+o);
            vl = *(const uint4*)(pAl+o);
            vw = *(const uint4*)(pWh+o);
            vx = *(const uint4*)(pWl+o);
        }
        u32 bofs = (u32)(t & 1) * 10240u;
        #pragma unroll
        for (int sub = 0; sub < 2; sub++) {
            u32 ko = bofs + sub*32;
            uint4 fAh = ldsm4(aA + ko);
            uint4 fAl = ldsm4(aA + ko + 5120);
            uint4 bh0 = ldsm4(aW + ko);
            uint4 bh1 = ldsm4(aW + ko + 1280);
            uint4 bl0 = ldsm4(aW + ko + 5120);
            uint4 bl1 = ldsm4(aW + ko + 5120 + 1280);
            mma16816(c[0], fAh, bh0.x, bh0.z);
            mma16816(c[1], fAh, bh0.y, bh0.w);
            mma16816(c[2], fAh, bh1.x, bh1.z);
            mma16816(c[3], fAh, bh1.y, bh1.w);
            mma16816(c[0], fAh, bl0.x, bl0.z);
            mma16816(c[1], fAh, bl0.y, bl0.w);
            mma16816(c[2], fAh, bl1.x, bl1.z);
            mma16816(c[3], fAh, bl1.y, bl1.w);
            mma16816(c[0], fAl, bh0.x, bh0.z);
            mma16816(c[1], fAl, bh0.y, bh0.w);
            mma16816(c[2], fAl, bh1.x, bh1.z);
            mma16816(c[3], fAl, bh1.y, bh1.w);
        }
        if (t + 1 < nc) {
            int nb = (t & 1) ^ 1;
            *(uint4*)&sA[nb][0][r][q*8] = va;
            *(uint4*)&sA[nb][1][r][q*8] = vl;
            *(uint4*)&sW[nb][0][r][q*8] = vw;
            *(uint4*)&sW[nb][1][r][q*8] = vx;
        }
        __syncthreads();
    }

    const int row = m0 + wr*16 + (lane >> 2);
    const int cbase = n0 + wc*32;
    const int cb = (lane & 3)*2;
    #pragma unroll
    for (int nt = 0; nt < 4; nt++) {
        int col = cbase + nt*8 + cb;
        float b0 = bias[col], b1 = bias[col+1];
        float v0 = c[nt][0]+b0, v1 = c[nt][1]+b1;
        float v2 = c[nt][2]+b0, v3 = c[nt][3]+b1;
        if (OUTMODE == 1) {
            u32* O = (u32*)out1;
            float sc = (col < 128) ? (QSCALE*LOG2E) : 1.0f;
            O[((size_t)row*N + col) >> 1]     = cvtbf2(v1*sc, v0*sc);
            O[((size_t)(row+8)*N + col) >> 1] = cvtbf2(v3*sc, v2*sc);
        }
    }
}

// ---------------- fused (sa_out+LN1)? + MLP + LN(+ca+LN / +final) ----------------
// SAOUT=1: prestage computes x = LN1(g_x + attn@Wo^T + sab) in smem (fp32 + hi/lo frags)
// MODE 1: LN(ng1,nb1); +catab[label]; LN(ng2,nb2) -> outf fp32 + oh/ol
// MODE 2: LN(ng1,nb1); dot(ng2=fin_w)+nb2[0] -> sigmoid -> outf[row]
template<int MODE, int SAOUT>
__global__ __launch_bounds__(256) void k_mlpln(
    const __nv_bfloat16* __restrict__ Ah, const __nv_bfloat16* __restrict__ Al,
    const __nv_bfloat16* __restrict__ W1h, const __nv_bfloat16* __restrict__ W1l,
    const float* __restrict__ b1,
    const __nv_bfloat16* __restrict__ W2h, const __nv_bfloat16* __restrict__ W2l,
    const float* __restrict__ b2,
    const float* __restrict__ R,
    const float* __restrict__ ng1, const float* __restrict__ nb1,
    const float* __restrict__ ng2, const float* __restrict__ nb2,
    const float* __restrict__ catab, const int* __restrict__ labels,
    float* __restrict__ outf, __nv_bfloat16* __restrict__ oh, __nv_bfloat16* __restrict__ ol,
    const __nv_bfloat16* __restrict__ Woh, const __nv_bfloat16* __restrict__ Wol,
    const float* __restrict__ sab, const float* __restrict__ Rpre,
    const float* __restrict__ ln1g, const float* __restrict__ ln1b)
{
    extern __shared__ char sm[];
    const u32 SW1 = 0;         // 81920
    const u32 SW2 = 81920;     // 81920
    const u32 SH  = 163840;    // 10240
    const u32 SC  = 174080;    // 16896
    const u32 SX  = 190976;    // 16384 (SAOUT only)
    float* sC = (float*)(sm + SC);
    float* sX = (float*)(sm + SX);

    const int tid = threadIdx.x;
    const int lane = tid & 31, w = tid >> 5;
    const int wr = w & 1, wc = w >> 1;
    const int m0 = blockIdx.x * 32;
    const u32 smb = s2u(sm);
    const u32 frag_off = (u32)((lane & 15)*80 + (lane >> 4)*16);
    const int r0 = wr*16 + (lane >> 2);

    if (SAOUT) {
        // stage attn A (32 rows hi/lo) into SW2 + Wo (128x128 hi/lo) into SW1
        #pragma unroll
        for (int i = 0; i < 4; i++) {
            int idx = tid + i*256;
            int kc = idx >> 8; int rem = idx & 255; int mat = rem >> 7; int rm = rem & 127;
            int row = rm >> 2; int seg = rm & 3;
            const __nv_bfloat16* src = (mat ? Al : Ah) + (size_t)(m0+row)*128 + kc*32 + seg*8;
            cpa16(smb + SW2 + (u32)(kc*5120 + mat*2560 + row*80 + seg*16), src);
        }
        #pragma unroll
        for (int i = 0; i < 16; i++) {
            int idx = tid + i*256;
            int seg = idx & 3; int row = (idx >> 2) & 127; int mat = (idx >> 9) & 1; int kc = idx >> 10;
            const __nv_bfloat16* src = (mat ? Wol : Woh) + (size_t)row*128 + kc*32 + seg*8;
            cpa16(smb + SW1 + (u32)(kc*20480 + mat*10240 + row*80 + seg*16), src);
        }
        cpa_commit();
        cpa_wait0();
        __syncthreads();

        // GEMM: attn @ Wo^T
        float cp[4][4];
        #pragma unroll
        for (int j = 0; j < 4; j++) { cp[j][0]=0.f; cp[j][1]=0.f; cp[j][2]=0.f; cp[j][3]=0.f; }
        {
            u32 aA = smb + SW2 + (u32)(wr*16*80) + frag_off;
            u32 aW = smb + SW1 + (u32)(wc*32*80) + frag_off;
            #pragma unroll
            for (int kc = 0; kc < 4; kc++) {
                #pragma unroll
                for (int sub = 0; sub < 2; sub++) {
                    u32 koA = (u32)(kc*5120 + sub*32);
                    u32 koB = (u32)(kc*20480 + sub*32);
                    uint4 fAh = ldsm4(aA + koA);
                    uint4 fAl = ldsm4(aA + koA + 2560);
                    uint4 bh0 = ldsm4(aW + koB);
                    uint4 bh1 = ldsm4(aW + koB + 1280);
                    uint4 bl0 = ldsm4(aW + koB + 10240);
                    uint4 bl1 = ldsm4(aW + koB + 11520);
                    mma16816(cp[0], fAh, bh0.x, bh0.z);
                    mma16816(cp[1], fAh, bh0.y, bh0.w);
                    mma16816(cp[2], fAh, bh1.x, bh1.z);
                    mma16816(cp[3], fAh, bh1.y, bh1.w);
                    mma16816(cp[0], fAh, bl0.x, bl0.z);
                    mma16816(cp[1], fAh, bl0.y, bl0.w);
                    mma16816(cp[2], fAh, bl1.x, bl1.z);
                    mma16816(cp[3], fAh, bl1.y, bl1.w);
                    mma16816(cp[0], fAl, bh0.x, bh0.z);
                    mma16816(cp[1], fAl, bh0.y, bh0.w);
                    mma16816(cp[2], fAl, bh1.x, bh1.z);
                    mma16816(cp[3], fAl, bh1.y, bh1.w);
                }
            }
        }
        {
            const int cb = (lane & 3)*2;
            #pragma unroll
            for (int nt = 0; nt < 4; nt++) {
                int col = wc*32 + nt*8 + cb;
                float bb0 = sab[col], bb1 = sab[col+1];
                sC[r0*132 + col]       = cp[nt][0] + bb0;
                sC[r0*132 + col + 1]   = cp[nt][1] + bb1;
                sC[(r0+8)*132 + col]     = cp[nt][2] + bb0;
                sC[(r0+8)*132 + col + 1] = cp[nt][3] + bb1;
            }
        }
        __syncthreads();

        // LN1: x = LN(g_x + c); store fp32 -> sX, hi/lo frag-layout -> SW2
        float4 g1v = *(const float4*)&ln1g[lane*4];
        float4 b1v = *(const float4*)&ln1b[lane*4];
        #pragma unroll
        for (int rr = 0; rr < 4; rr++) {
            int rl2 = w*4 + rr;
            int row = m0 + rl2;
            float4 v = *(float4*)&sC[rl2*132 + lane*4];
            float4 rv = *(const float4*)&Rpre[(size_t)row*128 + lane*4];
            v.x += rv.x; v.y += rv.y; v.z += rv.z; v.w += rv.w;
            float s  = v.x + v.y + v.z + v.w;
            float s2 = v.x*v.x + v.y*v.y + v.z*v.z + v.w*v.w;
            #pragma unroll
            for (int off = 16; off > 0; off >>= 1) {
                s  += __shfl_xor_sync(0xffffffffu, s,  off);
                s2 += __shfl_xor_sync(0xffffffffu, s2, off);
            }
            float mean = s * (1.0f/128.0f);
            float var  = s2 * (1.0f/128.0f) - mean*mean;
            float rstd = rsqrtf(var + 1e-5f);
            v.x = (v.x - mean)*rstd*g1v.x + b1v.x;
            v.y = (v.y - mean)*rstd*g1v.y + b1v.y;
            v.z = (v.z - mean)*rstd*g1v.z + b1v.z;
            v.w = (v.w - mean)*rstd*g1v.w + b1v.w;
            *(float4*)&sX[rl2*128 + lane*4] = v;
            // hi/lo to SW2 staging layout [kc][mat][32][40]
            int kc = lane >> 3;
            int cc = (lane*4) & 31;
            char* p0 = sm + SW2 + kc*5120 + rl2*80 + cc*2;
            u32 hp, lp;
            split2(v.x, v.y, hp, lp);
            *(u32*)p0 = hp; *(u32*)(p0 + 2560) = lp;
            split2(v.z, v.w, hp, lp);
            *(u32*)(p0 + 4) = hp; *(u32*)(p0 + 2560 + 4) = lp;
        }
        __syncthreads();
    } else {
        // stage x tile from global into SW2
        #pragma unroll
        for (int i = 0; i < 4; i++) {
            int idx = tid + i*256;
            int kc = idx >> 8;
            int rem = idx & 255;
            int mat = rem >> 7;
            int rm  = rem & 127;
            int row = rm >> 2;
            int seg = rm & 3;
            const __nv_bfloat16* src = (mat ? Al : Ah) + (size_t)(m0+row)*128 + kc*32 + seg*8;
            cpa16(smb + SW2 + (u32)(kc*5120 + mat*2560 + row*80 + seg*16), src);
        }
        cpa_commit();
        cpa_wait0();
        __syncthreads();
    }

    // ---- x fragments to registers ----
    uint4 fXh[4][2], fXl[4][2];
    {
        u32 aX = smb + SW2 + (u32)(wr*16*80) + frag_off;
        #pragma unroll
        for (int kc = 0; kc < 4; kc++) {
            fXh[kc][0] = ldsm4(aX + kc*5120);
            fXh[kc][1] = ldsm4(aX + kc*5120 + 32);
            fXl[kc][0] = ldsm4(aX + kc*5120 + 2560);
            fXl[kc][1] = ldsm4(aX + kc*5120 + 2560 + 32);
        }
    }
    __syncthreads();

    auto stageW = [&](int nh, int b) {
        #pragma unroll
        for (int i = 0; i < 8; i++) {
            int idx = tid + i*256;
            int kc = idx >> 9;
            int rem = idx & 511;
            int mat = rem >> 8;
            int rm = rem & 255;
            int row = rm >> 2;
            int seg = rm & 3;
            const __nv_bfloat16* src = (mat ? W1l : W1h) + (size_t)(nh*64+row)*128 + kc*32 + seg*8;
            cpa16(smb + SW1 + (u32)(b*40960 + kc*10240 + mat*5120 + row*80 + seg*16), src);
        }
        #pragma unroll
        for (int i = 0; i < 8; i++) {
            int idx = tid + i*256;
            int kc = idx >> 10;
            int rem = idx & 1023;
            int mat = rem >> 9;
            int rm = rem & 511;
            int row = rm >> 2;
            int seg = rm & 3;
            const __nv_bfloat16* src = (mat ? W2l : W2h) + (size_t)row*512 + nh*64 + kc*32 + seg*8;
            cpa16(smb + SW2 + (u32)(b*40960 + kc*20480 + mat*10240 + row*80 + seg*16), src);
        }
    };

    stageW(0, 0);
    cpa_commit();

    float c2[4][4];
    #pragma unroll
    for (int j = 0; j < 4; j++) { c2[j][0]=0.f; c2[j][1]=0.f; c2[j][2]=0.f; c2[j][3]=0.f; }

    for (int nh = 0; nh < 8; nh++) {
        const int b = nh & 1;
        __syncthreads();
        if (nh + 1 < 8) { stageW(nh+1, b^1); cpa_commit(); cpa_wait1(); }
        else cpa_wait0();
        __syncthreads();

        float c1[2][4];
        c1[0][0]=0.f; c1[0][1]=0.f; c1[0][2]=0.f; c1[0][3]=0.f;
        c1[1][0]=0.f; c1[1][1]=0.f; c1[1][2]=0.f; c1[1][3]=0.f;
        {
            u32 aW1 = smb + SW1 + (u32)(b*40960) + (u32)(wc*16*80) + frag_off;
            #pragma unroll
            for (int kc = 0; kc < 4; kc++) {
                #pragma unroll
                for (int sub = 0; sub < 2; sub++) {
                    u32 ko = (u32)(kc*10240 + sub*32);
                    uint4 bh = ldsm4(aW1 + ko);
                    uint4 bl = ldsm4(aW1 + ko + 5120);
                    uint4 fh = fXh[kc][sub], fl = fXl[kc][sub];
                    mma16816(c1[0], fh, bh.x, bh.z);
                    mma16816(c1[1], fh, bh.y, bh.w);
                    mma16816(c1[0], fh, bl.x, bl.z);
                    mma16816(c1[1], fh, bl.y, bl.w);
                    mma16816(c1[0], fl, bh.x, bh.z);
                    mma16816(c1[1], fl, bh.y, bh.w);
                }
            }
        }
        #pragma unroll
        for (int nt = 0; nt < 2; nt++) {
            int hc = wc*16 + nt*8 + (lane & 3)*2;
            float bb0 = b1[nh*64 + hc], bb1 = b1[nh*64 + hc + 1];
            float v0 = c1[nt][0]+bb0, v1 = c1[nt][1]+bb1;
            float v2 = c1[nt][2]+bb0, v3 = c1[nt][3]+bb1;
            v0 = 0.5f*v0*(1.0f + erff(v0*0.7071067811865475f));
            v1 = 0.5f*v1*(1.0f + erff(v1*0.7071067811865475f));
            v2 = 0.5f*v2*(1.0f + erff(v2*0.7071067811865475f));
            v3 = 0.5f*v3*(1.0f + erff(v3*0.7071067811865475f));
            int kc2 = hc >> 5, cc = hc & 31;
            char* p0 = sm + SH + kc2*5120 + r0*80 + cc*2;
            u32 hp, lp;
            split2(v0, v1, hp, lp);
            *(u32*)p0 = hp; *(u32*)(p0 + 2560) = lp;
            split2(v2, v3, hp, lp);
            *(u32*)(p0 + 640) = hp; *(u32*)(p0 + 640 + 2560) = lp;
        }
        __syncthreads();

        {
            u32 aH  = smb + SH + (u32)(wr*16*80) + frag_off;
            u32 aW2 = smb + SW2 + (u32)(b*40960) + (u32)(wc*32*80) + frag_off;
            #pragma unroll
            for (int kc = 0; kc < 2; kc++) {
                #pragma unroll
                for (int sub = 0; sub < 2; sub++) {
                    u32 koA = (u32)(kc*5120 + sub*32);
                    u32 koB = (u32)(kc*20480 + sub*32);
                    uint4 ah = ldsm4(aH + koA);
                    uint4 al = ldsm4(aH + koA + 2560);
                    uint4 bh0 = ldsm4(aW2 + koB);
                    uint4 bh1 = ldsm4(aW2 + koB + 1280);
                    uint4 bl0 = ldsm4(aW2 + koB + 10240);
                    uint4 bl1 = ldsm4(aW2 + koB + 10240 + 1280);
                    mma16816(c2[0], ah, bh0.x, bh0.z);
                    mma16816(c2[1], ah, bh0.y, bh0.w);
                    mma16816(c2[2], ah, bh1.x, bh1.z);
                    mma16816(c2[3], ah, bh1.y, bh1.w);
                    mma16816(c2[0], ah, bl0.x, bl0.z);
                    mma16816(c2[1], ah, bl0.y, bl0.w);
                    mma16816(c2[2], ah, bl1.x, bl1.z);
                    mma16816(c2[3], ah, bl1.y, bl1.w);
                    mma16816(c2[0], al, bh0.x, bh0.z);
                    mma16816(c2[1], al, bh0.y, bh0.w);
                    mma16816(c2[2], al, bh1.x, bh1.z);
                    mma16816(c2[3], al, bh1.y, bh1.w);
                }
            }
        }
    }

    {
        const int cb = (lane & 3)*2;
        #pragma unroll
        for (int nt = 0; nt < 4; nt++) {
            int col = wc*32 + nt*8 + cb;
            float bb0 = b2[col], bb1 = b2[col+1];
            sC[r0*132 + col]       = c2[nt][0] + bb0;
            sC[r0*132 + col + 1]   = c2[nt][1] + bb1;
            sC[(r0+8)*132 + col]     = c2[nt][2] + bb0;
            sC[(r0+8)*132 + col + 1] = c2[nt][3] + bb1;
        }
    }
    __syncthreads();

    float4 g1v = *(const float4*)&ng1[lane*4];
    float4 b1v = *(const float4*)&nb1[lane*4];
    float4 g2v = make_float4(0,0,0,0), b2v = make_float4(0,0,0,0), fwv = make_float4(0,0,0,0);
    float fb = 0.f;
    if (MODE == 1) { g2v = *(const float4*)&ng2[lane*4]; b2v = *(const float4*)&nb2[lane*4]; }
    if (MODE == 2) { fwv = *(const float4*)&ng2[lane*4]; fb = nb2[0]; }

    #pragma unroll
    for (int rr = 0; rr < 4; rr++) {
        int rl2 = w*4 + rr;
        int row = m0 + rl2;
        float4 v = *(float4*)&sC[rl2*132 + lane*4];
        float4 rv;
        if (SAOUT) rv = *(float4*)&sX[rl2*128 + lane*4];
        else       rv = *(const float4*)&R[(size_t)row*128 + lane*4];
        v.x += rv.x; v.y += rv.y; v.z += rv.z; v.w += rv.w;

        float s  = v.x + v.y + v.z + v.w;
        float s2 = v.x*v.x + v.y*v.y + v.z*v.z + v.w*v.w;
        #pragma unroll
        for (int off = 16; off > 0; off >>= 1) {
            s  += __shfl_xor_sync(0xffffffffu, s,  off);
            s2 += __shfl_xor_sync(0xffffffffu, s2, off);
        }
        float mean = s * (1.0f/128.0f);
        float var  = s2 * (1.0f/128.0f) - mean*mean;
        float rstd = rsqrtf(var + 1e-5f);
        v.x = (v.x - mean)*rstd*g1v.x + b1v.x;
        v.y = (v.y - mean)*rstd*g1v.y + b1v.y;
        v.z = (v.z - mean)*rstd*g1v.z + b1v.z;
        v.w = (v.w - mean)*rstd*g1v.w + b1v.w;

        if (MODE == 1) {
            int lab = labels[row];
            float4 cv = *(const float4*)&catab[(size_t)lab*128 + lane*4];
            v.x += cv.x; v.y += cv.y; v.z += cv.z; v.w += cv.w;
            float t1 = v.x + v.y + v.z + v.w;
            float t2 = v.x*v.x + v.y*v.y + v.z*v.z + v.w*v.w;
            #pragma unroll
            for (int off = 16; off > 0; off >>= 1) {
                t1 += __shfl_xor_sync(0xffffffffu, t1, off);
                t2 += __shfl_xor_sync(0xffffffffu, t2, off);
            }
            float mean2 = t1 * (1.0f/128.0f);
            float var2  = t2 * (1.0f/128.0f) - mean2*mean2;
            float rstd2 = rsqrtf(var2 + 1e-5f);
            v.x = (v.x - mean2)*rstd2*g2v.x + b2v.x;
            v.y = (v.y - mean2)*rstd2*g2v.y + b2v.y;
            v.z = (v.z - mean2)*rstd2*g2v.z + b2v.z;
            v.w = (v.w - mean2)*rstd2*g2v.w + b2v.w;
        }

        if (MODE == 2) {
            float d = v.x*fwv.x + v.y*fwv.y + v.z*fwv.z + v.w*fwv.w;
            #pragma unroll
            for (int off = 16; off > 0; off >>= 1) d += __shfl_xor_sync(0xffffffffu, d, off);
            if (lane == 0) outf[row] = 1.0f/(1.0f + expf(-(d + fb)));
        } else {
            *(float4*)&outf[(size_t)row*128 + lane*4] = v;
            u32 hp, lp;
            size_t idx = ((size_t)row*128 + lane*4) >> 1;
            split2(v.x, v.y, hp, lp);
            ((u32*)oh)[idx]   = hp; ((u32*)ol)[idx]   = lp;
            split2(v.z, v.w, hp, lp);
            ((u32*)oh)[idx+1] = hp; ((u32*)ol)[idx+1] = lp;
        }
    }
}

// ---------------- flash attention (round-11 measured version: 128-row KV tiles) ----------------
__global__ __launch_bounds__(512, 1) void k_attn() {
    extern __shared__ __nv_bfloat16 smh[];
    __nv_bfloat16* Qs  = smh;
    __nv_bfloat16* Ks0 = smh + 5120;
    __nv_bfloat16* Ks1 = smh + 10240;
    __nv_bfloat16* Vs0 = smh + 15360;
    __nv_bfloat16* Vs1 = smh + 20480;
    float* cbuf = (float*)(smh + 25600);

    const int h  = blockIdx.y;
    const int q0 = blockIdx.x * 128;
    const int tid  = threadIdx.x;
    const int lane = tid & 31;
    const int w    = tid >> 5;
    const int wq   = w & 3;
    const int hf   = w >> 2;

    const __nv_bfloat16* QKV = g_qkvh;

    const int sr = tid >> 2, sg = (tid & 3)*16;
    {
        const char* gq = (const char*)(QKV + (size_t)(q0 + sr)*384 + h*32);
        cpa16(s2u(Qs + sr*40) + sg, gq + sg);
        const char* gk = (const char*)(QKV + (size_t)sr*384 + 128 + h*32);
        cpa16(s2u(Ks0 + sr*40) + sg, gk + sg);
        const char* gv = (const char*)(QKV + (size_t)sr*384 + 256 + h*32);
        cpa16(s2u(Vs0 + sr*40) + sg, gv + sg);
    }
    cpa_commit();
    cpa_wait0();
    __syncthreads();

    const u32 frag_off = (u32)((lane & 15)*80 + (lane >> 4)*16);
    const u32 aQ  = s2u(Qs)  + (u32)(wq*32*80) + frag_off;
    const u32 qofs = (u32)hf * 2560u;
    const u32 aK0 = s2u(Ks0) + qofs + frag_off;
    const u32 aK1 = s2u(Ks1) + qofs + frag_off;
    const u32 aV0 = s2u(Vs0) + qofs + frag_off;
    const u32 aV1 = s2u(Vs1) + qofs + frag_off;

    uint4 qa[2][2];
    qa[0][0] = ldsm4(aQ);
    qa[0][1] = ldsm4(aQ + 32);
    qa[1][0] = ldsm4(aQ + 1280);
    qa[1][1] = ldsm4(aQ + 1280 + 32);

    float o[2][4][4];
    #pragma unroll
    for (int rg = 0; rg < 2; rg++)
        #pragma unroll
        for (int j = 0; j < 4; j++) { o[rg][j][0]=0.f; o[rg][j][1]=0.f; o[rg][j][2]=0.f; o[rg][j][3]=0.f; }
    float l[2][2] = {{0.f,0.f},{0.f,0.f}};

    for (int t = 0; t < 32; t++) {
        if (t < 31) {
            int row = (t+1)*128 + sr;
            const char* gk = (const char*)(QKV + (size_t)row*384 + 128 + h*32);
            const char* gv = (const char*)(QKV + (size_t)row*384 + 256 + h*32);
            cpa16(s2u(((t & 1) ? Ks0 : Ks1) + sr*40) + sg, gk + sg);
            cpa16(s2u(((t & 1) ? Vs0 : Vs1) + sr*40) + sg, gv + sg);
            cpa_commit();
        }
        const u32 aKb = (t & 1) ? aK1 : aK0;
        const u32 aVb = (t & 1) ? aV1 : aV0;

        float c[2][4][4];
        #pragma unroll
        for (int rg = 0; rg < 2; rg++)
            #pragma unroll
            for (int j = 0; j < 4; j++) { c[rg][j][0]=0.f; c[rg][j][1]=0.f; c[rg][j][2]=0.f; c[rg][j][3]=0.f; }

        #pragma unroll
        for (int g = 0; g < 2; g++) {
            uint4 k0 = ldsm4(aKb + g*1280);
            uint4 k1 = ldsm4(aKb + g*1280 + 32);
            #pragma unroll
            for (int rg = 0; rg < 2; rg++) {
                mma16816(c[rg][2*g],   qa[rg][0], k0.x, k0.z);
                mma16816(c[rg][2*g+1], qa[rg][0], k0.y, k0.w);
                mma16816(c[rg][2*g],   qa[rg][1], k1.x, k1.z);
                mma16816(c[rg][2*g+1], qa[rg][1], k1.y, k1.w);
            }
        }

        #pragma unroll
        for (int rg = 0; rg < 2; rg++) {
            #pragma unroll
            for (int j = 0; j < 4; j++) {
                c[rg][j][0] = ex2f(c[rg][j][0]);
                c[rg][j][1] = ex2f(c[rg][j][1]);
                c[rg][j][2] = ex2f(c[rg][j][2]);
                c[rg][j][3] = ex2f(c[rg][j][3]);
                l[rg][0] += c[rg][j][0] + c[rg][j][1];
                l[rg][1] += c[rg][j][2] + c[rg][j][3];
            }
        }

        #pragma unroll
        for (int kc = 0; kc < 2; kc++) {
            uint4 v0 = ldsm4t(aVb + kc*1280);
            uint4 v1 = ldsm4t(aVb + kc*1280 + 32);
            #pragma unroll
            for (int rg = 0; rg < 2; rg++) {
                uint4 pa;
                pa.x = cvtbf2(c[rg][2*kc][1],   c[rg][2*kc][0]);
                pa.y = cvtbf2(c[rg][2*kc][3],   c[rg][2*kc][2]);
                pa.z = cvtbf2(c[rg][2*kc+1][1], c[rg][2*kc+1][0]);
                pa.w = cvtbf2(c[rg][2*kc+1][3], c[rg][2*kc+1][2]);
                mma16816(o[rg][0], pa, v0.x, v0.y);
                mma16816(o[rg][1], pa, v0.z, v0.w);
                mma16816(o[rg][2], pa, v1.x, v1.y);
                mma16816(o[rg][3], pa, v1.z, v1.w);
            }
        }

        if (t < 31) cpa_wait0();
        __syncthreads();
    }

    if (hf > 0) {
        float* dst = cbuf + (size_t)(hf-1)*128*36 + (wq*32 + lane)*36;
        #pragma unroll
        for (int rg = 0; rg < 2; rg++)
            #pragma unroll
            for (int j = 0; j < 4; j++)
                *(float4*)&dst[rg*16 + j*4] = make_float4(o[rg][j][0], o[rg][j][1], o[rg][j][2], o[rg][j][3]);
        *(float4*)&dst[32] = make_float4(l[0][0], l[0][1], l[1][0], l[1][1]);
    }
    __syncthreads();
    if (hf > 0) return;

    #pragma unroll
    for (int b = 0; b < 3; b++) {
        const float* src = cbuf + (size_t)b*128*36 + (wq*32 + lane)*36;
        #pragma unroll
        for (int rg = 0; rg < 2; rg++)
            #pragma unroll
            for (int j = 0; j < 4; j++) {
                float4 s4 = *(const float4*)&src[rg*16 + j*4];
                o[rg][j][0] += s4.x; o[rg][j][1] += s4.y; o[rg][j][2] += s4.z; o[rg][j][3] += s4.w;
            }
        float4 ls = *(const float4*)&src[32];
        l[0][0] += ls.x; l[0][1] += ls.y; l[1][0] += ls.z; l[1][1] += ls.w;
    }

    #pragma unroll
    for (int rg = 0; rg < 2; rg++) {
        #pragma unroll
        for (int p = 0; p < 2; p++) {
            l[rg][p] += __shfl_xor_sync(0xffffffffu, l[rg][p], 1);
            l[rg][p] += __shfl_xor_sync(0xffffffffu, l[rg][p], 2);
        }
    }

    u32* OH = (u32*)g_attnh;
    u32* OL = (u32*)g_attnl;
    const int col = h*32 + (lane & 3)*2;
    #pragma unroll
    for (int rg = 0; rg < 2; rg++) {
        float li0 = 1.0f / l[rg][0], li1 = 1.0f / l[rg][1];
        int row0 = q0 + wq*32 + rg*16 + (lane >> 2);
        #pragma unroll
        for (int j = 0; j < 4; j++) {
            u32 hp, lp;
            split2(o[rg][j][0]*li0, o[rg][j][1]*li0, hp, lp);
            OH[((size_t)row0*128 + col + j*8) >> 1] = hp;
            OL[((size_t)row0*128 + col + j*8) >> 1] = lp;
            split2(o[rg][j][2]*li1, o[rg][j][3]*li1, hp, lp);
            OH[((size_t)(row0+8)*128 + col + j*8) >> 1] = hp;
            OL[((size_t)(row0+8)*128 + col + j*8) >> 1] = lp;
        }
    }
}

// ---------------- launch ----------------
extern "C" void kernel_launch(void* const* d_in, const int* in_sizes, int n_in,
                              void* d_out, int out_size) {
    const float* coords   = (const float*)d_in[0];
    const int*   labels   = (const int*)  d_in[1];
    const float* ce_w     = (const float*)d_in[2];
    const float* ce_b     = (const float*)d_in[3];
    const float* emb      = (const float*)d_in[4];
    const float* sa_in_w  = (const float*)d_in[5];
    const float* sa_in_b  = (const float*)d_in[6];
    const float* sa_out_w = (const float*)d_in[7];
    const float* sa_out_b = (const float*)d_in[8];
    const float* n1_g     = (const float*)d_in[9];
    const float* n1_b     = (const float*)d_in[10];
    const float* m1_w1    = (const float*)d_in[11];
    const float* m1_b1    = (const float*)d_in[12];
    const float* m1_w2    = (const float*)d_in[13];
    const float* m1_b2    = (const float*)d_in[14];
    const float* n2_g     = (const float*)d_in[15];
    const float* n2_b     = (const float*)d_in[16];
    const float* ca_in_w  = (const float*)d_in[17];
    const float* ca_in_b  = (const float*)d_in[18];
    const float* ca_out_w = (const float*)d_in[19];
    const float* ca_out_b = (const float*)d_in[20];
    const float* n3_g     = (const float*)d_in[21];
    const float* n3_b     = (const float*)d_in[22];
    const float* m2_w1    = (const float*)d_in[23];
    const float* m2_b1    = (const float*)d_in[24];
    const float* m2_w2    = (const float*)d_in[25];
    const float* m2_b2    = (const float*)d_in[26];
    const float* n4_g     = (const float*)d_in[27];
    const float* n4_b     = (const float*)d_in[28];
    const float* fin_w    = (const float*)d_in[29];
    const float* fin_b    = (const float*)d_in[30];
    float* out = (float*)d_out;

    float *px, *py, *pca;
    __nv_bfloat16 *pxh, *pxl, *pqkvh, *pah, *pal, *pwh, *pwl;
    cudaGetSymbolAddress((void**)&px,    g_x);
    cudaGetSymbolAddress((void**)&py,    g_y);
    cudaGetSymbolAddress((void**)&pxh,   g_xh);
    cudaGetSymbolAddress((void**)&pxl,   g_xl);
    cudaGetSymbolAddress((void**)&pqkvh, g_qkvh);
    cudaGetSymbolAddress((void**)&pah,   g_attnh);
    cudaGetSymbolAddress((void**)&pal,   g_attnl);
    cudaGetSymbolAddress((void**)&pwh,   g_wh);
    cudaGetSymbolAddress((void**)&pwl,   g_wl);
    cudaGetSymbolAddress((void**)&pca,   g_ca);

    const int ATTN_SMEM = 5*128*40*2 + 3*128*36*4;   // 106496 B
    cudaFuncSetAttribute(k_attn, cudaFuncAttributeMaxDynamicSharedMemorySize, ATTN_SMEM);
    const int MLP_SMEM = 207360;
    cudaFuncSetAttribute(k_mlpln<1,1>, cudaFuncAttributeMaxDynamicSharedMemorySize, MLP_SMEM);
    cudaFuncSetAttribute(k_mlpln<2,0>, cudaFuncAttributeMaxDynamicSharedMemorySize, MLP_SMEM);

    WSrc ws;
    ws.p[0] = sa_in_w;  ws.p[1] = sa_out_w; ws.p[2] = m1_w1;
    ws.p[3] = m1_w2;    ws.p[4] = m2_w1;    ws.p[5] = m2_w2;
    ws.end[0] = WO_SAOUT/2; ws.end[1] = WO_M1W1/2; ws.end[2] = WO_M1W2/2;
    ws.end[3] = WO_M2W1/2;  ws.end[4] = WO_M2W2/2; ws.end[5] = W_TOTAL/2;

    k_setup<<<2698, 256>>>(ws, pwh, pwl, coords, ce_w, ce_b,
                           emb, ca_in_w + 2*DD*DD, ca_in_b + 2*DD, ca_out_w, ca_out_b);
    k_gemm3<1,0><<<dim3(6, 64), 256>>>(pxh, pxl, pwh+WO_SAIN, pwl+WO_SAIN, sa_in_b, pqkvh, nullptr, 384, 128);
    k_attn<<<dim3(32, 4), 512, ATTN_SMEM>>>();
    // fused: sa_out+LN1 prestage, then MLP1 + LN2 + ca + LN3 -> py + pxh/pxl
    k_mlpln<1,1><<<128, 256, MLP_SMEM>>>(pah, pal, pwh+WO_M1W1, pwl+WO_M1W1, m1_b1,
                                         pwh+WO_M1W2, pwl+WO_M1W2, m1_b2, nullptr,
                                         n2_g, n2_b, n3_g, n3_b, pca, labels,
                                         py, pxh, pxl,
                                         pwh+WO_SAOUT, pwl+WO_SAOUT, sa_out_b, px, n1_g, n1_b);
    // fused MLP2 + LN4 + final sigmoid -> out
    k_mlpln<2,0><<<128, 256, MLP_SMEM>>>(pxh, pxl, pwh+WO_M2W1, pwl+WO_M2W1, m2_b1,
                                         pwh+WO_M2W2, pwl+WO_M2W2, m2_b2, py,
                                         n4_g, n4_b, fin_w, fin_b, nullptr, nullptr,
                                         out, nullptr, nullptr,
                                         nullptr, nullptr, nullptr, nullptr, nullptr, nullptr);
}

// round 14
// speedup vs baseline: 1.0573x; 1.0299x over previous
#include <cuda_runtime.h>
#include <cuda_bf16.h>
#include <math.h>

#define BB 4096
#define DD 128

typedef unsigned int u32;

// ---- tensor-core helpers ----
__device__ __forceinline__ uint4 ldsm4(u32 addr) {
    uint4 r;
    asm volatile("ldmatrix.sync.aligned.m8n8.x4.shared.b16 {%0,%1,%2,%3},[%4];"
        : "=r"(r.x), "=r"(r.y), "=r"(r.z), "=r"(r.w) : "r"(addr));
    return r;
}
__device__ __forceinline__ uint4 ldsm4t(u32 addr) {
    uint4 r;
    asm volatile("ldmatrix.sync.aligned.m8n8.x4.trans.shared.b16 {%0,%1,%2,%3},[%4];"
        : "=r"(r.x), "=r"(r.y), "=r"(r.z), "=r"(r.w) : "r"(addr));
    return r;
}
__device__ __forceinline__ void mma16816(float* c, uint4 a, u32 b0, u32 b1) {
    asm volatile(
        "mma.sync.aligned.m16n8k16.row.col.f32.bf16.bf16.f32 "
        "{%0,%1,%2,%3},{%4,%5,%6,%7},{%8,%9},{%0,%1,%2,%3};"
        : "+f"(c[0]), "+f"(c[1]), "+f"(c[2]), "+f"(c[3])
        : "r"(a.x), "r"(a.y), "r"(a.z), "r"(a.w), "r"(b0), "r"(b1));
}
__device__ __forceinline__ float ex2f(float x) {
    float y; asm("ex2.approx.f32 %0,%1;" : "=f"(y) : "f"(x)); return y;
}
__device__ __forceinline__ u32 cvtbf2(float hi, float lo) {
    u32 r; asm("cvt.rn.bf16x2.f32 %0,%1,%2;" : "=r"(r) : "f"(hi), "f"(lo)); return r;
}
__device__ __forceinline__ u32 s2u(const void* p) {
    return (u32)__cvta_generic_to_shared(p);
}
__device__ __forceinline__ void split2(float v0, float v1, u32& hp, u32& lp) {
    hp = cvtbf2(v1, v0);
    float h0 = __uint_as_float(hp << 16);
    float h1 = __uint_as_float(hp & 0xffff0000u);
    lp = cvtbf2(v1 - h1, v0 - h0);
}
__device__ __forceinline__ void cpa16(u32 dst, const void* src) {
    asm volatile("cp.async.cg.shared.global [%0],[%1],16;" :: "r"(dst), "l"(src));
}
__device__ __forceinline__ void cpa_commit() {
    asm volatile("cp.async.commit_group;");
}
__device__ __forceinline__ void cpa_wait0() {
    asm volatile("cp.async.wait_group 0;");
}
__device__ __forceinline__ void gbar(int id) {
    asm volatile("bar.sync %0, 256;" :: "r"(id) : "memory");
}

#define QSCALE 0.17677669529663688f
#define LOG2E  1.4426950408889634f

// ---------------- scratch ----------------
__device__ float g_x[BB*DD];
__device__ float g_y[BB*DD];
__device__ __nv_bfloat16 g_xh[BB*DD];
__device__ __nv_bfloat16 g_xl[BB*DD];
__device__ __nv_bfloat16 g_qkvh[BB*3*DD];
__device__ __nv_bfloat16 g_attnh[BB*DD];
__device__ __nv_bfloat16 g_attnl[BB*DD];
__device__ __nv_bfloat16 g_wh[327680];
__device__ __nv_bfloat16 g_wl[327680];
__device__ float g_ca[10*DD];

#define WO_SAIN  0
#define WO_SAOUT 49152
#define WO_M1W1  65536
#define WO_M1W2  131072
#define WO_M2W1  196608
#define WO_M2W2  262144
#define W_TOTAL  327680

// ---------------- setup: weight convert + embed + ca table ----------------
struct WSrc { const float* p[6]; int end[6]; };
__global__ __launch_bounds__(256) void k_setup(WSrc a, __nv_bfloat16* dh, __nv_bfloat16* dl,
    const float* __restrict__ coords, const float* __restrict__ ce_w, const float* __restrict__ ce_b,
    const float* __restrict__ emb, const float* __restrict__ wv, const float* __restrict__ bv,
    const float* __restrict__ wo, const float* __restrict__ bo)
{
    int b = blockIdx.x;
    int tid = threadIdx.x;
    if (b < 640) {
        int i = b*256 + tid;
        if (i >= a.end[5]) return;
        int k = 0;
        #pragma unroll
        for (int j = 1; j < 6; j++) if (i >= a.end[j-1]) k = j;
        int beg = (k > 0) ? a.end[k-1] : 0;
        float2 v = ((const float2*)a.p[k])[i - beg];
        u32 hp, lp; split2(v.x, v.y, hp, lp);
        ((u32*)dh)[i] = hp;
        ((u32*)dl)[i] = lp;
    } else if (b < 2688) {
        int i = (b - 640)*2 + (tid >> 7);
        int d = tid & 127;
        float c0 = coords[2*i], c1 = coords[2*i+1];
        int j = d >> 1;
        float dv = expf(9.210340371976184f * (float)j * (1.0f/64.0f));
        float pe = (d & 1) ? cosf(c1 / dv) : sinf(c0 / dv);
        float v = c0*ce_w[2*d] + c1*ce_w[2*d+1] + ce_b[d] + pe;
        g_x[i*DD + d] = v;
        __nv_bfloat16 h = __float2bfloat16_rn(v);
        g_xh[i*DD + d] = h;
        g_xl[i*DD + d] = __float2bfloat16_rn(v - __bfloat162float(h));
    } else {
        __shared__ float e[128], t[128];
        int c = b - 2688, j = tid;
        if (j < 128) e[j] = emb[c*128 + j];
        __syncthreads();
        if (j < 128) {
            float s = bv[j];
            #pragma unroll 8
            for (int d0 = 0; d0 < 128; d0++) s += e[d0]*wv[j*128 + d0];
            t[j] = s;
        }
        __syncthreads();
        if (j < 128) {
            float s2 = bo[j];
            #pragma unroll 8
            for (int d0 = 0; d0 < 128; d0++) s2 += t[d0]*wo[j*128 + d0];
            g_ca[c*128 + j] = s2;
        }
    }
}

// ---------------- 3xBF16 GEMM, 64x64 tile (qkv) ----------------
__global__ __launch_bounds__(256) void k_gemm3(
    const __nv_bfloat16* __restrict__ Ah, const __nv_bfloat16* __restrict__ Al,
    const __nv_bfloat16* __restrict__ Wh, const __nv_bfloat16* __restrict__ Wl,
    const float* __restrict__ bias,
    void* __restrict__ out1, int N, int K)
{
    __shared__ __nv_bfloat16 sA[2][2][64][40];
    __shared__ __nv_bfloat16 sW[2][2][64][40];

    const int tid = threadIdx.x;
    const int lane = tid & 31, w = tid >> 5;
    const int wr = w & 3, wc = w >> 2;
    const int m0 = blockIdx.y*64, n0 = blockIdx.x*64;
    const int r = tid >> 2, q = tid & 3;
    const int nc = K >> 5;

    const __nv_bfloat16* pAh = Ah + (size_t)(m0+r)*K + q*8;
    const __nv_bfloat16* pAl = Al + (size_t)(m0+r)*K + q*8;
    const __nv_bfloat16* pWh = Wh + (size_t)(n0+r)*K + q*8;
    const __nv_bfloat16* pWl = Wl + (size_t)(n0+r)*K + q*8;

    {
        uint4 va = *(const uint4*)pAh;
        uint4 vl = *(const uint4*)pAl;
        uint4 vw = *(const uint4*)pWh;
        uint4 vx = *(const uint4*)pWl;
        *(uint4*)&sA[0][0][r][q*8] = va;
        *(uint4*)&sA[0][1][r][q*8] = vl;
        *(uint4*)&sW[0][0][r][q*8] = vw;
        *(uint4*)&sW[0][1][r][q*8] = vx;
    }
    __syncthreads();

    float c[4][4];
    #pragma unroll
    for (int j = 0; j < 4; j++) { c[j][0]=0.f; c[j][1]=0.f; c[j][2]=0.f; c[j][3]=0.f; }

    const u32 frag_off = (u32)((lane & 15)*80 + (lane >> 4)*16);
    const u32 aA = s2u(&sA[0][0][0][0]) + (u32)(wr*16*80) + frag_off;
    const u32 aW = s2u(&sW[0][0][0][0]) + (u32)(wc*32*80) + frag_off;

    for (int t = 0; t < nc; t++) {
        uint4 va, vl, vw, vx;
        if (t + 1 < nc) {
            int o = (t+1)*32;
            va = *(const uint4*)(pAh+o);
            vl = *(const uint4*)(pAl+o);
            vw = *(const uint4*)(pWh+o);
            vx = *(const uint4*)(pWl+o);
        }
        u32 bofs = (u32)(t & 1) * 10240u;
        #pragma unroll
        for (int sub = 0; sub < 2; sub++) {
            u32 ko = bofs + sub*32;
            uint4 fAh = ldsm4(aA + ko);
            uint4 fAl = ldsm4(aA + ko + 5120);
            uint4 bh0 = ldsm4(aW + ko);
            uint4 bh1 = ldsm4(aW + ko + 1280);
            uint4 bl0 = ldsm4(aW + ko + 5120);
            uint4 bl1 = ldsm4(aW + ko + 5120 + 1280);
            mma16816(c[0], fAh, bh0.x, bh0.z);
            mma16816(c[1], fAh, bh0.y, bh0.w);
            mma16816(c[2], fAh, bh1.x, bh1.z);
            mma16816(c[3], fAh, bh1.y, bh1.w);
            mma16816(c[0], fAh, bl0.x, bl0.z);
            mma16816(c[1], fAh, bl0.y, bl0.w);
            mma16816(c[2], fAh, bl1.x, bl1.z);
            mma16816(c[3], fAh, bl1.y, bl1.w);
            mma16816(c[0], fAl, bh0.x, bh0.z);
            mma16816(c[1], fAl, bh0.y, bh0.w);
            mma16816(c[2], fAl, bh1.x, bh1.z);
            mma16816(c[3], fAl, bh1.y, bh1.w);
        }
        if (t + 1 < nc) {
            int nb = (t & 1) ^ 1;
            *(uint4*)&sA[nb][0][r][q*8] = va;
            *(uint4*)&sA[nb][1][r][q*8] = vl;
            *(uint4*)&sW[nb][0][r][q*8] = vw;
            *(uint4*)&sW[nb][1][r][q*8] = vx;
        }
        __syncthreads();
    }

    const int row = m0 + wr*16 + (lane >> 2);
    const int cbase = n0 + wc*32;
    const int cb = (lane & 3)*2;
    #pragma unroll
    for (int nt = 0; nt < 4; nt++) {
        int col = cbase + nt*8 + cb;
        float b0 = bias[col], b1 = bias[col+1];
        float v0 = c[nt][0]+b0, v1 = c[nt][1]+b1;
        float v2 = c[nt][2]+b0, v3 = c[nt][3]+b1;
        u32* O = (u32*)out1;
        float sc = (col < 128) ? (QSCALE*LOG2E) : 1.0f;
        O[((size_t)row*N + col) >> 1]     = cvtbf2(v1*sc, v0*sc);
        O[((size_t)(row+8)*N + col) >> 1] = cvtbf2(v3*sc, v2*sc);
    }
}

// ---------------- fused (sa_out+LN1)? + MLP (2 warp-groups) + LN(...) ----------------
// 512 threads, 32 rows/CTA. Group g = w>>3 processes hidden chunks nh = g, g+2, g+4, g+6.
// smem layout (bytes):
//   SW1(g) = g*81920            (40960)   W1 chunk, single-buffered per group
//   SW2(g) = 40960 + g*81920    (40960)   W2 chunk
//   SH(g)  = 163840 + g*10240   (10240)   gelu(h) hi/lo
//   SXF    = 163840             (20480)   x hi/lo frag staging (before SH use)
//   SC     = 184320             (16896)   fp32 tile
//   SX     = 201216             (16384)   LN1(x) fp32 (SAOUT only)
// Prestage (SAOUT): Wo at 0..81920, A at SXF.
template<int MODE, int SAOUT>
__global__ __launch_bounds__(512) void k_mlpln(
    const __nv_bfloat16* __restrict__ Ah, const __nv_bfloat16* __restrict__ Al,
    const __nv_bfloat16* __restrict__ W1h, const __nv_bfloat16* __restrict__ W1l,
    const float* __restrict__ b1,
    const __nv_bfloat16* __restrict__ W2h, const __nv_bfloat16* __restrict__ W2l,
    const float* __restrict__ b2,
    const float* __restrict__ R,
    const float* __restrict__ ng1, const float* __restrict__ nb1,
    const float* __restrict__ ng2, const float* __restrict__ nb2,
    const float* __restrict__ catab, const int* __restrict__ labels,
    float* __restrict__ outf, __nv_bfloat16* __restrict__ oh, __nv_bfloat16* __restrict__ ol,
    const __nv_bfloat16* __restrict__ Woh, const __nv_bfloat16* __restrict__ Wol,
    const float* __restrict__ sab, const float* __restrict__ Rpre,
    const float* __restrict__ ln1g, const float* __restrict__ ln1b)
{
    extern __shared__ char sm[];
    const u32 SXF = 163840, SC = 184320, SX = 201216;
    float* sC = (float*)(sm + SC);
    float* sX = (float*)(sm + SX);

    const int tid = threadIdx.x;
    const int lane = tid & 31, w = tid >> 5;
    const int g = w >> 3, lw = w & 7, ltid = tid & 255;
    const int wr = lw & 1, wc = lw >> 1;
    const int gb = 1 + g;
    const int m0 = blockIdx.x * 32;
    const u32 smb = s2u(sm);
    const u32 frag_off = (u32)((lane & 15)*80 + (lane >> 4)*16);
    const int r0 = wr*16 + (lane >> 2);
    const u32 GW1 = (u32)g*81920u;
    const u32 GW2 = 40960u + (u32)g*81920u;
    const u32 GH  = 163840u + (u32)g*10240u;

    if (SAOUT) {
        // stage A (32 rows hi/lo) -> SXF ; Wo (128x128 hi/lo) -> 0..81920
        #pragma unroll
        for (int i = 0; i < 2; i++) {
            int idx = tid + i*512;
            int kc = idx >> 8; int rem = idx & 255; int mat = rem >> 7; int rm = rem & 127;
            int row = rm >> 2; int seg = rm & 3;
            const __nv_bfloat16* src = (mat ? Al : Ah) + (size_t)(m0+row)*128 + kc*32 + seg*8;
            cpa16(smb + SXF + (u32)(kc*5120 + mat*2560 + row*80 + seg*16), src);
        }
        #pragma unroll
        for (int i = 0; i < 8; i++) {
            int idx = tid + i*512;
            int seg = idx & 3; int row = (idx >> 2) & 127; int mat = (idx >> 9) & 1; int kc = idx >> 10;
            const __nv_bfloat16* src = (mat ? Wol : Woh) + (size_t)row*128 + kc*32 + seg*8;
            cpa16(smb + (u32)(kc*20480 + mat*10240 + row*80 + seg*16), src);
        }
        cpa_commit();
        cpa_wait0();
        __syncthreads();

        // GEMM: attn @ Wo^T  (16 warps: wr2 row-half, wc2 16-col group)
        const int wr2 = w & 1, wc2 = w >> 1;
        float cp[2][4];
        cp[0][0]=0.f; cp[0][1]=0.f; cp[0][2]=0.f; cp[0][3]=0.f;
        cp[1][0]=0.f; cp[1][1]=0.f; cp[1][2]=0.f; cp[1][3]=0.f;
        {
            u32 aA = smb + SXF + (u32)(wr2*16*80) + frag_off;
            u32 aW = smb + (u32)(wc2*16*80) + frag_off;
            #pragma unroll
            for (int kc = 0; kc < 4; kc++) {
                #pragma unroll
                for (int sub = 0; sub < 2; sub++) {
                    u32 koA = (u32)(kc*5120 + sub*32);
                    u32 koB = (u32)(kc*20480 + sub*32);
                    uint4 fAh = ldsm4(aA + koA);
                    uint4 fAl = ldsm4(aA + koA + 2560);
                    uint4 bh = ldsm4(aW + koB);
                    uint4 bl = ldsm4(aW + koB + 10240);
                    mma16816(cp[0], fAh, bh.x, bh.z);
                    mma16816(cp[1], fAh, bh.y, bh.w);
                    mma16816(cp[0], fAh, bl.x, bl.z);
                    mma16816(cp[1], fAh, bl.y, bl.w);
                    mma16816(cp[0], fAl, bh.x, bh.z);
                    mma16816(cp[1], fAl, bh.y, bh.w);
                }
            }
        }
        {
            const int cb = (lane & 3)*2;
            const int rp = wr2*16 + (lane >> 2);
            #pragma unroll
            for (int nt = 0; nt < 2; nt++) {
                int col = wc2*16 + nt*8 + cb;
                float bb0 = sab[col], bb1 = sab[col+1];
                sC[rp*132 + col]       = cp[nt][0] + bb0;
                sC[rp*132 + col + 1]   = cp[nt][1] + bb1;
                sC[(rp+8)*132 + col]     = cp[nt][2] + bb0;
                sC[(rp+8)*132 + col + 1] = cp[nt][3] + bb1;
            }
        }
        __syncthreads();

        // LN1 over 32 rows (16 warps x 2 rows); fp32 -> sX, hi/lo frags -> SXF
        float4 g1v = *(const float4*)&ln1g[lane*4];
        float4 b1v = *(const float4*)&ln1b[lane*4];
        #pragma unroll
        for (int rr = 0; rr < 2; rr++) {
            int rl2 = w*2 + rr;
            int row = m0 + rl2;
            float4 v = *(float4*)&sC[rl2*132 + lane*4];
            float4 rv = *(const float4*)&Rpre[(size_t)row*128 + lane*4];
            v.x += rv.x; v.y += rv.y; v.z += rv.z; v.w += rv.w;
            float s  = v.x + v.y + v.z + v.w;
            float s2 = v.x*v.x + v.y*v.y + v.z*v.z + v.w*v.w;
            #pragma unroll
            for (int off = 16; off > 0; off >>= 1) {
                s  += __shfl_xor_sync(0xffffffffu, s,  off);
                s2 += __shfl_xor_sync(0xffffffffu, s2, off);
            }
            float mean = s * (1.0f/128.0f);
            float var  = s2 * (1.0f/128.0f) - mean*mean;
            float rstd = rsqrtf(var + 1e-5f);
            v.x = (v.x - mean)*rstd*g1v.x + b1v.x;
            v.y = (v.y - mean)*rstd*g1v.y + b1v.y;
            v.z = (v.z - mean)*rstd*g1v.z + b1v.z;
            v.w = (v.w - mean)*rstd*g1v.w + b1v.w;
            *(float4*)&sX[rl2*128 + lane*4] = v;
            int kc = lane >> 3;
            int cc = (lane*4) & 31;
            char* p0 = sm + SXF + kc*5120 + rl2*80 + cc*2;
            u32 hp, lp;
            split2(v.x, v.y, hp, lp);
            *(u32*)p0 = hp; *(u32*)(p0 + 2560) = lp;
            split2(v.z, v.w, hp, lp);
            *(u32*)(p0 + 4) = hp; *(u32*)(p0 + 2560 + 4) = lp;
        }
        __syncthreads();
    } else {
        #pragma unroll
        for (int i = 0; i < 2; i++) {
            int idx = tid + i*512;
            int kc = idx >> 8; int rem = idx & 255; int mat = rem >> 7; int rm = rem & 127;
            int row = rm >> 2; int seg = rm & 3;
            const __nv_bfloat16* src = (mat ? Al : Ah) + (size_t)(m0+row)*128 + kc*32 + seg*8;
            cpa16(smb + SXF + (u32)(kc*5120 + mat*2560 + row*80 + seg*16), src);
        }
        cpa_commit();
        cpa_wait0();
        __syncthreads();
    }

    // x fragments to registers (all 16 warps)
    uint4 fXh[4][2], fXl[4][2];
    {
        u32 aX = smb + SXF + (u32)(wr*16*80) + frag_off;
        #pragma unroll
        for (int kc = 0; kc < 4; kc++) {
            fXh[kc][0] = ldsm4(aX + kc*5120);
            fXh[kc][1] = ldsm4(aX + kc*5120 + 32);
            fXl[kc][0] = ldsm4(aX + kc*5120 + 2560);
            fXl[kc][1] = ldsm4(aX + kc*5120 + 2560 + 32);
        }
    }
    __syncthreads();   // SXF region becomes H buffers after this

    float c2[4][4];
    #pragma unroll
    for (int j = 0; j < 4; j++) { c2[j][0]=0.f; c2[j][1]=0.f; c2[j][2]=0.f; c2[j][3]=0.f; }

    // per-group chunk loop: nh = g, g+2, g+4, g+6; single-buffered, group barriers
    for (int ii = 0; ii < 4; ii++) {
        const int nh = g + ii*2;
        // stage W1/W2 chunk (256 threads of this group)
        #pragma unroll
        for (int i = 0; i < 8; i++) {
            int idx = ltid + i*256;
            int kc = idx >> 9; int rem = idx & 511; int mat = rem >> 8; int rm = rem & 255;
            int row = rm >> 2; int seg = rm & 3;
            const __nv_bfloat16* src = (mat ? W1l : W1h) + (size_t)(nh*64+row)*128 + kc*32 + seg*8;
            cpa16(smb + GW1 + (u32)(kc*10240 + mat*5120 + row*80 + seg*16), src);
        }
        #pragma unroll
        for (int i = 0; i < 8; i++) {
            int idx = ltid + i*256;
            int kc = idx >> 10; int rem = idx & 1023; int mat = rem >> 9; int rm = rem & 511;
            int row = rm >> 2; int seg = rm & 3;
            const __nv_bfloat16* src = (mat ? W2l : W2h) + (size_t)row*512 + nh*64 + kc*32 + seg*8;
            cpa16(smb + GW2 + (u32)(kc*20480 + mat*10240 + row*80 + seg*16), src);
        }
        cpa_commit();
        cpa_wait0();
        gbar(gb);

        // GEMM1: c1 = x @ W1chunk^T
        float c1[2][4];
        c1[0][0]=0.f; c1[0][1]=0.f; c1[0][2]=0.f; c1[0][3]=0.f;
        c1[1][0]=0.f; c1[1][1]=0.f; c1[1][2]=0.f; c1[1][3]=0.f;
        {
            u32 aW1 = smb + GW1 + (u32)(wc*16*80) + frag_off;
            #pragma unroll
            for (int kc = 0; kc < 4; kc++) {
                #pragma unroll
                for (int sub = 0; sub < 2; sub++) {
                    u32 ko = (u32)(kc*10240 + sub*32);
                    uint4 bh = ldsm4(aW1 + ko);
                    uint4 bl = ldsm4(aW1 + ko + 5120);
                    uint4 fh = fXh[kc][sub], fl = fXl[kc][sub];
                    mma16816(c1[0], fh, bh.x, bh.z);
                    mma16816(c1[1], fh, bh.y, bh.w);
                    mma16816(c1[0], fh, bl.x, bl.z);
                    mma16816(c1[1], fh, bl.y, bl.w);
                    mma16816(c1[0], fl, bh.x, bh.z);
                    mma16816(c1[1], fl, bh.y, bh.w);
                }
            }
        }
        // bias + gelu + hi/lo -> H[g]
        #pragma unroll
        for (int nt = 0; nt < 2; nt++) {
            int hc = wc*16 + nt*8 + (lane & 3)*2;
            float bb0 = b1[nh*64 + hc], bb1 = b1[nh*64 + hc + 1];
            float v0 = c1[nt][0]+bb0, v1 = c1[nt][1]+bb1;
            float v2 = c1[nt][2]+bb0, v3 = c1[nt][3]+bb1;
            v0 = 0.5f*v0*(1.0f + erff(v0*0.7071067811865475f));
            v1 = 0.5f*v1*(1.0f + erff(v1*0.7071067811865475f));
            v2 = 0.5f*v2*(1.0f + erff(v2*0.7071067811865475f));
            v3 = 0.5f*v3*(1.0f + erff(v3*0.7071067811865475f));
            int kc2 = hc >> 5, cc = hc & 31;
            char* p0 = sm + GH + kc2*5120 + r0*80 + cc*2;
            u32 hp, lp;
            split2(v0, v1, hp, lp);
            *(u32*)p0 = hp; *(u32*)(p0 + 2560) = lp;
            split2(v2, v3, hp, lp);
            *(u32*)(p0 + 640) = hp; *(u32*)(p0 + 640 + 2560) = lp;
        }
        gbar(gb);

        // GEMM2: c2 += h @ W2chunk^T
        {
            u32 aH  = smb + GH + (u32)(wr*16*80) + frag_off;
            u32 aW2 = smb + GW2 + (u32)(wc*32*80) + frag_off;
            #pragma unroll
            for (int kc = 0; kc < 2; kc++) {
                #pragma unroll
                for (int sub = 0; sub < 2; sub++) {
                    u32 koA = (u32)(kc*5120 + sub*32);
                    u32 koB = (u32)(kc*20480 + sub*32);
                    uint4 ah = ldsm4(aH + koA);
                    uint4 al = ldsm4(aH + koA + 2560);
                    uint4 bh0 = ldsm4(aW2 + koB);
                    uint4 bh1 = ldsm4(aW2 + koB + 1280);
                    uint4 bl0 = ldsm4(aW2 + koB + 10240);
                    uint4 bl1 = ldsm4(aW2 + koB + 10240 + 1280);
                    mma16816(c2[0], ah, bh0.x, bh0.z);
                    mma16816(c2[1], ah, bh0.y, bh0.w);
                    mma16816(c2[2], ah, bh1.x, bh1.z);
                    mma16816(c2[3], ah, bh1.y, bh1.w);
                    mma16816(c2[0], ah, bl0.x, bl0.z);
                    mma16816(c2[1], ah, bl0.y, bl0.w);
                    mma16816(c2[2], ah, bl1.x, bl1.z);
                    mma16816(c2[3], ah, bl1.y, bl1.w);
                    mma16816(c2[0], al, bh0.x, bh0.z);
                    mma16816(c2[1], al, bh0.y, bh0.w);
                    mma16816(c2[2], al, bh1.x, bh1.z);
                    mma16816(c2[3], al, bh1.y, bh1.w);
                }
            }
        }
        gbar(gb);   // protect W/H overwrite in next iteration
    }

    // combine group partials: group 1 publishes, group 0 accumulates
    __syncthreads();
    float* P = (float*)sm;               // reuse bytes 0..16384
    if (g == 1) {
        float* dst = P + ltid*16;
        #pragma unroll
        for (int j = 0; j < 4; j++) {
            dst[j*4+0] = c2[j][0]; dst[j*4+1] = c2[j][1];
            dst[j*4+2] = c2[j][2]; dst[j*4+3] = c2[j][3];
        }
    }
    __syncthreads();
    if (g == 1) return;
    {
        const float* src = P + ltid*16;
        #pragma unroll
        for (int j = 0; j < 4; j++) {
            c2[j][0] += src[j*4+0]; c2[j][1] += src[j*4+1];
            c2[j][2] += src[j*4+2]; c2[j][3] += src[j*4+3];
        }
    }

    // epilogue (group 0, 8 warps): bias2 -> sC
    {
        const int cb = (lane & 3)*2;
        #pragma unroll
        for (int nt = 0; nt < 4; nt++) {
            int col = wc*32 + nt*8 + cb;
            float bb0 = b2[col], bb1 = b2[col+1];
            sC[r0*132 + col]       = c2[nt][0] + bb0;
            sC[r0*132 + col + 1]   = c2[nt][1] + bb1;
            sC[(r0+8)*132 + col]     = c2[nt][2] + bb0;
            sC[(r0+8)*132 + col + 1] = c2[nt][3] + bb1;
        }
    }
    gbar(1);

    float4 g1v = *(const float4*)&ng1[lane*4];
    float4 b1v = *(const float4*)&nb1[lane*4];
    float4 g2v = make_float4(0,0,0,0), b2v = make_float4(0,0,0,0), fwv = make_float4(0,0,0,0);
    float fb = 0.f;
    if (MODE == 1) { g2v = *(const float4*)&ng2[lane*4]; b2v = *(const float4*)&nb2[lane*4]; }
    if (MODE == 2) { fwv = *(const float4*)&ng2[lane*4]; fb = nb2[0]; }

    #pragma unroll
    for (int rr = 0; rr < 4; rr++) {
        int rl2 = lw*4 + rr;
        int row = m0 + rl2;
        float4 v = *(float4*)&sC[rl2*132 + lane*4];
        float4 rv;
        if (SAOUT) rv = *(float4*)&sX[rl2*128 + lane*4];
        else       rv = *(const float4*)&R[(size_t)row*128 + lane*4];
        v.x += rv.x; v.y += rv.y; v.z += rv.z; v.w += rv.w;

        float s  = v.x + v.y + v.z + v.w;
        float s2 = v.x*v.x + v.y*v.y + v.z*v.z + v.w*v.w;
        #pragma unroll
        for (int off = 16; off > 0; off >>= 1) {
            s  += __shfl_xor_sync(0xffffffffu, s,  off);
            s2 += __shfl_xor_sync(0xffffffffu, s2, off);
        }
        float mean = s * (1.0f/128.0f);
        float var  = s2 * (1.0f/128.0f) - mean*mean;
        float rstd = rsqrtf(var + 1e-5f);
        v.x = (v.x - mean)*rstd*g1v.x + b1v.x;
        v.y = (v.y - mean)*rstd*g1v.y + b1v.y;
        v.z = (v.z - mean)*rstd*g1v.z + b1v.z;
        v.w = (v.w - mean)*rstd*g1v.w + b1v.w;

        if (MODE == 1) {
            int lab = labels[row];
            float4 cv = *(const float4*)&catab[(size_t)lab*128 + lane*4];
            v.x += cv.x; v.y += cv.y; v.z += cv.z; v.w += cv.w;
            float t1 = v.x + v.y + v.z + v.w;
            float t2 = v.x*v.x + v.y*v.y + v.z*v.z + v.w*v.w;
            #pragma unroll
            for (int off = 16; off > 0; off >>= 1) {
                t1 += __shfl_xor_sync(0xffffffffu, t1, off);
                t2 += __shfl_xor_sync(0xffffffffu, t2, off);
            }
            float mean2 = t1 * (1.0f/128.0f);
            float var2  = t2 * (1.0f/128.0f) - mean2*mean2;
            float rstd2 = rsqrtf(var2 + 1e-5f);
            v.x = (v.x - mean2)*rstd2*g2v.x + b2v.x;
            v.y = (v.y - mean2)*rstd2*g2v.y + b2v.y;
            v.z = (v.z - mean2)*rstd2*g2v.z + b2v.z;
            v.w = (v.w - mean2)*rstd2*g2v.w + b2v.w;
        }

        if (MODE == 2) {
            float d = v.x*fwv.x + v.y*fwv.y + v.z*fwv.z + v.w*fwv.w;
            #pragma unroll
            for (int off = 16; off > 0; off >>= 1) d += __shfl_xor_sync(0xffffffffu, d, off);
            if (lane == 0) outf[row] = 1.0f/(1.0f + expf(-(d + fb)));
        } else {
            *(float4*)&outf[(size_t)row*128 + lane*4] = v;
            u32 hp, lp;
            size_t idx = ((size_t)row*128 + lane*4) >> 1;
            split2(v.x, v.y, hp, lp);
            ((u32*)oh)[idx]   = hp; ((u32*)ol)[idx]   = lp;
            split2(v.z, v.w, hp, lp);
            ((u32*)oh)[idx+1] = hp; ((u32*)ol)[idx+1] = lp;
        }
    }
}

// ---------------- flash attention (round-11 measured version) ----------------
__global__ __launch_bounds__(512, 1) void k_attn() {
    extern __shared__ __nv_bfloat16 smh[];
    __nv_bfloat16* Qs  = smh;
    __nv_bfloat16* Ks0 = smh + 5120;
    __nv_bfloat16* Ks1 = smh + 10240;
    __nv_bfloat16* Vs0 = smh + 15360;
    __nv_bfloat16* Vs1 = smh + 20480;
    float* cbuf = (float*)(smh + 25600);

    const int h  = blockIdx.y;
    const int q0 = blockIdx.x * 128;
    const int tid  = threadIdx.x;
    const int lane = tid & 31;
    const int w    = tid >> 5;
    const int wq   = w & 3;
    const int hf   = w >> 2;

    const __nv_bfloat16* QKV = g_qkvh;

    const int sr = tid >> 2, sg = (tid & 3)*16;
    {
        const char* gq = (const char*)(QKV + (size_t)(q0 + sr)*384 + h*32);
        cpa16(s2u(Qs + sr*40) + sg, gq + sg);
        const char* gk = (const char*)(QKV + (size_t)sr*384 + 128 + h*32);
        cpa16(s2u(Ks0 + sr*40) + sg, gk + sg);
        const char* gv = (const char*)(QKV + (size_t)sr*384 + 256 + h*32);
        cpa16(s2u(Vs0 + sr*40) + sg, gv + sg);
    }
    cpa_commit();
    cpa_wait0();
    __syncthreads();

    const u32 frag_off = (u32)((lane & 15)*80 + (lane >> 4)*16);
    const u32 aQ  = s2u(Qs)  + (u32)(wq*32*80) + frag_off;
    const u32 qofs = (u32)hf * 2560u;
    const u32 aK0 = s2u(Ks0) + qofs + frag_off;
    const u32 aK1 = s2u(Ks1) + qofs + frag_off;
    const u32 aV0 = s2u(Vs0) + qofs + frag_off;
    const u32 aV1 = s2u(Vs1) + qofs + frag_off;

    uint4 qa[2][2];
    qa[0][0] = ldsm4(aQ);
    qa[0][1] = ldsm4(aQ + 32);
    qa[1][0] = ldsm4(aQ + 1280);
    qa[1][1] = ldsm4(aQ + 1280 + 32);

    float o[2][4][4];
    #pragma unroll
    for (int rg = 0; rg < 2; rg++)
        #pragma unroll
        for (int j = 0; j < 4; j++) { o[rg][j][0]=0.f; o[rg][j][1]=0.f; o[rg][j][2]=0.f; o[rg][j][3]=0.f; }
    float l[2][2] = {{0.f,0.f},{0.f,0.f}};

    for (int t = 0; t < 32; t++) {
        if (t < 31) {
            int row = (t+1)*128 + sr;
            const char* gk = (const char*)(QKV + (size_t)row*384 + 128 + h*32);
            const char* gv = (const char*)(QKV + (size_t)row*384 + 256 + h*32);
            cpa16(s2u(((t & 1) ? Ks0 : Ks1) + sr*40) + sg, gk + sg);
            cpa16(s2u(((t & 1) ? Vs0 : Vs1) + sr*40) + sg, gv + sg);
            cpa_commit();
        }
        const u32 aKb = (t & 1) ? aK1 : aK0;
        const u32 aVb = (t & 1) ? aV1 : aV0;

        float c[2][4][4];
        #pragma unroll
        for (int rg = 0; rg < 2; rg++)
            #pragma unroll
            for (int j = 0; j < 4; j++) { c[rg][j][0]=0.f; c[rg][j][1]=0.f; c[rg][j][2]=0.f; c[rg][j][3]=0.f; }

        #pragma unroll
        for (int g = 0; g < 2; g++) {
            uint4 k0 = ldsm4(aKb + g*1280);
            uint4 k1 = ldsm4(aKb + g*1280 + 32);
            #pragma unroll
            for (int rg = 0; rg < 2; rg++) {
                mma16816(c[rg][2*g],   qa[rg][0], k0.x, k0.z);
                mma16816(c[rg][2*g+1], qa[rg][0], k0.y, k0.w);
                mma16816(c[rg][2*g],   qa[rg][1], k1.x, k1.z);
                mma16816(c[rg][2*g+1], qa[rg][1], k1.y, k1.w);
            }
        }

        #pragma unroll
        for (int rg = 0; rg < 2; rg++) {
            #pragma unroll
            for (int j = 0; j < 4; j++) {
                c[rg][j][0] = ex2f(c[rg][j][0]);
                c[rg][j][1] = ex2f(c[rg][j][1]);
                c[rg][j][2] = ex2f(c[rg][j][2]);
                c[rg][j][3] = ex2f(c[rg][j][3]);
                l[rg][0] += c[rg][j][0] + c[rg][j][1];
                l[rg][1] += c[rg][j][2] + c[rg][j][3];
            }
        }

        #pragma unroll
        for (int kc = 0; kc < 2; kc++) {
            uint4 v0 = ldsm4t(aVb + kc*1280);
            uint4 v1 = ldsm4t(aVb + kc*1280 + 32);
            #pragma unroll
            for (int rg = 0; rg < 2; rg++) {
                uint4 pa;
                pa.x = cvtbf2(c[rg][2*kc][1],   c[rg][2*kc][0]);
                pa.y = cvtbf2(c[rg][2*kc][3],   c[rg][2*kc][2]);
                pa.z = cvtbf2(c[rg][2*kc+1][1], c[rg][2*kc+1][0]);
                pa.w = cvtbf2(c[rg][2*kc+1][3], c[rg][2*kc+1][2]);
                mma16816(o[rg][0], pa, v0.x, v0.y);
                mma16816(o[rg][1], pa, v0.z, v0.w);
                mma16816(o[rg][2], pa, v1.x, v1.y);
                mma16816(o[rg][3], pa, v1.z, v1.w);
            }
        }

        if (t < 31) cpa_wait0();
        __syncthreads();
    }

    if (hf > 0) {
        float* dst = cbuf + (size_t)(hf-1)*128*36 + (wq*32 + lane)*36;
        #pragma unroll
        for (int rg = 0; rg < 2; rg++)
            #pragma unroll
            for (int j = 0; j < 4; j++)
                *(float4*)&dst[rg*16 + j*4] = make_float4(o[rg][j][0], o[rg][j][1], o[rg][j][2], o[rg][j][3]);
        *(float4*)&dst[32] = make_float4(l[0][0], l[0][1], l[1][0], l[1][1]);
    }
    __syncthreads();
    if (hf > 0) return;

    #pragma unroll
    for (int b = 0; b < 3; b++) {
        const float* src = cbuf + (size_t)b*128*36 + (wq*32 + lane)*36;
        #pragma unroll
        for (int rg = 0; rg < 2; rg++)
            #pragma unroll
            for (int j = 0; j < 4; j++) {
                float4 s4 = *(const float4*)&src[rg*16 + j*4];
                o[rg][j][0] += s4.x; o[rg][j][1] += s4.y; o[rg][j][2] += s4.z; o[rg][j][3] += s4.w;
            }
        float4 ls = *(const float4*)&src[32];
        l[0][0] += ls.x; l[0][1] += ls.y; l[1][0] += ls.z; l[1][1] += ls.w;
    }

    #pragma unroll
    for (int rg = 0; rg < 2; rg++) {
        #pragma unroll
        for (int p = 0; p < 2; p++) {
            l[rg][p] += __shfl_xor_sync(0xffffffffu, l[rg][p], 1);
            l[rg][p] += __shfl_xor_sync(0xffffffffu, l[rg][p], 2);
        }
    }

    u32* OH = (u32*)g_attnh;
    u32* OL = (u32*)g_attnl;
    const int col = h*32 + (lane & 3)*2;
    #pragma unroll
    for (int rg = 0; rg < 2; rg++) {
        float li0 = 1.0f / l[rg][0], li1 = 1.0f / l[rg][1];
        int row0 = q0 + wq*32 + rg*16 + (lane >> 2);
        #pragma unroll
        for (int j = 0; j < 4; j++) {
            u32 hp, lp;
            split2(o[rg][j][0]*li0, o[rg][j][1]*li0, hp, lp);
            OH[((size_t)row0*128 + col + j*8) >> 1] = hp;
            OL[((size_t)row0*128 + col + j*8) >> 1] = lp;
            split2(o[rg][j][2]*li1, o[rg][j][3]*li1, hp, lp);
            OH[((size_t)(row0+8)*128 + col + j*8) >> 1] = hp;
            OL[((size_t)(row0+8)*128 + col + j*8) >> 1] = lp;
        }
    }
}

// ---------------- launch ----------------
extern "C" void kernel_launch(void* const* d_in, const int* in_sizes, int n_in,
                              void* d_out, int out_size) {
    const float* coords   = (const float*)d_in[0];
    const int*   labels   = (const int*)  d_in[1];
    const float* ce_w     = (const float*)d_in[2];
    const float* ce_b     = (const float*)d_in[3];
    const float* emb      = (const float*)d_in[4];
    const float* sa_in_w  = (const float*)d_in[5];
    const float* sa_in_b  = (const float*)d_in[6];
    const float* sa_out_w = (const float*)d_in[7];
    const float* sa_out_b = (const float*)d_in[8];
    const float* n1_g     = (const float*)d_in[9];
    const float* n1_b     = (const float*)d_in[10];
    const float* m1_w1    = (const float*)d_in[11];
    const float* m1_b1    = (const float*)d_in[12];
    const float* m1_w2    = (const float*)d_in[13];
    const float* m1_b2    = (const float*)d_in[14];
    const float* n2_g     = (const float*)d_in[15];
    const float* n2_b     = (const float*)d_in[16];
    const float* ca_in_w  = (const float*)d_in[17];
    const float* ca_in_b  = (const float*)d_in[18];
    const float* ca_out_w = (const float*)d_in[19];
    const float* ca_out_b = (const float*)d_in[20];
    const float* n3_g     = (const float*)d_in[21];
    const float* n3_b     = (const float*)d_in[22];
    const float* m2_w1    = (const float*)d_in[23];
    const float* m2_b1    = (const float*)d_in[24];
    const float* m2_w2    = (const float*)d_in[25];
    const float* m2_b2    = (const float*)d_in[26];
    const float* n4_g     = (const float*)d_in[27];
    const float* n4_b     = (const float*)d_in[28];
    const float* fin_w    = (const float*)d_in[29];
    const float* fin_b    = (const float*)d_in[30];
    float* out = (float*)d_out;

    float *px, *py, *pca;
    __nv_bfloat16 *pxh, *pxl, *pqkvh, *pah, *pal, *pwh, *pwl;
    cudaGetSymbolAddress((void**)&px,    g_x);
    cudaGetSymbolAddress((void**)&py,    g_y);
    cudaGetSymbolAddress((void**)&pxh,   g_xh);
    cudaGetSymbolAddress((void**)&pxl,   g_xl);
    cudaGetSymbolAddress((void**)&pqkvh, g_qkvh);
    cudaGetSymbolAddress((void**)&pah,   g_attnh);
    cudaGetSymbolAddress((void**)&pal,   g_attnl);
    cudaGetSymbolAddress((void**)&pwh,   g_wh);
    cudaGetSymbolAddress((void**)&pwl,   g_wl);
    cudaGetSymbolAddress((void**)&pca,   g_ca);

    const int ATTN_SMEM = 5*128*40*2 + 3*128*36*4;   // 106496 B
    cudaFuncSetAttribute(k_attn, cudaFuncAttributeMaxDynamicSharedMemorySize, ATTN_SMEM);
    const int MLP_SMEM = 217600;
    cudaFuncSetAttribute(k_mlpln<1,1>, cudaFuncAttributeMaxDynamicSharedMemorySize, MLP_SMEM);
    cudaFuncSetAttribute(k_mlpln<2,0>, cudaFuncAttributeMaxDynamicSharedMemorySize, MLP_SMEM);

    WSrc ws;
    ws.p[0] = sa_in_w;  ws.p[1] = sa_out_w; ws.p[2] = m1_w1;
    ws.p[3] = m1_w2;    ws.p[4] = m2_w1;    ws.p[5] = m2_w2;
    ws.end[0] = WO_SAOUT/2; ws.end[1] = WO_M1W1/2; ws.end[2] = WO_M1W2/2;
    ws.end[3] = WO_M2W1/2;  ws.end[4] = WO_M2W2/2; ws.end[5] = W_TOTAL/2;

    k_setup<<<2698, 256>>>(ws, pwh, pwl, coords, ce_w, ce_b,
                           emb, ca_in_w + 2*DD*DD, ca_in_b + 2*DD, ca_out_w, ca_out_b);
    k_gemm3<<<dim3(6, 64), 256>>>(pxh, pxl, pwh+WO_SAIN, pwl+WO_SAIN, sa_in_b, pqkvh, 384, 128);
    k_attn<<<dim3(32, 4), 512, ATTN_SMEM>>>();
    // fused: sa_out+LN1 prestage, then MLP1 + LN2 + ca + LN3 -> py + pxh/pxl
    k_mlpln<1,1><<<128, 512, MLP_SMEM>>>(pah, pal, pwh+WO_M1W1, pwl+WO_M1W1, m1_b1,
                                         pwh+WO_M1W2, pwl+WO_M1W2, m1_b2, nullptr,
                                         n2_g, n2_b, n3_g, n3_b, pca, labels,
                                         py, pxh, pxl,
                                         pwh+WO_SAOUT, pwl+WO_SAOUT, sa_out_b, px, n1_g, n1_b);
    // fused MLP2 + LN4 + final sigmoid -> out
    k_mlpln<2,0><<<128, 512, MLP_SMEM>>>(pxh, pxl, pwh+WO_M2W1, pwl+WO_M2W1, m2_b1,
                                         pwh+WO_M2W2, pwl+WO_M2W2, m2_b2, py,
                                         n4_g, n4_b, fin_w, fin_b, nullptr, nullptr,
                                         out, nullptr, nullptr,
                                         nullptr, nullptr, nullptr, nullptr, nullptr, nullptr);
}

// round 15
// speedup vs baseline: 1.0807x; 1.0220x over previous
#include <cuda_runtime.h>
#include <cuda_bf16.h>
#include <math.h>

#define BB 4096
#define DD 128

typedef unsigned int u32;

// ---- tensor-core helpers ----
__device__ __forceinline__ uint4 ldsm4(u32 addr) {
    uint4 r;
    asm volatile("ldmatrix.sync.aligned.m8n8.x4.shared.b16 {%0,%1,%2,%3},[%4];"
        : "=r"(r.x), "=r"(r.y), "=r"(r.z), "=r"(r.w) : "r"(addr));
    return r;
}
__device__ __forceinline__ uint4 ldsm4t(u32 addr) {
    uint4 r;
    asm volatile("ldmatrix.sync.aligned.m8n8.x4.trans.shared.b16 {%0,%1,%2,%3},[%4];"
        : "=r"(r.x), "=r"(r.y), "=r"(r.z), "=r"(r.w) : "r"(addr));
    return r;
}
__device__ __forceinline__ void mma16816(float* c, uint4 a, u32 b0, u32 b1) {
    asm volatile(
        "mma.sync.aligned.m16n8k16.row.col.f32.bf16.bf16.f32 "
        "{%0,%1,%2,%3},{%4,%5,%6,%7},{%8,%9},{%0,%1,%2,%3};"
        : "+f"(c[0]), "+f"(c[1]), "+f"(c[2]), "+f"(c[3])
        : "r"(a.x), "r"(a.y), "r"(a.z), "r"(a.w), "r"(b0), "r"(b1));
}
__device__ __forceinline__ float ex2f(float x) {
    float y; asm("ex2.approx.f32 %0,%1;" : "=f"(y) : "f"(x)); return y;
}
__device__ __forceinline__ u32 cvtbf2(float hi, float lo) {
    u32 r; asm("cvt.rn.bf16x2.f32 %0,%1,%2;" : "=r"(r) : "f"(hi), "f"(lo)); return r;
}
__device__ __forceinline__ u32 s2u(const void* p) {
    return (u32)__cvta_generic_to_shared(p);
}
__device__ __forceinline__ void split2(float v0, float v1, u32& hp, u32& lp) {
    hp = cvtbf2(v1, v0);
    float h0 = __uint_as_float(hp << 16);
    float h1 = __uint_as_float(hp & 0xffff0000u);
    lp = cvtbf2(v1 - h1, v0 - h0);
}
__device__ __forceinline__ void cpa16(u32 dst, const void* src) {
    asm volatile("cp.async.cg.shared.global [%0],[%1],16;" :: "r"(dst), "l"(src));
}
__device__ __forceinline__ void cpa_commit() {
    asm volatile("cp.async.commit_group;");
}
__device__ __forceinline__ void cpa_wait0() {
    asm volatile("cp.async.wait_group 0;");
}
__device__ __forceinline__ void cpa_wait1() {
    asm volatile("cp.async.wait_group 1;");
}
__device__ __forceinline__ void gbar(int id) {
    asm volatile("bar.sync %0, 256;" :: "r"(id) : "memory");
}

#define QSCALE 0.17677669529663688f
#define LOG2E  1.4426950408889634f

// ---------------- scratch ----------------
__device__ float g_x[BB*DD];
__device__ float g_y[BB*DD];
__device__ __nv_bfloat16 g_xh[BB*DD];
__device__ __nv_bfloat16 g_xl[BB*DD];
__device__ __nv_bfloat16 g_qkvh[BB*3*DD];
__device__ __nv_bfloat16 g_attnh[BB*DD];
__device__ __nv_bfloat16 g_attnl[BB*DD];
__device__ __nv_bfloat16 g_wh[327680];
__device__ __nv_bfloat16 g_wl[327680];
__device__ float g_ca[10*DD];

#define WO_SAIN  0
#define WO_SAOUT 49152
#define WO_M1W1  65536
#define WO_M1W2  131072
#define WO_M2W1  196608
#define WO_M2W2  262144
#define W_TOTAL  327680

// ---------------- setup: weight convert + embed + ca table ----------------
struct WSrc { const float* p[6]; int end[6]; };
__global__ __launch_bounds__(256) void k_setup(WSrc a, __nv_bfloat16* dh, __nv_bfloat16* dl,
    const float* __restrict__ coords, const float* __restrict__ ce_w, const float* __restrict__ ce_b,
    const float* __restrict__ emb, const float* __restrict__ wv, const float* __restrict__ bv,
    const float* __restrict__ wo, const float* __restrict__ bo)
{
    int b = blockIdx.x;
    int tid = threadIdx.x;
    if (b < 640) {
        int i = b*256 + tid;
        if (i >= a.end[5]) return;
        int k = 0;
        #pragma unroll
        for (int j = 1; j < 6; j++) if (i >= a.end[j-1]) k = j;
        int beg = (k > 0) ? a.end[k-1] : 0;
        float2 v = ((const float2*)a.p[k])[i - beg];
        u32 hp, lp; split2(v.x, v.y, hp, lp);
        ((u32*)dh)[i] = hp;
        ((u32*)dl)[i] = lp;
    } else if (b < 2688) {
        int i = (b - 640)*2 + (tid >> 7);
        int d = tid & 127;
        float c0 = coords[2*i], c1 = coords[2*i+1];
        int j = d >> 1;
        float dv = expf(9.210340371976184f * (float)j * (1.0f/64.0f));
        float pe = (d & 1) ? cosf(c1 / dv) : sinf(c0 / dv);
        float v = c0*ce_w[2*d] + c1*ce_w[2*d+1] + ce_b[d] + pe;
        g_x[i*DD + d] = v;
        __nv_bfloat16 h = __float2bfloat16_rn(v);
        g_xh[i*DD + d] = h;
        g_xl[i*DD + d] = __float2bfloat16_rn(v - __bfloat162float(h));
    } else {
        __shared__ float e[128], t[128];
        int c = b - 2688, j = tid;
        if (j < 128) e[j] = emb[c*128 + j];
        __syncthreads();
        if (j < 128) {
            float s = bv[j];
            #pragma unroll 8
            for (int d0 = 0; d0 < 128; d0++) s += e[d0]*wv[j*128 + d0];
            t[j] = s;
        }
        __syncthreads();
        if (j < 128) {
            float s2 = bo[j];
            #pragma unroll 8
            for (int d0 = 0; d0 < 128; d0++) s2 += t[d0]*wo[j*128 + d0];
            g_ca[c*128 + j] = s2;
        }
    }
}

// ---------------- 3xBF16 GEMM, 64x64 tile (qkv) ----------------
__global__ __launch_bounds__(256) void k_gemm3(
    const __nv_bfloat16* __restrict__ Ah, const __nv_bfloat16* __restrict__ Al,
    const __nv_bfloat16* __restrict__ Wh, const __nv_bfloat16* __restrict__ Wl,
    const float* __restrict__ bias,
    void* __restrict__ out1, int N, int K)
{
    __shared__ __nv_bfloat16 sA[2][2][64][40];
    __shared__ __nv_bfloat16 sW[2][2][64][40];

    const int tid = threadIdx.x;
    const int lane = tid & 31, w = tid >> 5;
    const int wr = w & 3, wc = w >> 2;
    const int m0 = blockIdx.y*64, n0 = blockIdx.x*64;
    const int r = tid >> 2, q = tid & 3;
    const int nc = K >> 5;

    const __nv_bfloat16* pAh = Ah + (size_t)(m0+r)*K + q*8;
    const __nv_bfloat16* pAl = Al + (size_t)(m0+r)*K + q*8;
    const __nv_bfloat16* pWh = Wh + (size_t)(n0+r)*K + q*8;
    const __nv_bfloat16* pWl = Wl + (size_t)(n0+r)*K + q*8;

    {
        uint4 va = *(const uint4*)pAh;
        uint4 vl = *(const uint4*)pAl;
        uint4 vw = *(const uint4*)pWh;
        uint4 vx = *(const uint4*)pWl;
        *(uint4*)&sA[0][0][r][q*8] = va;
        *(uint4*)&sA[0][1][r][q*8] = vl;
        *(uint4*)&sW[0][0][r][q*8] = vw;
        *(uint4*)&sW[0][1][r][q*8] = vx;
    }
    __syncthreads();

    float c[4][4];
    #pragma unroll
    for (int j = 0; j < 4; j++) { c[j][0]=0.f; c[j][1]=0.f; c[j][2]=0.f; c[j][3]=0.f; }

    const u32 frag_off = (u32)((lane & 15)*80 + (lane >> 4)*16);
    const u32 aA = s2u(&sA[0][0][0][0]) + (u32)(wr*16*80) + frag_off;
    const u32 aW = s2u(&sW[0][0][0][0]) + (u32)(wc*32*80) + frag_off;

    for (int t = 0; t < nc; t++) {
        uint4 va, vl, vw, vx;
        if (t + 1 < nc) {
            int o = (t+1)*32;
            va = *(const uint4*)(pAh+o);
            vl = *(const uint4*)(pAl+o);
            vw = *(const uint4*)(pWh+o);
            vx = *(const uint4*)(pWl+o);
        }
        u32 bofs = (u32)(t & 1) * 10240u;
        #pragma unroll
        for (int sub = 0; sub < 2; sub++) {
            u32 ko = bofs + sub*32;
            uint4 fAh = ldsm4(aA + ko);
            uint4 fAl = ldsm4(aA + ko + 5120);
            uint4 bh0 = ldsm4(aW + ko);
            uint4 bh1 = ldsm4(aW + ko + 1280);
            uint4 bl0 = ldsm4(aW + ko + 5120);
            uint4 bl1 = ldsm4(aW + ko + 5120 + 1280);
            mma16816(c[0], fAh, bh0.x, bh0.z);
            mma16816(c[1], fAh, bh0.y, bh0.w);
            mma16816(c[2], fAh, bh1.x, bh1.z);
            mma16816(c[3], fAh, bh1.y, bh1.w);
            mma16816(c[0], fAh, bl0.x, bl0.z);
            mma16816(c[1], fAh, bl0.y, bl0.w);
            mma16816(c[2], fAh, bl1.x, bl1.z);
            mma16816(c[3], fAh, bl1.y, bl1.w);
            mma16816(c[0], fAl, bh0.x, bh0.z);
            mma16816(c[1], fAl, bh0.y, bh0.w);
            mma16816(c[2], fAl, bh1.x, bh1.z);
            mma16816(c[3], fAl, bh1.y, bh1.w);
        }
        if (t + 1 < nc) {
            int nb = (t & 1) ^ 1;
            *(uint4*)&sA[nb][0][r][q*8] = va;
            *(uint4*)&sA[nb][1][r][q*8] = vl;
            *(uint4*)&sW[nb][0][r][q*8] = vw;
            *(uint4*)&sW[nb][1][r][q*8] = vx;
        }
        __syncthreads();
    }

    const int row = m0 + wr*16 + (lane >> 2);
    const int cbase = n0 + wc*32;
    const int cb = (lane & 3)*2;
    #pragma unroll
    for (int nt = 0; nt < 4; nt++) {
        int col = cbase + nt*8 + cb;
        float b0 = bias[col], b1 = bias[col+1];
        float v0 = c[nt][0]+b0, v1 = c[nt][1]+b1;
        float v2 = c[nt][2]+b0, v3 = c[nt][3]+b1;
        u32* O = (u32*)out1;
        float sc = (col < 128) ? (QSCALE*LOG2E) : 1.0f;
        O[((size_t)row*N + col) >> 1]     = cvtbf2(v1*sc, v0*sc);
        O[((size_t)(row+8)*N + col) >> 1] = cvtbf2(v3*sc, v2*sc);
    }
}

// ---------------- fused (sa_out+LN1)? + MLP (2 warp-groups, 1.5-buffered) + LN(...) ----------------
template<int MODE, int SAOUT>
__global__ __launch_bounds__(512) void k_mlpln(
    const __nv_bfloat16* __restrict__ Ah, const __nv_bfloat16* __restrict__ Al,
    const __nv_bfloat16* __restrict__ W1h, const __nv_bfloat16* __restrict__ W1l,
    const float* __restrict__ b1,
    const __nv_bfloat16* __restrict__ W2h, const __nv_bfloat16* __restrict__ W2l,
    const float* __restrict__ b2,
    const float* __restrict__ R,
    const float* __restrict__ ng1, const float* __restrict__ nb1,
    const float* __restrict__ ng2, const float* __restrict__ nb2,
    const float* __restrict__ catab, const int* __restrict__ labels,
    float* __restrict__ outf, __nv_bfloat16* __restrict__ oh, __nv_bfloat16* __restrict__ ol,
    const __nv_bfloat16* __restrict__ Woh, const __nv_bfloat16* __restrict__ Wol,
    const float* __restrict__ sab, const float* __restrict__ Rpre,
    const float* __restrict__ ln1g, const float* __restrict__ ln1b)
{
    extern __shared__ char sm[];
    const u32 SXF = 163840, SC = 184320, SX = 201216;
    float* sC = (float*)(sm + SC);
    float* sX = (float*)(sm + SX);

    const int tid = threadIdx.x;
    const int lane = tid & 31, w = tid >> 5;
    const int g = w >> 3, lw = w & 7, ltid = tid & 255;
    const int wr = lw & 1, wc = lw >> 1;
    const int gb = 1 + g;
    const int m0 = blockIdx.x * 32;
    const u32 smb = s2u(sm);
    const u32 frag_off = (u32)((lane & 15)*80 + (lane >> 4)*16);
    const int r0 = wr*16 + (lane >> 2);
    const u32 GW1 = (u32)g*81920u;
    const u32 GW2 = 40960u + (u32)g*81920u;
    const u32 GH  = 163840u + (u32)g*10240u;

    if (SAOUT) {
        #pragma unroll
        for (int i = 0; i < 2; i++) {
            int idx = tid + i*512;
            int kc = idx >> 8; int rem = idx & 255; int mat = rem >> 7; int rm = rem & 127;
            int row = rm >> 2; int seg = rm & 3;
            const __nv_bfloat16* src = (mat ? Al : Ah) + (size_t)(m0+row)*128 + kc*32 + seg*8;
            cpa16(smb + SXF + (u32)(kc*5120 + mat*2560 + row*80 + seg*16), src);
        }
        #pragma unroll
        for (int i = 0; i < 8; i++) {
            int idx = tid + i*512;
            int seg = idx & 3; int row = (idx >> 2) & 127; int mat = (idx >> 9) & 1; int kc = idx >> 10;
            const __nv_bfloat16* src = (mat ? Wol : Woh) + (size_t)row*128 + kc*32 + seg*8;
            cpa16(smb + (u32)(kc*20480 + mat*10240 + row*80 + seg*16), src);
        }
        cpa_commit();
        cpa_wait0();
        __syncthreads();

        const int wr2 = w & 1, wc2 = w >> 1;
        float cp[2][4];
        cp[0][0]=0.f; cp[0][1]=0.f; cp[0][2]=0.f; cp[0][3]=0.f;
        cp[1][0]=0.f; cp[1][1]=0.f; cp[1][2]=0.f; cp[1][3]=0.f;
        {
            u32 aA = smb + SXF + (u32)(wr2*16*80) + frag_off;
            u32 aW = smb + (u32)(wc2*16*80) + frag_off;
            #pragma unroll
            for (int kc = 0; kc < 4; kc++) {
                #pragma unroll
                for (int sub = 0; sub < 2; sub++) {
                    u32 koA = (u32)(kc*5120 + sub*32);
                    u32 koB = (u32)(kc*20480 + sub*32);
                    uint4 fAh = ldsm4(aA + koA);
                    uint4 fAl = ldsm4(aA + koA + 2560);
                    uint4 bh = ldsm4(aW + koB);
                    uint4 bl = ldsm4(aW + koB + 10240);
                    mma16816(cp[0], fAh, bh.x, bh.z);
                    mma16816(cp[1], fAh, bh.y, bh.w);
                    mma16816(cp[0], fAh, bl.x, bl.z);
                    mma16816(cp[1], fAh, bl.y, bl.w);
                    mma16816(cp[0], fAl, bh.x, bh.z);
                    mma16816(cp[1], fAl, bh.y, bh.w);
                }
            }
        }
        {
            const int cb = (lane & 3)*2;
            const int rp = wr2*16 + (lane >> 2);
            #pragma unroll
            for (int nt = 0; nt < 2; nt++) {
                int col = wc2*16 + nt*8 + cb;
                float bb0 = sab[col], bb1 = sab[col+1];
                sC[rp*132 + col]       = cp[nt][0] + bb0;
                sC[rp*132 + col + 1]   = cp[nt][1] + bb1;
                sC[(rp+8)*132 + col]     = cp[nt][2] + bb0;
                sC[(rp+8)*132 + col + 1] = cp[nt][3] + bb1;
            }
        }
        __syncthreads();

        float4 g1v = *(const float4*)&ln1g[lane*4];
        float4 b1v = *(const float4*)&ln1b[lane*4];
        #pragma unroll
        for (int rr = 0; rr < 2; rr++) {
            int rl2 = w*2 + rr;
            int row = m0 + rl2;
            float4 v = *(float4*)&sC[rl2*132 + lane*4];
            float4 rv = *(const float4*)&Rpre[(size_t)row*128 + lane*4];
            v.x += rv.x; v.y += rv.y; v.z += rv.z; v.w += rv.w;
            float s  = v.x + v.y + v.z + v.w;
            float s2 = v.x*v.x + v.y*v.y + v.z*v.z + v.w*v.w;
            #pragma unroll
            for (int off = 16; off > 0; off >>= 1) {
                s  += __shfl_xor_sync(0xffffffffu, s,  off);
                s2 += __shfl_xor_sync(0xffffffffu, s2, off);
            }
            float mean = s * (1.0f/128.0f);
            float var  = s2 * (1.0f/128.0f) - mean*mean;
            float rstd = rsqrtf(var + 1e-5f);
            v.x = (v.x - mean)*rstd*g1v.x + b1v.x;
            v.y = (v.y - mean)*rstd*g1v.y + b1v.y;
            v.z = (v.z - mean)*rstd*g1v.z + b1v.z;
            v.w = (v.w - mean)*rstd*g1v.w + b1v.w;
            *(float4*)&sX[rl2*128 + lane*4] = v;
            int kc = lane >> 3;
            int cc = (lane*4) & 31;
            char* p0 = sm + SXF + kc*5120 + rl2*80 + cc*2;
            u32 hp, lp;
            split2(v.x, v.y, hp, lp);
            *(u32*)p0 = hp; *(u32*)(p0 + 2560) = lp;
            split2(v.z, v.w, hp, lp);
            *(u32*)(p0 + 4) = hp; *(u32*)(p0 + 2560 + 4) = lp;
        }
        __syncthreads();
    } else {
        #pragma unroll
        for (int i = 0; i < 2; i++) {
            int idx = tid + i*512;
            int kc = idx >> 8; int rem = idx & 255; int mat = rem >> 7; int rm = rem & 127;
            int row = rm >> 2; int seg = rm & 3;
            const __nv_bfloat16* src = (mat ? Al : Ah) + (size_t)(m0+row)*128 + kc*32 + seg*8;
            cpa16(smb + SXF + (u32)(kc*5120 + mat*2560 + row*80 + seg*16), src);
        }
        cpa_commit();
        cpa_wait0();
        __syncthreads();
    }

    // x fragments to registers (all 16 warps)
    uint4 fXh[4][2], fXl[4][2];
    {
        u32 aX = smb + SXF + (u32)(wr*16*80) + frag_off;
        #pragma unroll
        for (int kc = 0; kc < 4; kc++) {
            fXh[kc][0] = ldsm4(aX + kc*5120);
            fXh[kc][1] = ldsm4(aX + kc*5120 + 32);
            fXl[kc][0] = ldsm4(aX + kc*5120 + 2560);
            fXl[kc][1] = ldsm4(aX + kc*5120 + 2560 + 32);
        }
    }
    __syncthreads();   // SXF region becomes H buffers after this

    // staging helpers (per group, 256 threads)
    auto stageW1 = [&](int nh) {
        #pragma unroll
        for (int i = 0; i < 8; i++) {
            int idx = ltid + i*256;
            int kc = idx >> 9; int rem = idx & 511; int mat = rem >> 8; int rm = rem & 255;
            int row = rm >> 2; int seg = rm & 3;
            const __nv_bfloat16* src = (mat ? W1l : W1h) + (size_t)(nh*64+row)*128 + kc*32 + seg*8;
            cpa16(smb + GW1 + (u32)(kc*10240 + mat*5120 + row*80 + seg*16), src);
        }
    };
    auto stageW2 = [&](int nh) {
        #pragma unroll
        for (int i = 0; i < 8; i++) {
            int idx = ltid + i*256;
            int kc = idx >> 10; int rem = idx & 1023; int mat = rem >> 9; int rm = rem & 511;
            int row = rm >> 2; int seg = rm & 3;
            const __nv_bfloat16* src = (mat ? W2l : W2h) + (size_t)row*512 + nh*64 + kc*32 + seg*8;
            cpa16(smb + GW2 + (u32)(kc*20480 + mat*10240 + row*80 + seg*16), src);
        }
    };

    // prologue: W1_0 and W2_0 in separate commit groups
    stageW1(g); cpa_commit();
    stageW2(g); cpa_commit();

    float c2[4][4];
    #pragma unroll
    for (int j = 0; j < 4; j++) { c2[j][0]=0.f; c2[j][1]=0.f; c2[j][2]=0.f; c2[j][3]=0.f; }

    for (int ii = 0; ii < 4; ii++) {
        const int nh = g + ii*2;
        cpa_wait1();            // W1_ii arrived (W2_ii may still be in flight)
        gbar(gb);

        // GEMM1: c1 = x @ W1chunk^T
        float c1[2][4];
        c1[0][0]=0.f; c1[0][1]=0.f; c1[0][2]=0.f; c1[0][3]=0.f;
        c1[1][0]=0.f; c1[1][1]=0.f; c1[1][2]=0.f; c1[1][3]=0.f;
        {
            u32 aW1 = smb + GW1 + (u32)(wc*16*80) + frag_off;
            #pragma unroll
            for (int kc = 0; kc < 4; kc++) {
                #pragma unroll
                for (int sub = 0; sub < 2; sub++) {
                    u32 ko = (u32)(kc*10240 + sub*32);
                    uint4 bh = ldsm4(aW1 + ko);
                    uint4 bl = ldsm4(aW1 + ko + 5120);
                    uint4 fh = fXh[kc][sub], fl = fXl[kc][sub];
                    mma16816(c1[0], fh, bh.x, bh.z);
                    mma16816(c1[1], fh, bh.y, bh.w);
                    mma16816(c1[0], fh, bl.x, bl.z);
                    mma16816(c1[1], fh, bl.y, bl.w);
                    mma16816(c1[0], fl, bh.x, bh.z);
                    mma16816(c1[1], fl, bh.y, bh.w);
                }
            }
        }
        // bias + gelu + hi/lo -> H[g]
        #pragma unroll
        for (int nt = 0; nt < 2; nt++) {
            int hc = wc*16 + nt*8 + (lane & 3)*2;
            float bb0 = b1[nh*64 + hc], bb1 = b1[nh*64 + hc + 1];
            float v0 = c1[nt][0]+bb0, v1 = c1[nt][1]+bb1;
            float v2 = c1[nt][2]+bb0, v3 = c1[nt][3]+bb1;
            v0 = 0.5f*v0*(1.0f + erff(v0*0.7071067811865475f));
            v1 = 0.5f*v1*(1.0f + erff(v1*0.7071067811865475f));
            v2 = 0.5f*v2*(1.0f + erff(v2*0.7071067811865475f));
            v3 = 0.5f*v3*(1.0f + erff(v3*0.7071067811865475f));
            int kc2 = hc >> 5, cc = hc & 31;
            char* p0 = sm + GH + kc2*5120 + r0*80 + cc*2;
            u32 hp, lp;
            split2(v0, v1, hp, lp);
            *(u32*)p0 = hp; *(u32*)(p0 + 2560) = lp;
            split2(v2, v3, hp, lp);
            *(u32*)(p0 + 640) = hp; *(u32*)(p0 + 640 + 2560) = lp;
        }
        gbar(gb);   // GEMM1 done by all; W1 region free, H visible

        // prefetch next W1 into freed region; overlaps GEMM2
        if (ii < 3) { stageW1(g + (ii+1)*2); cpa_commit(); cpa_wait1(); }
        else cpa_wait0();
        gbar(gb);   // W2_ii arrived + visible to all

        // GEMM2: c2 += h @ W2chunk^T
        {
            u32 aH  = smb + GH + (u32)(wr*16*80) + frag_off;
            u32 aW2 = smb + GW2 + (u32)(wc*32*80) + frag_off;
            #pragma unroll
            for (int kc = 0; kc < 2; kc++) {
                #pragma unroll
                for (int sub = 0; sub < 2; sub++) {
                    u32 koA = (u32)(kc*5120 + sub*32);
                    u32 koB = (u32)(kc*20480 + sub*32);
                    uint4 ah = ldsm4(aH + koA);
                    uint4 al = ldsm4(aH + koA + 2560);
                    uint4 bh0 = ldsm4(aW2 + koB);
                    uint4 bh1 = ldsm4(aW2 + koB + 1280);
                    uint4 bl0 = ldsm4(aW2 + koB + 10240);
                    uint4 bl1 = ldsm4(aW2 + koB + 10240 + 1280);
                    mma16816(c2[0], ah, bh0.x, bh0.z);
                    mma16816(c2[1], ah, bh0.y, bh0.w);
                    mma16816(c2[2], ah, bh1.x, bh1.z);
                    mma16816(c2[3], ah, bh1.y, bh1.w);
                    mma16816(c2[0], ah, bl0.x, bl0.z);
                    mma16816(c2[1], ah, bl0.y, bl0.w);
                    mma16816(c2[2], ah, bl1.x, bl1.z);
                    mma16816(c2[3], ah, bl1.y, bl1.w);
                    mma16816(c2[0], al, bh0.x, bh0.z);
                    mma16816(c2[1], al, bh0.y, bh0.w);
                    mma16816(c2[2], al, bh1.x, bh1.z);
                    mma16816(c2[3], al, bh1.y, bh1.w);
                }
            }
        }
        gbar(gb);   // GEMM2 done; W2/H regions free

        // prefetch next W2; overlaps next GEMM1
        if (ii < 3) { stageW2(g + (ii+1)*2); cpa_commit(); }
    }

    // combine group partials: group 1 publishes, group 0 accumulates
    __syncthreads();
    float* P = (float*)sm;
    if (g == 1) {
        float* dst = P + ltid*16;
        #pragma unroll
        for (int j = 0; j < 4; j++) {
            dst[j*4+0] = c2[j][0]; dst[j*4+1] = c2[j][1];
            dst[j*4+2] = c2[j][2]; dst[j*4+3] = c2[j][3];
        }
    }
    __syncthreads();
    if (g == 1) return;
    {
        const float* src = P + ltid*16;
        #pragma unroll
        for (int j = 0; j < 4; j++) {
            c2[j][0] += src[j*4+0]; c2[j][1] += src[j*4+1];
            c2[j][2] += src[j*4+2]; c2[j][3] += src[j*4+3];
        }
    }

    {
        const int cb = (lane & 3)*2;
        #pragma unroll
        for (int nt = 0; nt < 4; nt++) {
            int col = wc*32 + nt*8 + cb;
            float bb0 = b2[col], bb1 = b2[col+1];
            sC[r0*132 + col]       = c2[nt][0] + bb0;
            sC[r0*132 + col + 1]   = c2[nt][1] + bb1;
            sC[(r0+8)*132 + col]     = c2[nt][2] + bb0;
            sC[(r0+8)*132 + col + 1] = c2[nt][3] + bb1;
        }
    }
    gbar(1);

    float4 g1v = *(const float4*)&ng1[lane*4];
    float4 b1v = *(const float4*)&nb1[lane*4];
    float4 g2v = make_float4(0,0,0,0), b2v = make_float4(0,0,0,0), fwv = make_float4(0,0,0,0);
    float fb = 0.f;
    if (MODE == 1) { g2v = *(const float4*)&ng2[lane*4]; b2v = *(const float4*)&nb2[lane*4]; }
    if (MODE == 2) { fwv = *(const float4*)&ng2[lane*4]; fb = nb2[0]; }

    #pragma unroll
    for (int rr = 0; rr < 4; rr++) {
        int rl2 = lw*4 + rr;
        int row = m0 + rl2;
        float4 v = *(float4*)&sC[rl2*132 + lane*4];
        float4 rv;
        if (SAOUT) rv = *(float4*)&sX[rl2*128 + lane*4];
        else       rv = *(const float4*)&R[(size_t)row*128 + lane*4];
        v.x += rv.x; v.y += rv.y; v.z += rv.z; v.w += rv.w;

        float s  = v.x + v.y + v.z + v.w;
        float s2 = v.x*v.x + v.y*v.y + v.z*v.z + v.w*v.w;
        #pragma unroll
        for (int off = 16; off > 0; off >>= 1) {
            s  += __shfl_xor_sync(0xffffffffu, s,  off);
            s2 += __shfl_xor_sync(0xffffffffu, s2, off);
        }
        float mean = s * (1.0f/128.0f);
        float var  = s2 * (1.0f/128.0f) - mean*mean;
        float rstd = rsqrtf(var + 1e-5f);
        v.x = (v.x - mean)*rstd*g1v.x + b1v.x;
        v.y = (v.y - mean)*rstd*g1v.y + b1v.y;
        v.z = (v.z - mean)*rstd*g1v.z + b1v.z;
        v.w = (v.w - mean)*rstd*g1v.w + b1v.w;

        if (MODE == 1) {
            int lab = labels[row];
            float4 cv = *(const float4*)&catab[(size_t)lab*128 + lane*4];
            v.x += cv.x; v.y += cv.y; v.z += cv.z; v.w += cv.w;
            float t1 = v.x + v.y + v.z + v.w;
            float t2 = v.x*v.x + v.y*v.y + v.z*v.z + v.w*v.w;
            #pragma unroll
            for (int off = 16; off > 0; off >>= 1) {
                t1 += __shfl_xor_sync(0xffffffffu, t1, off);
                t2 += __shfl_xor_sync(0xffffffffu, t2, off);
            }
            float mean2 = t1 * (1.0f/128.0f);
            float var2  = t2 * (1.0f/128.0f) - mean2*mean2;
            float rstd2 = rsqrtf(var2 + 1e-5f);
            v.x = (v.x - mean2)*rstd2*g2v.x + b2v.x;
            v.y = (v.y - mean2)*rstd2*g2v.y + b2v.y;
            v.z = (v.z - mean2)*rstd2*g2v.z + b2v.z;
            v.w = (v.w - mean2)*rstd2*g2v.w + b2v.w;
        }

        if (MODE == 2) {
            float d = v.x*fwv.x + v.y*fwv.y + v.z*fwv.z + v.w*fwv.w;
            #pragma unroll
            for (int off = 16; off > 0; off >>= 1) d += __shfl_xor_sync(0xffffffffu, d, off);
            if (lane == 0) outf[row] = 1.0f/(1.0f + expf(-(d + fb)));
        } else {
            *(float4*)&outf[(size_t)row*128 + lane*4] = v;
            u32 hp, lp;
            size_t idx = ((size_t)row*128 + lane*4) >> 1;
            split2(v.x, v.y, hp, lp);
            ((u32*)oh)[idx]   = hp; ((u32*)ol)[idx]   = lp;
            split2(v.z, v.w, hp, lp);
            ((u32*)oh)[idx+1] = hp; ((u32*)ol)[idx+1] = lp;
        }
    }
}

// ---------------- flash attention (round-11 measured version) ----------------
__global__ __launch_bounds__(512, 1) void k_attn() {
    extern __shared__ __nv_bfloat16 smh[];
    __nv_bfloat16* Qs  = smh;
    __nv_bfloat16* Ks0 = smh + 5120;
    __nv_bfloat16* Ks1 = smh + 10240;
    __nv_bfloat16* Vs0 = smh + 15360;
    __nv_bfloat16* Vs1 = smh + 20480;
    float* cbuf = (float*)(smh + 25600);

    const int h  = blockIdx.y;
    const int q0 = blockIdx.x * 128;
    const int tid  = threadIdx.x;
    const int lane = tid & 31;
    const int w    = tid >> 5;
    const int wq   = w & 3;
    const int hf   = w >> 2;

    const __nv_bfloat16* QKV = g_qkvh;

    const int sr = tid >> 2, sg = (tid & 3)*16;
    {
        const char* gq = (const char*)(QKV + (size_t)(q0 + sr)*384 + h*32);
        cpa16(s2u(Qs + sr*40) + sg, gq + sg);
        const char* gk = (const char*)(QKV + (size_t)sr*384 + 128 + h*32);
        cpa16(s2u(Ks0 + sr*40) + sg, gk + sg);
        const char* gv = (const char*)(QKV + (size_t)sr*384 + 256 + h*32);
        cpa16(s2u(Vs0 + sr*40) + sg, gv + sg);
    }
    cpa_commit();
    cpa_wait0();
    __syncthreads();

    const u32 frag_off = (u32)((lane & 15)*80 + (lane >> 4)*16);
    const u32 aQ  = s2u(Qs)  + (u32)(wq*32*80) + frag_off;
    const u32 qofs = (u32)hf * 2560u;
    const u32 aK0 = s2u(Ks0) + qofs + frag_off;
    const u32 aK1 = s2u(Ks1) + qofs + frag_off;
    const u32 aV0 = s2u(Vs0) + qofs + frag_off;
    const u32 aV1 = s2u(Vs1) + qofs + frag_off;

    uint4 qa[2][2];
    qa[0][0] = ldsm4(aQ);
    qa[0][1] = ldsm4(aQ + 32);
    qa[1][0] = ldsm4(aQ + 1280);
    qa[1][1] = ldsm4(aQ + 1280 + 32);

    float o[2][4][4];
    #pragma unroll
    for (int rg = 0; rg < 2; rg++)
        #pragma unroll
        for (int j = 0; j < 4; j++) { o[rg][j][0]=0.f; o[rg][j][1]=0.f; o[rg][j][2]=0.f; o[rg][j][3]=0.f; }
    float l[2][2] = {{0.f,0.f},{0.f,0.f}};

    for (int t = 0; t < 32; t++) {
        if (t < 31) {
            int row = (t+1)*128 + sr;
            const char* gk = (const char*)(QKV + (size_t)row*384 + 128 + h*32);
            const char* gv = (const char*)(QKV + (size_t)row*384 + 256 + h*32);
            cpa16(s2u(((t & 1) ? Ks0 : Ks1) + sr*40) + sg, gk + sg);
            cpa16(s2u(((t & 1) ? Vs0 : Vs1) + sr*40) + sg, gv + sg);
            cpa_commit();
        }
        const u32 aKb = (t & 1) ? aK1 : aK0;
        const u32 aVb = (t & 1) ? aV1 : aV0;

        float c[2][4][4];
        #pragma unroll
        for (int rg = 0; rg < 2; rg++)
            #pragma unroll
            for (int j = 0; j < 4; j++) { c[rg][j][0]=0.f; c[rg][j][1]=0.f; c[rg][j][2]=0.f; c[rg][j][3]=0.f; }

        #pragma unroll
        for (int g = 0; g < 2; g++) {
            uint4 k0 = ldsm4(aKb + g*1280);
            uint4 k1 = ldsm4(aKb + g*1280 + 32);
            #pragma unroll
            for (int rg = 0; rg < 2; rg++) {
                mma16816(c[rg][2*g],   qa[rg][0], k0.x, k0.z);
                mma16816(c[rg][2*g+1], qa[rg][0], k0.y, k0.w);
                mma16816(c[rg][2*g],   qa[rg][1], k1.x, k1.z);
                mma16816(c[rg][2*g+1], qa[rg][1], k1.y, k1.w);
            }
        }

        #pragma unroll
        for (int rg = 0; rg < 2; rg++) {
            #pragma unroll
            for (int j = 0; j < 4; j++) {
                c[rg][j][0] = ex2f(c[rg][j][0]);
                c[rg][j][1] = ex2f(c[rg][j][1]);
                c[rg][j][2] = ex2f(c[rg][j][2]);
                c[rg][j][3] = ex2f(c[rg][j][3]);
                l[rg][0] += c[rg][j][0] + c[rg][j][1];
                l[rg][1] += c[rg][j][2] + c[rg][j][3];
            }
        }

        #pragma unroll
        for (int kc = 0; kc < 2; kc++) {
            uint4 v0 = ldsm4t(aVb + kc*1280);
            uint4 v1 = ldsm4t(aVb + kc*1280 + 32);
            #pragma unroll
            for (int rg = 0; rg < 2; rg++) {
                uint4 pa;
                pa.x = cvtbf2(c[rg][2*kc][1],   c[rg][2*kc][0]);
                pa.y = cvtbf2(c[rg][2*kc][3],   c[rg][2*kc][2]);
                pa.z = cvtbf2(c[rg][2*kc+1][1], c[rg][2*kc+1][0]);
                pa.w = cvtbf2(c[rg][2*kc+1][3], c[rg][2*kc+1][2]);
                mma16816(o[rg][0], pa, v0.x, v0.y);
                mma16816(o[rg][1], pa, v0.z, v0.w);
                mma16816(o[rg][2], pa, v1.x, v1.y);
                mma16816(o[rg][3], pa, v1.z, v1.w);
            }
        }

        if (t < 31) cpa_wait0();
        __syncthreads();
    }

    if (hf > 0) {
        float* dst = cbuf + (size_t)(hf-1)*128*36 + (wq*32 + lane)*36;
        #pragma unroll
        for (int rg = 0; rg < 2; rg++)
            #pragma unroll
            for (int j = 0; j < 4; j++)
                *(float4*)&dst[rg*16 + j*4] = make_float4(o[rg][j][0], o[rg][j][1], o[rg][j][2], o[rg][j][3]);
        *(float4*)&dst[32] = make_float4(l[0][0], l[0][1], l[1][0], l[1][1]);
    }
    __syncthreads();
    if (hf > 0) return;

    #pragma unroll
    for (int b = 0; b < 3; b++) {
        const float* src = cbuf + (size_t)b*128*36 + (wq*32 + lane)*36;
        #pragma unroll
        for (int rg = 0; rg < 2; rg++)
            #pragma unroll
            for (int j = 0; j < 4; j++) {
                float4 s4 = *(const float4*)&src[rg*16 + j*4];
                o[rg][j][0] += s4.x; o[rg][j][1] += s4.y; o[rg][j][2] += s4.z; o[rg][j][3] += s4.w;
            }
        float4 ls = *(const float4*)&src[32];
        l[0][0] += ls.x; l[0][1] += ls.y; l[1][0] += ls.z; l[1][1] += ls.w;
    }

    #pragma unroll
    for (int rg = 0; rg < 2; rg++) {
        #pragma unroll
        for (int p = 0; p < 2; p++) {
            l[rg][p] += __shfl_xor_sync(0xffffffffu, l[rg][p], 1);
            l[rg][p] += __shfl_xor_sync(0xffffffffu, l[rg][p], 2);
        }
    }

    u32* OH = (u32*)g_attnh;
    u32* OL = (u32*)g_attnl;
    const int col = h*32 + (lane & 3)*2;
    #pragma unroll
    for (int rg = 0; rg < 2; rg++) {
        float li0 = 1.0f / l[rg][0], li1 = 1.0f / l[rg][1];
        int row0 = q0 + wq*32 + rg*16 + (lane >> 2);
        #pragma unroll
        for (int j = 0; j < 4; j++) {
            u32 hp, lp;
            split2(o[rg][j][0]*li0, o[rg][j][1]*li0, hp, lp);
            OH[((size_t)row0*128 + col + j*8) >> 1] = hp;
            OL[((size_t)row0*128 + col + j*8) >> 1] = lp;
            split2(o[rg][j][2]*li1, o[rg][j][3]*li1, hp, lp);
            OH[((size_t)(row0+8)*128 + col + j*8) >> 1] = hp;
            OL[((size_t)(row0+8)*128 + col + j*8) >> 1] = lp;
        }
    }
}

// ---------------- launch ----------------
extern "C" void kernel_launch(void* const* d_in, const int* in_sizes, int n_in,
                              void* d_out, int out_size) {
    const float* coords   = (const float*)d_in[0];
    const int*   labels   = (const int*)  d_in[1];
    const float* ce_w     = (const float*)d_in[2];
    const float* ce_b     = (const float*)d_in[3];
    const float* emb      = (const float*)d_in[4];
    const float* sa_in_w  = (const float*)d_in[5];
    const float* sa_in_b  = (const float*)d_in[6];
    const float* sa_out_w = (const float*)d_in[7];
    const float* sa_out_b = (const float*)d_in[8];
    const float* n1_g     = (const float*)d_in[9];
    const float* n1_b     = (const float*)d_in[10];
    const float* m1_w1    = (const float*)d_in[11];
    const float* m1_b1    = (const float*)d_in[12];
    const float* m1_w2    = (const float*)d_in[13];
    const float* m1_b2    = (const float*)d_in[14];
    const float* n2_g     = (const float*)d_in[15];
    const float* n2_b     = (const float*)d_in[16];
    const float* ca_in_w  = (const float*)d_in[17];
    const float* ca_in_b  = (const float*)d_in[18];
    const float* ca_out_w = (const float*)d_in[19];
    const float* ca_out_b = (const float*)d_in[20];
    const float* n3_g     = (const float*)d_in[21];
    const float* n3_b     = (const float*)d_in[22];
    const float* m2_w1    = (const float*)d_in[23];
    const float* m2_b1    = (const float*)d_in[24];
    const float* m2_w2    = (const float*)d_in[25];
    const float* m2_b2    = (const float*)d_in[26];
    const float* n4_g     = (const float*)d_in[27];
    const float* n4_b     = (const float*)d_in[28];
    const float* fin_w    = (const float*)d_in[29];
    const float* fin_b    = (const float*)d_in[30];
    float* out = (float*)d_out;

    float *px, *py, *pca;
    __nv_bfloat16 *pxh, *pxl, *pqkvh, *pah, *pal, *pwh, *pwl;
    cudaGetSymbolAddress((void**)&px,    g_x);
    cudaGetSymbolAddress((void**)&py,    g_y);
    cudaGetSymbolAddress((void**)&pxh,   g_xh);
    cudaGetSymbolAddress((void**)&pxl,   g_xl);
    cudaGetSymbolAddress((void**)&pqkvh, g_qkvh);
    cudaGetSymbolAddress((void**)&pah,   g_attnh);
    cudaGetSymbolAddress((void**)&pal,   g_attnl);
    cudaGetSymbolAddress((void**)&pwh,   g_wh);
    cudaGetSymbolAddress((void**)&pwl,   g_wl);
    cudaGetSymbolAddress((void**)&pca,   g_ca);

    const int ATTN_SMEM = 5*128*40*2 + 3*128*36*4;   // 106496 B
    cudaFuncSetAttribute(k_attn, cudaFuncAttributeMaxDynamicSharedMemorySize, ATTN_SMEM);
    const int MLP_SMEM = 217600;
    cudaFuncSetAttribute(k_mlpln<1,1>, cudaFuncAttributeMaxDynamicSharedMemorySize, MLP_SMEM);
    cudaFuncSetAttribute(k_mlpln<2,0>, cudaFuncAttributeMaxDynamicSharedMemorySize, MLP_SMEM);

    WSrc ws;
    ws.p[0] = sa_in_w;  ws.p[1] = sa_out_w; ws.p[2] = m1_w1;
    ws.p[3] = m1_w2;    ws.p[4] = m2_w1;    ws.p[5] = m2_w2;
    ws.end[0] = WO_SAOUT/2; ws.end[1] = WO_M1W1/2; ws.end[2] = WO_M1W2/2;
    ws.end[3] = WO_M2W1/2;  ws.end[4] = WO_M2W2/2; ws.end[5] = W_TOTAL/2;

    k_setup<<<2698, 256>>>(ws, pwh, pwl, coords, ce_w, ce_b,
                           emb, ca_in_w + 2*DD*DD, ca_in_b + 2*DD, ca_out_w, ca_out_b);
    k_gemm3<<<dim3(6, 64), 256>>>(pxh, pxl, pwh+WO_SAIN, pwl+WO_SAIN, sa_in_b, pqkvh, 384, 128);
    k_attn<<<dim3(32, 4), 512, ATTN_SMEM>>>();
    k_mlpln<1,1><<<128, 512, MLP_SMEM>>>(pah, pal, pwh+WO_M1W1, pwl+WO_M1W1, m1_b1,
                                         pwh+WO_M1W2, pwl+WO_M1W2, m1_b2, nullptr,
                                         n2_g, n2_b, n3_g, n3_b, pca, labels,
                                         py, pxh, pxl,
                                         pwh+WO_SAOUT, pwl+WO_SAOUT, sa_out_b, px, n1_g, n1_b);
    k_mlpln<2,0><<<128, 512, MLP_SMEM>>>(pxh, pxl, pwh+WO_M2W1, pwl+WO_M2W1, m2_b1,
                                         pwh+WO_M2W2, pwl+WO_M2W2, m2_b2, py,
                                         n4_g, n4_b, fin_w, fin_b, nullptr, nullptr,
                                         out, nullptr, nullptr,
                                         nullptr, nullptr, nullptr, nullptr, nullptr, nullptr);
}

// round 16
// speedup vs baseline: 1.1978x; 1.1084x over previous
#include <cuda_runtime.h>
#include <cuda_bf16.h>
#include <math.h>

#define BB 4096
#define DD 128

typedef unsigned int u32;

// ---- tensor-core helpers ----
__device__ __forceinline__ uint4 ldsm4(u32 addr) {
    uint4 r;
    asm volatile("ldmatrix.sync.aligned.m8n8.x4.shared.b16 {%0,%1,%2,%3},[%4];"
        : "=r"(r.x), "=r"(r.y), "=r"(r.z), "=r"(r.w) : "r"(addr));
    return r;
}
__device__ __forceinline__ uint4 ldsm4t(u32 addr) {
    uint4 r;
    asm volatile("ldmatrix.sync.aligned.m8n8.x4.trans.shared.b16 {%0,%1,%2,%3},[%4];"
        : "=r"(r.x), "=r"(r.y), "=r"(r.z), "=r"(r.w) : "r"(addr));
    return r;
}
__device__ __forceinline__ void mma16816(float* c, uint4 a, u32 b0, u32 b1) {
    asm volatile(
        "mma.sync.aligned.m16n8k16.row.col.f32.bf16.bf16.f32 "
        "{%0,%1,%2,%3},{%4,%5,%6,%7},{%8,%9},{%0,%1,%2,%3};"
        : "+f"(c[0]), "+f"(c[1]), "+f"(c[2]), "+f"(c[3])
        : "r"(a.x), "r"(a.y), "r"(a.z), "r"(a.w), "r"(b0), "r"(b1));
}
__device__ __forceinline__ float ex2f(float x) {
    float y; asm("ex2.approx.f32 %0,%1;" : "=f"(y) : "f"(x)); return y;
}
__device__ __forceinline__ u32 cvtbf2(float hi, float lo) {
    u32 r; asm("cvt.rn.bf16x2.f32 %0,%1,%2;" : "=r"(r) : "f"(hi), "f"(lo)); return r;
}
__device__ __forceinline__ u32 s2u(const void* p) {
    return (u32)__cvta_generic_to_shared(p);
}
__device__ __forceinline__ void split2(float v0, float v1, u32& hp, u32& lp) {
    hp = cvtbf2(v1, v0);
    float h0 = __uint_as_float(hp << 16);
    float h1 = __uint_as_float(hp & 0xffff0000u);
    lp = cvtbf2(v1 - h1, v0 - h0);
}
__device__ __forceinline__ float2 bf2sum(u32 h, u32 l) {
    __nv_bfloat162 hb = *(__nv_bfloat162*)&h;
    __nv_bfloat162 lb = *(__nv_bfloat162*)&l;
    float2 r;
    r.x = __bfloat162float(hb.x) + __bfloat162float(lb.x);
    r.y = __bfloat162float(hb.y) + __bfloat162float(lb.y);
    return r;
}
__device__ __forceinline__ void cpa16(u32 dst, const void* src) {
    asm volatile("cp.async.cg.shared.global [%0],[%1],16;" :: "r"(dst), "l"(src));
}
__device__ __forceinline__ void cpa_commit() {
    asm volatile("cp.async.commit_group;");
}
__device__ __forceinline__ void cpa_wait0() {
    asm volatile("cp.async.wait_group 0;");
}
__device__ __forceinline__ void cpa_wait1() {
    asm volatile("cp.async.wait_group 1;");
}
__device__ __forceinline__ void gbar128(int id) {
    asm volatile("bar.sync %0, 128;" :: "r"(id) : "memory");
}

#define QSCALE 0.17677669529663688f
#define LOG2E  1.4426950408889634f

// ---------------- scratch ----------------
__device__ float g_x[BB*DD];
__device__ float g_y[BB*DD];
__device__ __nv_bfloat16 g_xh[BB*DD];
__device__ __nv_bfloat16 g_xl[BB*DD];
__device__ __nv_bfloat16 g_qkvh[BB*3*DD];
__device__ __nv_bfloat16 g_attnh[BB*DD];
__device__ __nv_bfloat16 g_attnl[BB*DD];
__device__ __nv_bfloat16 g_wh[327680];
__device__ __nv_bfloat16 g_wl[327680];
__device__ float g_ca[10*DD];

#define WO_SAIN  0
#define WO_SAOUT 49152
#define WO_M1W1  65536
#define WO_M1W2  131072
#define WO_M2W1  196608
#define WO_M2W2  262144
#define W_TOTAL  327680

// ---------------- setup: weight convert + embed + ca table ----------------
struct WSrc { const float* p[6]; int end[6]; };
__global__ __launch_bounds__(256) void k_setup(WSrc a, __nv_bfloat16* dh, __nv_bfloat16* dl,
    const float* __restrict__ coords, const float* __restrict__ ce_w, const float* __restrict__ ce_b,
    const float* __restrict__ emb, const float* __restrict__ wv, const float* __restrict__ bv,
    const float* __restrict__ wo, const float* __restrict__ bo)
{
    int b = blockIdx.x;
    int tid = threadIdx.x;
    if (b < 640) {
        int i = b*256 + tid;
        if (i >= a.end[5]) return;
        int k = 0;
        #pragma unroll
        for (int j = 1; j < 6; j++) if (i >= a.end[j-1]) k = j;
        int beg = (k > 0) ? a.end[k-1] : 0;
        float2 v = ((const float2*)a.p[k])[i - beg];
        u32 hp, lp; split2(v.x, v.y, hp, lp);
        ((u32*)dh)[i] = hp;
        ((u32*)dl)[i] = lp;
    } else if (b < 2688) {
        int i = (b - 640)*2 + (tid >> 7);
        int d = tid & 127;
        float c0 = coords[2*i], c1 = coords[2*i+1];
        int j = d >> 1;
        float dv = expf(9.210340371976184f * (float)j * (1.0f/64.0f));
        float pe = (d & 1) ? cosf(c1 / dv) : sinf(c0 / dv);
        float v = c0*ce_w[2*d] + c1*ce_w[2*d+1] + ce_b[d] + pe;
        g_x[i*DD + d] = v;
        __nv_bfloat16 h = __float2bfloat16_rn(v);
        g_xh[i*DD + d] = h;
        g_xl[i*DD + d] = __float2bfloat16_rn(v - __bfloat162float(h));
    } else {
        __shared__ float e[128], t[128];
        int c = b - 2688, j = tid;
        if (j < 128) e[j] = emb[c*128 + j];
        __syncthreads();
        if (j < 128) {
            float s = bv[j];
            #pragma unroll 8
            for (int d0 = 0; d0 < 128; d0++) s += e[d0]*wv[j*128 + d0];
            t[j] = s;
        }
        __syncthreads();
        if (j < 128) {
            float s2 = bo[j];
            #pragma unroll 8
            for (int d0 = 0; d0 < 128; d0++) s2 += t[d0]*wo[j*128 + d0];
            g_ca[c*128 + j] = s2;
        }
    }
}

// ---------------- 3xBF16 GEMM, 64x64 tile (qkv) ----------------
__global__ __launch_bounds__(256) void k_gemm3(
    const __nv_bfloat16* __restrict__ Ah, const __nv_bfloat16* __restrict__ Al,
    const __nv_bfloat16* __restrict__ Wh, const __nv_bfloat16* __restrict__ Wl,
    const float* __restrict__ bias,
    void* __restrict__ out1, int N, int K)
{
    __shared__ __nv_bfloat16 sA[2][2][64][40];
    __shared__ __nv_bfloat16 sW[2][2][64][40];

    const int tid = threadIdx.x;
    const int lane = tid & 31, w = tid >> 5;
    const int wr = w & 3, wc = w >> 2;
    const int m0 = blockIdx.y*64, n0 = blockIdx.x*64;
    const int r = tid >> 2, q = tid & 3;
    const int nc = K >> 5;

    const __nv_bfloat16* pAh = Ah + (size_t)(m0+r)*K + q*8;
    const __nv_bfloat16* pAl = Al + (size_t)(m0+r)*K + q*8;
    const __nv_bfloat16* pWh = Wh + (size_t)(n0+r)*K + q*8;
    const __nv_bfloat16* pWl = Wl + (size_t)(n0+r)*K + q*8;

    {
        uint4 va = *(const uint4*)pAh;
        uint4 vl = *(const uint4*)pAl;
        uint4 vw = *(const uint4*)pWh;
        uint4 vx = *(const uint4*)pWl;
        *(uint4*)&sA[0][0][r][q*8] = va;
        *(uint4*)&sA[0][1][r][q*8] = vl;
        *(uint4*)&sW[0][0][r][q*8] = vw;
        *(uint4*)&sW[0][1][r][q*8] = vx;
    }
    __syncthreads();

    float c[4][4];
    #pragma unroll
    for (int j = 0; j < 4; j++) { c[j][0]=0.f; c[j][1]=0.f; c[j][2]=0.f; c[j][3]=0.f; }

    const u32 frag_off = (u32)((lane & 15)*80 + (lane >> 4)*16);
    const u32 aA = s2u(&sA[0][0][0][0]) + (u32)(wr*16*80) + frag_off;
    const u32 aW = s2u(&sW[0][0][0][0]) + (u32)(wc*32*80) + frag_off;

    for (int t = 0; t < nc; t++) {
        uint4 va, vl, vw, vx;
        if (t + 1 < nc) {
            int o = (t+1)*32;
            va = *(const uint4*)(pAh+o);
            vl = *(const uint4*)(pAl+o);
            vw = *(const uint4*)(pWh+o);
            vx = *(const uint4*)(pWl+o);
        }
        u32 bofs = (u32)(t & 1) * 10240u;
        #pragma unroll
        for (int sub = 0; sub < 2; sub++) {
            u32 ko = bofs + sub*32;
            uint4 fAh = ldsm4(aA + ko);
            uint4 fAl = ldsm4(aA + ko + 5120);
            uint4 bh0 = ldsm4(aW + ko);
            uint4 bh1 = ldsm4(aW + ko + 1280);
            uint4 bl0 = ldsm4(aW + ko + 5120);
            uint4 bl1 = ldsm4(aW + ko + 5120 + 1280);
            mma16816(c[0], fAh, bh0.x, bh0.z);
            mma16816(c[1], fAh, bh0.y, bh0.w);
            mma16816(c[2], fAh, bh1.x, bh1.z);
            mma16816(c[3], fAh, bh1.y, bh1.w);
            mma16816(c[0], fAh, bl0.x, bl0.z);
            mma16816(c[1], fAh, bl0.y, bl0.w);
            mma16816(c[2], fAh, bl1.x, bl1.z);
            mma16816(c[3], fAh, bl1.y, bl1.w);
            mma16816(c[0], fAl, bh0.x, bh0.z);
            mma16816(c[1], fAl, bh0.y, bh0.w);
            mma16816(c[2], fAl, bh1.x, bh1.z);
            mma16816(c[3], fAl, bh1.y, bh1.w);
        }
        if (t + 1 < nc) {
            int nb = (t & 1) ^ 1;
            *(uint4*)&sA[nb][0][r][q*8] = va;
            *(uint4*)&sA[nb][1][r][q*8] = vl;
            *(uint4*)&sW[nb][0][r][q*8] = vw;
            *(uint4*)&sW[nb][1][r][q*8] = vx;
        }
        __syncthreads();
    }

    const int row = m0 + wr*16 + (lane >> 2);
    const int cbase = n0 + wc*32;
    const int cb = (lane & 3)*2;
    #pragma unroll
    for (int nt = 0; nt < 4; nt++) {
        int col = cbase + nt*8 + cb;
        float b0 = bias[col], b1 = bias[col+1];
        float v0 = c[nt][0]+b0, v1 = c[nt][1]+b1;
        float v2 = c[nt][2]+b0, v3 = c[nt][3]+b1;
        u32* O = (u32*)out1;
        float sc = (col < 128) ? (QSCALE*LOG2E) : 1.0f;
        O[((size_t)row*N + col) >> 1]     = cvtbf2(v1*sc, v0*sc);
        O[((size_t)(row+8)*N + col) >> 1] = cvtbf2(v3*sc, v2*sc);
    }
}

// ---------------- fused (sa_out+LN1)? + MLP (4 warp-groups x 2 chunks) + LN(...) ----------------
// 512 threads, 32 rows/CTA. Group g = w>>2 (128 thr) handles hidden chunks {g, g+4} of 32.
// smem (bytes): G(g) = g*46080: [GW1 20480][GW2 20480][GH 5120]
//   SXF = 184320 (20480): x hi/lo frag staging, PERSISTENT (epilogue residual for SAOUT)
//   SC  = 204800 (16896): fp32 tile.  Total 221696.
template<int MODE, int SAOUT>
__global__ __launch_bounds__(512) void k_mlpln(
    const __nv_bfloat16* __restrict__ Ah, const __nv_bfloat16* __restrict__ Al,
    const __nv_bfloat16* __restrict__ W1h, const __nv_bfloat16* __restrict__ W1l,
    const float* __restrict__ b1,
    const __nv_bfloat16* __restrict__ W2h, const __nv_bfloat16* __restrict__ W2l,
    const float* __restrict__ b2,
    const float* __restrict__ R,
    const float* __restrict__ ng1, const float* __restrict__ nb1,
    const float* __restrict__ ng2, const float* __restrict__ nb2,
    const float* __restrict__ catab, const int* __restrict__ labels,
    float* __restrict__ outf, __nv_bfloat16* __restrict__ oh, __nv_bfloat16* __restrict__ ol,
    const __nv_bfloat16* __restrict__ Woh, const __nv_bfloat16* __restrict__ Wol,
    const float* __restrict__ sab, const float* __restrict__ Rpre,
    const float* __restrict__ ln1g, const float* __restrict__ ln1b)
{
    extern __shared__ char sm[];
    const u32 SXF = 184320, SC = 204800;
    float* sC = (float*)(sm + SC);

    const int tid = threadIdx.x;
    const int lane = tid & 31, w = tid >> 5;
    const int g = w >> 2, lw = w & 3, ltid = tid & 127;
    const int wr = lw & 1, wc = lw >> 1;     // GEMM1: 16 rows x 16 hidden; GEMM2: 16 rows x 64 cols (wc as col-half)
    const int m0 = blockIdx.x * 32;
    const u32 smb = s2u(sm);
    const u32 frag_off = (u32)((lane & 15)*80 + (lane >> 4)*16);
    const int r0 = wr*16 + (lane >> 2);
    const u32 GW1 = (u32)g*46080u;
    const u32 GW2 = (u32)g*46080u + 20480u;
    const u32 GH  = (u32)g*46080u + 40960u;

    if (SAOUT) {
        // stage A (32 rows hi/lo) -> SXF ; Wo (128x128 hi/lo) -> bytes 0..81920
        #pragma unroll
        for (int i = 0; i < 2; i++) {
            int idx = tid + i*512;
            int kc = idx >> 8; int rem = idx & 255; int mat = rem >> 7; int rm = rem & 127;
            int row = rm >> 2; int seg = rm & 3;
            const __nv_bfloat16* src = (mat ? Al : Ah) + (size_t)(m0+row)*128 + kc*32 + seg*8;
            cpa16(smb + SXF + (u32)(kc*5120 + mat*2560 + row*80 + seg*16), src);
        }
        #pragma unroll
        for (int i = 0; i < 8; i++) {
            int idx = tid + i*512;
            int seg = idx & 3; int row = (idx >> 2) & 127; int mat = (idx >> 9) & 1; int kc = idx >> 10;
            const __nv_bfloat16* src = (mat ? Wol : Woh) + (size_t)row*128 + kc*32 + seg*8;
            cpa16(smb + (u32)(kc*20480 + mat*10240 + row*80 + seg*16), src);
        }
        cpa_commit();
        cpa_wait0();
        __syncthreads();

        // GEMM: attn @ Wo^T  (16 warps: wr2 row-half, wc2 16-col group)
        const int wr2 = w & 1, wc2 = w >> 1;
        float cp[2][4];
        cp[0][0]=0.f; cp[0][1]=0.f; cp[0][2]=0.f; cp[0][3]=0.f;
        cp[1][0]=0.f; cp[1][1]=0.f; cp[1][2]=0.f; cp[1][3]=0.f;
        {
            u32 aA = smb + SXF + (u32)(wr2*16*80) + frag_off;
            u32 aW = smb + (u32)(wc2*16*80) + frag_off;
            #pragma unroll
            for (int kc = 0; kc < 4; kc++) {
                #pragma unroll
                for (int sub = 0; sub < 2; sub++) {
                    u32 koA = (u32)(kc*5120 + sub*32);
                    u32 koB = (u32)(kc*20480 + sub*32);
                    uint4 fAh = ldsm4(aA + koA);
                    uint4 fAl = ldsm4(aA + koA + 2560);
                    uint4 bh = ldsm4(aW + koB);
                    uint4 bl = ldsm4(aW + koB + 10240);
                    mma16816(cp[0], fAh, bh.x, bh.z);
                    mma16816(cp[1], fAh, bh.y, bh.w);
                    mma16816(cp[0], fAh, bl.x, bl.z);
                    mma16816(cp[1], fAh, bl.y, bl.w);
                    mma16816(cp[0], fAl, bh.x, bh.z);
                    mma16816(cp[1], fAl, bh.y, bh.w);
                }
            }
        }
        {
            const int cb = (lane & 3)*2;
            const int rp = wr2*16 + (lane >> 2);
            #pragma unroll
            for (int nt = 0; nt < 2; nt++) {
                int col = wc2*16 + nt*8 + cb;
                float bb0 = sab[col], bb1 = sab[col+1];
                sC[rp*132 + col]       = cp[nt][0] + bb0;
                sC[rp*132 + col + 1]   = cp[nt][1] + bb1;
                sC[(rp+8)*132 + col]     = cp[nt][2] + bb0;
                sC[(rp+8)*132 + col + 1] = cp[nt][3] + bb1;
            }
        }
        __syncthreads();

        // LN1 (16 warps x 2 rows); hi/lo frags -> SXF (persistent; fp32 reconstructed later)
        float4 g1v = *(const float4*)&ln1g[lane*4];
        float4 b1v = *(const float4*)&ln1b[lane*4];
        #pragma unroll
        for (int rr = 0; rr < 2; rr++) {
            int rl2 = w*2 + rr;
            int row = m0 + rl2;
            float4 v = *(float4*)&sC[rl2*132 + lane*4];
            float4 rv = *(const float4*)&Rpre[(size_t)row*128 + lane*4];
            v.x += rv.x; v.y += rv.y; v.z += rv.z; v.w += rv.w;
            float s  = v.x + v.y + v.z + v.w;
            float s2 = v.x*v.x + v.y*v.y + v.z*v.z + v.w*v.w;
            #pragma unroll
            for (int off = 16; off > 0; off >>= 1) {
                s  += __shfl_xor_sync(0xffffffffu, s,  off);
                s2 += __shfl_xor_sync(0xffffffffu, s2, off);
            }
            float mean = s * (1.0f/128.0f);
            float var  = s2 * (1.0f/128.0f) - mean*mean;
            float rstd = rsqrtf(var + 1e-5f);
            v.x = (v.x - mean)*rstd*g1v.x + b1v.x;
            v.y = (v.y - mean)*rstd*g1v.y + b1v.y;
            v.z = (v.z - mean)*rstd*g1v.z + b1v.z;
            v.w = (v.w - mean)*rstd*g1v.w + b1v.w;
            int kc = lane >> 3;
            int cc = (lane*4) & 31;
            char* p0 = sm + SXF + kc*5120 + rl2*80 + cc*2;
            u32 hp, lp;
            split2(v.x, v.y, hp, lp);
            *(u32*)p0 = hp; *(u32*)(p0 + 2560) = lp;
            split2(v.z, v.w, hp, lp);
            *(u32*)(p0 + 4) = hp; *(u32*)(p0 + 2560 + 4) = lp;
        }
        __syncthreads();
    } else {
        #pragma unroll
        for (int i = 0; i < 2; i++) {
            int idx = tid + i*512;
            int kc = idx >> 8; int rem = idx & 255; int mat = rem >> 7; int rm = rem & 127;
            int row = rm >> 2; int seg = rm & 3;
            const __nv_bfloat16* src = (mat ? Al : Ah) + (size_t)(m0+row)*128 + kc*32 + seg*8;
            cpa16(smb + SXF + (u32)(kc*5120 + mat*2560 + row*80 + seg*16), src);
        }
        cpa_commit();
        cpa_wait0();
        __syncthreads();
    }

    // per-group staging helpers (128 threads)
    auto stageW1 = [&](int nh) {   // W1 chunk: 32 hidden rows x 128 K, hi/lo
        #pragma unroll
        for (int i = 0; i < 8; i++) {
            int idx = ltid + i*128;
            int seg = idx & 3; int row = (idx >> 2) & 31; int mat = (idx >> 7) & 1; int kc = idx >> 8;
            const __nv_bfloat16* src = (mat ? W1l : W1h) + (size_t)(nh*32+row)*128 + kc*32 + seg*8;
            cpa16(smb + GW1 + (u32)(kc*5120 + mat*2560 + row*80 + seg*16), src);
        }
    };
    auto stageW2 = [&](int nh) {   // W2 chunk: 128 out rows x 32 K, hi/lo
        #pragma unroll
        for (int i = 0; i < 8; i++) {
            int idx = ltid + i*128;
            int seg = idx & 3; int row = (idx >> 2) & 127; int mat = idx >> 9;
            const __nv_bfloat16* src = (mat ? W2l : W2h) + (size_t)row*512 + nh*32 + seg*8;
            cpa16(smb + GW2 + (u32)(mat*10240 + row*80 + seg*16), src);
        }
    };

    stageW1(g); cpa_commit();
    stageW2(g); cpa_commit();

    float c2[8][4];
    #pragma unroll
    for (int j = 0; j < 8; j++) { c2[j][0]=0.f; c2[j][1]=0.f; c2[j][2]=0.f; c2[j][3]=0.f; }

    const int gid = 1 + g;
    #pragma unroll
    for (int ii = 0; ii < 2; ii++) {
        const int nh = g + ii*4;
        cpa_wait1();
        gbar128(gid);

        // GEMM1: c1(16r x 16h per warp) = x @ W1chunk^T ; x frags reloaded from SXF
        float c1[2][4];
        c1[0][0]=0.f; c1[0][1]=0.f; c1[0][2]=0.f; c1[0][3]=0.f;
        c1[1][0]=0.f; c1[1][1]=0.f; c1[1][2]=0.f; c1[1][3]=0.f;
        {
            u32 aX  = smb + SXF + (u32)(wr*16*80) + frag_off;
            u32 aW1 = smb + GW1 + (u32)(wc*16*80) + frag_off;
            #pragma unroll
            for (int kc = 0; kc < 4; kc++) {
                #pragma unroll
                for (int sub = 0; sub < 2; sub++) {
                    u32 ko = (u32)(kc*5120 + sub*32);
                    uint4 fh = ldsm4(aX + ko);
                    uint4 fl = ldsm4(aX + ko + 2560);
                    uint4 bh = ldsm4(aW1 + ko);
                    uint4 bl = ldsm4(aW1 + ko + 2560);
                    mma16816(c1[0], fh, bh.x, bh.z);
                    mma16816(c1[1], fh, bh.y, bh.w);
                    mma16816(c1[0], fh, bl.x, bl.z);
                    mma16816(c1[1], fh, bl.y, bl.w);
                    mma16816(c1[0], fl, bh.x, bh.z);
                    mma16816(c1[1], fl, bh.y, bh.w);
                }
            }
        }
        // bias + gelu + hi/lo -> GH
        #pragma unroll
        for (int nt = 0; nt < 2; nt++) {
            int hc = wc*16 + nt*8 + (lane & 3)*2;   // 0..31 within chunk
            float bb0 = b1[nh*32 + hc], bb1 = b1[nh*32 + hc + 1];
            float v0 = c1[nt][0]+bb0, v1 = c1[nt][1]+bb1;
            float v2 = c1[nt][2]+bb0, v3 = c1[nt][3]+bb1;
            v0 = 0.5f*v0*(1.0f + erff(v0*0.7071067811865475f));
            v1 = 0.5f*v1*(1.0f + erff(v1*0.7071067811865475f));
            v2 = 0.5f*v2*(1.0f + erff(v2*0.7071067811865475f));
            v3 = 0.5f*v3*(1.0f + erff(v3*0.7071067811865475f));
            char* p0 = sm + GH + r0*80 + hc*2;
            u32 hp, lp;
            split2(v0, v1, hp, lp);
            *(u32*)p0 = hp; *(u32*)(p0 + 2560) = lp;
            split2(v2, v3, hp, lp);
            *(u32*)(p0 + 640) = hp; *(u32*)(p0 + 640 + 2560) = lp;
        }
        gbar128(gid);

        if (ii == 0) { stageW1(g + 4); cpa_commit(); cpa_wait1(); }
        else cpa_wait0();
        gbar128(gid);

        // GEMM2: c2(16r x 64c per warp) += h @ W2chunk^T
        {
            u32 aH  = smb + GH + (u32)(wr*16*80) + frag_off;
            u32 aW2 = smb + GW2 + (u32)(wc*64*80) + frag_off;
            #pragma unroll
            for (int sub = 0; sub < 2; sub++) {
                uint4 ah = ldsm4(aH + sub*32);
                uint4 al = ldsm4(aH + sub*32 + 2560);
                #pragma unroll
                for (int p = 0; p < 4; p++) {
                    uint4 bh = ldsm4(aW2 + p*1280 + sub*32);
                    uint4 bl = ldsm4(aW2 + p*1280 + sub*32 + 10240);
                    mma16816(c2[2*p],   ah, bh.x, bh.z);
                    mma16816(c2[2*p+1], ah, bh.y, bh.w);
                    mma16816(c2[2*p],   ah, bl.x, bl.z);
                    mma16816(c2[2*p+1], ah, bl.y, bl.w);
                    mma16816(c2[2*p],   al, bh.x, bh.z);
                    mma16816(c2[2*p+1], al, bh.y, bh.w);
                }
            }
        }
        gbar128(gid);

        if (ii == 0) { stageW2(g + 4); cpa_commit(); }
    }

    // combine: groups 1..3 publish c2; group 0 accumulates
    __syncthreads();
    float* P = (float*)sm;    // bytes 0..49152 (W regions dead)
    if (g > 0) {
        float* dst = P + ((size_t)(g-1)*128 + ltid)*32;
        #pragma unroll
        for (int j = 0; j < 8; j++)
            *(float4*)&dst[j*4] = make_float4(c2[j][0], c2[j][1], c2[j][2], c2[j][3]);
    }
    __syncthreads();
    if (g > 0) return;
    #pragma unroll
    for (int b = 0; b < 3; b++) {
        const float* src = P + ((size_t)b*128 + ltid)*32;
        #pragma unroll
        for (int j = 0; j < 8; j++) {
            float4 s4 = *(const float4*)&src[j*4];
            c2[j][0] += s4.x; c2[j][1] += s4.y; c2[j][2] += s4.z; c2[j][3] += s4.w;
        }
    }

    // epilogue (group 0, 128 threads): bias2 -> sC
    {
        const int cb = (lane & 3)*2;
        #pragma unroll
        for (int nt = 0; nt < 8; nt++) {
            int col = wc*64 + nt*8 + cb;
            float bb0 = b2[col], bb1 = b2[col+1];
            sC[r0*132 + col]       = c2[nt][0] + bb0;
            sC[r0*132 + col + 1]   = c2[nt][1] + bb1;
            sC[(r0+8)*132 + col]     = c2[nt][2] + bb0;
            sC[(r0+8)*132 + col + 1] = c2[nt][3] + bb1;
        }
    }
    gbar128(1);

    float4 g1v = *(const float4*)&ng1[lane*4];
    float4 b1v = *(const float4*)&nb1[lane*4];
    float4 g2v = make_float4(0,0,0,0), b2v = make_float4(0,0,0,0), fwv = make_float4(0,0,0,0);
    float fb = 0.f;
    if (MODE == 1) { g2v = *(const float4*)&ng2[lane*4]; b2v = *(const float4*)&nb2[lane*4]; }
    if (MODE == 2) { fwv = *(const float4*)&ng2[lane*4]; fb = nb2[0]; }

    #pragma unroll
    for (int rr = 0; rr < 8; rr++) {
        int rl2 = lw*8 + rr;
        int row = m0 + rl2;
        float4 v = *(float4*)&sC[rl2*132 + lane*4];
        float4 rv;
        if (SAOUT) {
            int kcr = lane >> 3;
            int ccr = (lane*4) & 31;
            const char* q = sm + SXF + kcr*5120 + rl2*80 + ccr*2;
            float2 a0 = bf2sum(*(const u32*)q,       *(const u32*)(q + 2560));
            float2 a1 = bf2sum(*(const u32*)(q + 4), *(const u32*)(q + 2564));
            rv = make_float4(a0.x, a0.y, a1.x, a1.y);
        } else {
            rv = *(const float4*)&R[(size_t)row*128 + lane*4];
        }
        v.x += rv.x; v.y += rv.y; v.z += rv.z; v.w += rv.w;

        float s  = v.x + v.y + v.z + v.w;
        float s2 = v.x*v.x + v.y*v.y + v.z*v.z + v.w*v.w;
        #pragma unroll
        for (int off = 16; off > 0; off >>= 1) {
            s  += __shfl_xor_sync(0xffffffffu, s,  off);
            s2 += __shfl_xor_sync(0xffffffffu, s2, off);
        }
        float mean = s * (1.0f/128.0f);
        float var  = s2 * (1.0f/128.0f) - mean*mean;
        float rstd = rsqrtf(var + 1e-5f);
        v.x = (v.x - mean)*rstd*g1v.x + b1v.x;
        v.y = (v.y - mean)*rstd*g1v.y + b1v.y;
        v.z = (v.z - mean)*rstd*g1v.z + b1v.z;
        v.w = (v.w - mean)*rstd*g1v.w + b1v.w;

        if (MODE == 1) {
            int lab = labels[row];
            float4 cv = *(const float4*)&catab[(size_t)lab*128 + lane*4];
            v.x += cv.x; v.y += cv.y; v.z += cv.z; v.w += cv.w;
            float t1 = v.x + v.y + v.z + v.w;
            float t2 = v.x*v.x + v.y*v.y + v.z*v.z + v.w*v.w;
            #pragma unroll
            for (int off = 16; off > 0; off >>= 1) {
                t1 += __shfl_xor_sync(0xffffffffu, t1, off);
                t2 += __shfl_xor_sync(0xffffffffu, t2, off);
            }
            float mean2 = t1 * (1.0f/128.0f);
            float var2  = t2 * (1.0f/128.0f) - mean2*mean2;
            float rstd2 = rsqrtf(var2 + 1e-5f);
            v.x = (v.x - mean2)*rstd2*g2v.x + b2v.x;
            v.y = (v.y - mean2)*rstd2*g2v.y + b2v.y;
            v.z = (v.z - mean2)*rstd2*g2v.z + b2v.z;
            v.w = (v.w - mean2)*rstd2*g2v.w + b2v.w;
        }

        if (MODE == 2) {
            float d = v.x*fwv.x + v.y*fwv.y + v.z*fwv.z + v.w*fwv.w;
            #pragma unroll
            for (int off = 16; off > 0; off >>= 1) d += __shfl_xor_sync(0xffffffffu, d, off);
            if (lane == 0) outf[row] = 1.0f/(1.0f + expf(-(d + fb)));
        } else {
            *(float4*)&outf[(size_t)row*128 + lane*4] = v;
            u32 hp, lp;
            size_t idx = ((size_t)row*128 + lane*4) >> 1;
            split2(v.x, v.y, hp, lp);
            ((u32*)oh)[idx]   = hp; ((u32*)ol)[idx]   = lp;
            split2(v.z, v.w, hp, lp);
            ((u32*)oh)[idx+1] = hp; ((u32*)ol)[idx+1] = lp;
        }
    }
}

// ---------------- flash attention (round-11 measured version) ----------------
__global__ __launch_bounds__(512, 1) void k_attn() {
    extern __shared__ __nv_bfloat16 smh[];
    __nv_bfloat16* Qs  = smh;
    __nv_bfloat16* Ks0 = smh + 5120;
    __nv_bfloat16* Ks1 = smh + 10240;
    __nv_bfloat16* Vs0 = smh + 15360;
    __nv_bfloat16* Vs1 = smh + 20480;
    float* cbuf = (float*)(smh + 25600);

    const int h  = blockIdx.y;
    const int q0 = blockIdx.x * 128;
    const int tid  = threadIdx.x;
    const int lane = tid & 31;
    const int w    = tid >> 5;
    const int wq   = w & 3;
    const int hf   = w >> 2;

    const __nv_bfloat16* QKV = g_qkvh;

    const int sr = tid >> 2, sg = (tid & 3)*16;
    {
        const char* gq = (const char*)(QKV + (size_t)(q0 + sr)*384 + h*32);
        cpa16(s2u(Qs + sr*40) + sg, gq + sg);
        const char* gk = (const char*)(QKV + (size_t)sr*384 + 128 + h*32);
        cpa16(s2u(Ks0 + sr*40) + sg, gk + sg);
        const char* gv = (const char*)(QKV + (size_t)sr*384 + 256 + h*32);
        cpa16(s2u(Vs0 + sr*40) + sg, gv + sg);
    }
    cpa_commit();
    cpa_wait0();
    __syncthreads();

    const u32 frag_off = (u32)((lane & 15)*80 + (lane >> 4)*16);
    const u32 aQ  = s2u(Qs)  + (u32)(wq*32*80) + frag_off;
    const u32 qofs = (u32)hf * 2560u;
    const u32 aK0 = s2u(Ks0) + qofs + frag_off;
    const u32 aK1 = s2u(Ks1) + qofs + frag_off;
    const u32 aV0 = s2u(Vs0) + qofs + frag_off;
    const u32 aV1 = s2u(Vs1) + qofs + frag_off;

    uint4 qa[2][2];
    qa[0][0] = ldsm4(aQ);
    qa[0][1] = ldsm4(aQ + 32);
    qa[1][0] = ldsm4(aQ + 1280);
    qa[1][1] = ldsm4(aQ + 1280 + 32);

    float o[2][4][4];
    #pragma unroll
    for (int rg = 0; rg < 2; rg++)
        #pragma unroll
        for (int j = 0; j < 4; j++) { o[rg][j][0]=0.f; o[rg][j][1]=0.f; o[rg][j][2]=0.f; o[rg][j][3]=0.f; }
    float l[2][2] = {{0.f,0.f},{0.f,0.f}};

    for (int t = 0; t < 32; t++) {
        if (t < 31) {
            int row = (t+1)*128 + sr;
            const char* gk = (const char*)(QKV + (size_t)row*384 + 128 + h*32);
            const char* gv = (const char*)(QKV + (size_t)row*384 + 256 + h*32);
            cpa16(s2u(((t & 1) ? Ks0 : Ks1) + sr*40) + sg, gk + sg);
            cpa16(s2u(((t & 1) ? Vs0 : Vs1) + sr*40) + sg, gv + sg);
            cpa_commit();
        }
        const u32 aKb = (t & 1) ? aK1 : aK0;
        const u32 aVb = (t & 1) ? aV1 : aV0;

        float c[2][4][4];
        #pragma unroll
        for (int rg = 0; rg < 2; rg++)
            #pragma unroll
            for (int j = 0; j < 4; j++) { c[rg][j][0]=0.f; c[rg][j][1]=0.f; c[rg][j][2]=0.f; c[rg][j][3]=0.f; }

        #pragma unroll
        for (int gg = 0; gg < 2; gg++) {
            uint4 k0 = ldsm4(aKb + gg*1280);
            uint4 k1 = ldsm4(aKb + gg*1280 + 32);
            #pragma unroll
            for (int rg = 0; rg < 2; rg++) {
                mma16816(c[rg][2*gg],   qa[rg][0], k0.x, k0.z);
                mma16816(c[rg][2*gg+1], qa[rg][0], k0.y, k0.w);
                mma16816(c[rg][2*gg],   qa[rg][1], k1.x, k1.z);
                mma16816(c[rg][2*gg+1], qa[rg][1], k1.y, k1.w);
            }
        }

        #pragma unroll
        for (int rg = 0; rg < 2; rg++) {
            #pragma unroll
            for (int j = 0; j < 4; j++) {
                c[rg][j][0] = ex2f(c[rg][j][0]);
                c[rg][j][1] = ex2f(c[rg][j][1]);
                c[rg][j][2] = ex2f(c[rg][j][2]);
                c[rg][j][3] = ex2f(c[rg][j][3]);
                l[rg][0] += c[rg][j][0] + c[rg][j][1];
                l[rg][1] += c[rg][j][2] + c[rg][j][3];
            }
        }

        #pragma unroll
        for (int kc = 0; kc < 2; kc++) {
            uint4 v0 = ldsm4t(aVb + kc*1280);
            uint4 v1 = ldsm4t(aVb + kc*1280 + 32);
            #pragma unroll
            for (int rg = 0; rg < 2; rg++) {
                uint4 pa;
                pa.x = cvtbf2(c[rg][2*kc][1],   c[rg][2*kc][0]);
                pa.y = cvtbf2(c[rg][2*kc][3],   c[rg][2*kc][2]);
                pa.z = cvtbf2(c[rg][2*kc+1][1], c[rg][2*kc+1][0]);
                pa.w = cvtbf2(c[rg][2*kc+1][3], c[rg][2*kc+1][2]);
                mma16816(o[rg][0], pa, v0.x, v0.y);
                mma16816(o[rg][1], pa, v0.z, v0.w);
                mma16816(o[rg][2], pa, v1.x, v1.y);
                mma16816(o[rg][3], pa, v1.z, v1.w);
            }
        }

        if (t < 31) cpa_wait0();
        __syncthreads();
    }

    if (hf > 0) {
        float* dst = cbuf + (size_t)(hf-1)*128*36 + (wq*32 + lane)*36;
        #pragma unroll
        for (int rg = 0; rg < 2; rg++)
            #pragma unroll
            for (int j = 0; j < 4; j++)
                *(float4*)&dst[rg*16 + j*4] = make_float4(o[rg][j][0], o[rg][j][1], o[rg][j][2], o[rg][j][3]);
        *(float4*)&dst[32] = make_float4(l[0][0], l[0][1], l[1][0], l[1][1]);
    }
    __syncthreads();
    if (hf > 0) return;

    #pragma unroll
    for (int b = 0; b < 3; b++) {
        const float* src = cbuf + (size_t)b*128*36 + (wq*32 + lane)*36;
        #pragma unroll
        for (int rg = 0; rg < 2; rg++)
            #pragma unroll
            for (int j = 0; j < 4; j++) {
                float4 s4 = *(const float4*)&src[rg*16 + j*4];
                o[rg][j][0] += s4.x; o[rg][j][1] += s4.y; o[rg][j][2] += s4.z; o[rg][j][3] += s4.w;
            }
        float4 ls = *(const float4*)&src[32];
        l[0][0] += ls.x; l[0][1] += ls.y; l[1][0] += ls.z; l[1][1] += ls.w;
    }

    #pragma unroll
    for (int rg = 0; rg < 2; rg++) {
        #pragma unroll
        for (int p = 0; p < 2; p++) {
            l[rg][p] += __shfl_xor_sync(0xffffffffu, l[rg][p], 1);
            l[rg][p] += __shfl_xor_sync(0xffffffffu, l[rg][p], 2);
        }
    }

    u32* OH = (u32*)g_attnh;
    u32* OL = (u32*)g_attnl;
    const int col = h*32 + (lane & 3)*2;
    #pragma unroll
    for (int rg = 0; rg < 2; rg++) {
        float li0 = 1.0f / l[rg][0], li1 = 1.0f / l[rg][1];
        int row0 = q0 + wq*32 + rg*16 + (lane >> 2);
        #pragma unroll
        for (int j = 0; j < 4; j++) {
            u32 hp, lp;
            split2(o[rg][j][0]*li0, o[rg][j][1]*li0, hp, lp);
            OH[((size_t)row0*128 + col + j*8) >> 1] = hp;
            OL[((size_t)row0*128 + col + j*8) >> 1] = lp;
            split2(o[rg][j][2]*li1, o[rg][j][3]*li1, hp, lp);
            OH[((size_t)(row0+8)*128 + col + j*8) >> 1] = hp;
            OL[((size_t)(row0+8)*128 + col + j*8) >> 1] = lp;
        }
    }
}

// ---------------- launch ----------------
extern "C" void kernel_launch(void* const* d_in, const int* in_sizes, int n_in,
                              void* d_out, int out_size) {
    const float* coords   = (const float*)d_in[0];
    const int*   labels   = (const int*)  d_in[1];
    const float* ce_w     = (const float*)d_in[2];
    const float* ce_b     = (const float*)d_in[3];
    const float* emb      = (const float*)d_in[4];
    const float* sa_in_w  = (const float*)d_in[5];
    const float* sa_in_b  = (const float*)d_in[6];
    const float* sa_out_w = (const float*)d_in[7];
    const float* sa_out_b = (const float*)d_in[8];
    const float* n1_g     = (const float*)d_in[9];
    const float* n1_b     = (const float*)d_in[10];
    const float* m1_w1    = (const float*)d_in[11];
    const float* m1_b1    = (const float*)d_in[12];
    const float* m1_w2    = (const float*)d_in[13];
    const float* m1_b2    = (const float*)d_in[14];
    const float* n2_g     = (const float*)d_in[15];
    const float* n2_b     = (const float*)d_in[16];
    const float* ca_in_w  = (const float*)d_in[17];
    const float* ca_in_b  = (const float*)d_in[18];
    const float* ca_out_w = (const float*)d_in[19];
    const float* ca_out_b = (const float*)d_in[20];
    const float* n3_g     = (const float*)d_in[21];
    const float* n3_b     = (const float*)d_in[22];
    const float* m2_w1    = (const float*)d_in[23];
    const float* m2_b1    = (const float*)d_in[24];
    const float* m2_w2    = (const float*)d_in[25];
    const float* m2_b2    = (const float*)d_in[26];
    const float* n4_g     = (const float*)d_in[27];
    const float* n4_b     = (const float*)d_in[28];
    const float* fin_w    = (const float*)d_in[29];
    const float* fin_b    = (const float*)d_in[30];
    float* out = (float*)d_out;

    float *px, *py, *pca;
    __nv_bfloat16 *pxh, *pxl, *pqkvh, *pah, *pal, *pwh, *pwl;
    cudaGetSymbolAddress((void**)&px,    g_x);
    cudaGetSymbolAddress((void**)&py,    g_y);
    cudaGetSymbolAddress((void**)&pxh,   g_xh);
    cudaGetSymbolAddress((void**)&pxl,   g_xl);
    cudaGetSymbolAddress((void**)&pqkvh, g_qkvh);
    cudaGetSymbolAddress((void**)&pah,   g_attnh);
    cudaGetSymbolAddress((void**)&pal,   g_attnl);
    cudaGetSymbolAddress((void**)&pwh,   g_wh);
    cudaGetSymbolAddress((void**)&pwl,   g_wl);
    cudaGetSymbolAddress((void**)&pca,   g_ca);

    const int ATTN_SMEM = 5*128*40*2 + 3*128*36*4;   // 106496 B
    cudaFuncSetAttribute(k_attn, cudaFuncAttributeMaxDynamicSharedMemorySize, ATTN_SMEM);
    const int MLP_SMEM = 221696;
    cudaFuncSetAttribute(k_mlpln<1,1>, cudaFuncAttributeMaxDynamicSharedMemorySize, MLP_SMEM);
    cudaFuncSetAttribute(k_mlpln<2,0>, cudaFuncAttributeMaxDynamicSharedMemorySize, MLP_SMEM);

    WSrc ws;
    ws.p[0] = sa_in_w;  ws.p[1] = sa_out_w; ws.p[2] = m1_w1;
    ws.p[3] = m1_w2;    ws.p[4] = m2_w1;    ws.p[5] = m2_w2;
    ws.end[0] = WO_SAOUT/2; ws.end[1] = WO_M1W1/2; ws.end[2] = WO_M1W2/2;
    ws.end[3] = WO_M2W1/2;  ws.end[4] = WO_M2W2/2; ws.end[5] = W_TOTAL/2;

    k_setup<<<2698, 256>>>(ws, pwh, pwl, coords, ce_w, ce_b,
                           emb, ca_in_w + 2*DD*DD, ca_in_b + 2*DD, ca_out_w, ca_out_b);
    k_gemm3<<<dim3(6, 64), 256>>>(pxh, pxl, pwh+WO_SAIN, pwl+WO_SAIN, sa_in_b, pqkvh, 384, 128);
    k_attn<<<dim3(32, 4), 512, ATTN_SMEM>>>();
    k_mlpln<1,1><<<128, 512, MLP_SMEM>>>(pah, pal, pwh+WO_M1W1, pwl+WO_M1W1, m1_b1,
                                         pwh+WO_M1W2, pwl+WO_M1W2, m1_b2, nullptr,
                                         n2_g, n2_b, n3_g, n3_b, pca, labels,
                                         py, pxh, pxl,
                                         pwh+WO_SAOUT, pwl+WO_SAOUT, sa_out_b, px, n1_g, n1_b);
    k_mlpln<2,0><<<128, 512, MLP_SMEM>>>(pxh, pxl, pwh+WO_M2W1, pwl+WO_M2W1, m2_b1,
                                         pwh+WO_M2W2, pwl+WO_M2W2, m2_b2, py,
                                         n4_g, n4_b, fin_w, fin_b, nullptr, nullptr,
                                         out, nullptr, nullptr,
                                         nullptr, nullptr, nullptr, nullptr, nullptr, nullptr);
}